// round 7
// baseline (speedup 1.0000x reference)
#include <cuda_runtime.h>
#include <cuda_bf16.h>
#include <cstdint>
#include <math.h>

// ---------------- problem constants ----------------
#define D_MODEL 256
#define NH 8
#define HD 32
#define NL 4
#define NP 4
#define DFF 1024
#define B_SZ 2
#define LT 20
#define LQ_C 20197
#define NTOK (B_SZ * LQ_C)   // 40394

__device__ __constant__ int c_H[NL]  = {100, 50, 25, 13};
__device__ __constant__ int c_W[NL]  = {152, 76, 38, 19};
__device__ __constant__ int c_St[NL] = {0, 15200, 19000, 19950};

// ---------------- scratch (static device globals; no allocation) ----------------
__device__ float g_q[NTOK * D_MODEL];
__device__ float g_value[NTOK * D_MODEL];
__device__ float g_offs[NTOK * D_MODEL];
__device__ float g_aw[NTOK * 128];
__device__ float g_kh[B_SZ * LT * D_MODEL];
__device__ float g_vh[B_SZ * LT * D_MODEL];
// bf16 split activation planes
__device__ __nv_bfloat16 g_Ah[NTOK * D_MODEL], g_Al[NTOK * D_MODEL];
__device__ __nv_bfloat16 g_Bh[NTOK * D_MODEL], g_Bl[NTOK * D_MODEL];
__device__ __nv_bfloat16 g_hh[NTOK * DFF], g_hl[NTOK * DFF];
// bf16 split weight planes
__device__ __nv_bfloat16 g_vpw_h[65536], g_vpw_l[65536];
__device__ __nv_bfloat16 g_sow_h[65536], g_sow_l[65536];
__device__ __nv_bfloat16 g_aww_h[32768], g_aww_l[32768];
__device__ __nv_bfloat16 g_opw_h[65536], g_opw_l[65536];
__device__ __nv_bfloat16 g_wqw_h[65536], g_wqw_l[65536];
__device__ __nv_bfloat16 g_mow_h[65536], g_mow_l[65536];
__device__ __nv_bfloat16 g_l1w_h[262144], g_l1w_l[262144];
__device__ __nv_bfloat16 g_l2w_h[262144], g_l2w_l[262144];

static inline int cdiv(int a, int b) { return (a + b - 1) / b; }

__device__ __forceinline__ uint32_t smem_u32(const void* p) {
    uint32_t a;
    asm("{ .reg .u64 t; cvta.to.shared.u64 t, %1; cvt.u32.u64 %0, t; }" : "=r"(a) : "l"(p));
    return a;
}

__device__ __forceinline__ void ldm_x4(uint32_t addr, uint32_t& r0, uint32_t& r1,
                                       uint32_t& r2, uint32_t& r3) {
    asm volatile("ldmatrix.sync.aligned.m8n8.x4.shared.b16 {%0,%1,%2,%3}, [%4];"
                 : "=r"(r0), "=r"(r1), "=r"(r2), "=r"(r3) : "r"(addr));
}

__device__ __forceinline__ void mma_bf16(float* c, const uint32_t* a, const uint32_t* b) {
    asm volatile(
        "mma.sync.aligned.m16n8k16.row.col.f32.bf16.bf16.f32 "
        "{%0,%1,%2,%3}, {%4,%5,%6,%7}, {%8,%9}, {%0,%1,%2,%3};"
        : "+f"(c[0]), "+f"(c[1]), "+f"(c[2]), "+f"(c[3])
        : "r"(a[0]), "r"(a[1]), "r"(a[2]), "r"(a[3]), "r"(b[0]), "r"(b[1]));
}

__device__ __forceinline__ void split4(float4 v, uint2& h, uint2& l) {
    union U { __nv_bfloat16 b[4]; uint2 u; } H, L;
    H.b[0] = __float2bfloat16_rn(v.x);
    H.b[1] = __float2bfloat16_rn(v.y);
    H.b[2] = __float2bfloat16_rn(v.z);
    H.b[3] = __float2bfloat16_rn(v.w);
    L.b[0] = __float2bfloat16_rn(v.x - __bfloat162float(H.b[0]));
    L.b[1] = __float2bfloat16_rn(v.y - __bfloat162float(H.b[1]));
    L.b[2] = __float2bfloat16_rn(v.z - __bfloat162float(H.b[2]));
    L.b[3] = __float2bfloat16_rn(v.w - __bfloat162float(H.b[3]));
    h = H.u; l = L.u;
}
__device__ __forceinline__ uint32_t split2(float v0, float v1, uint32_t& lo) {
    union U { __nv_bfloat16 b[2]; uint32_t u; } H, L;
    H.b[0] = __float2bfloat16_rn(v0);
    H.b[1] = __float2bfloat16_rn(v1);
    L.b[0] = __float2bfloat16_rn(v0 - __bfloat162float(H.b[0]));
    L.b[1] = __float2bfloat16_rn(v1 - __bfloat162float(H.b[1]));
    lo = L.u;
    return H.u;
}

__device__ __forceinline__ void cpa16(uint32_t dst, const void* src) {
    asm volatile("cp.async.ca.shared.global [%0], [%1], 16;" :: "r"(dst), "l"(src));
}
__device__ __forceinline__ void cpa16z(uint32_t dst, const void* src, bool v) {
    int sz = v ? 16 : 0;
    asm volatile("cp.async.ca.shared.global [%0], [%1], 16, %2;"
                 :: "r"(dst), "l"(src), "r"(sz));
}

// =====================================================================
// bf16-split tensor-core GEMM on PRE-SPLIT operands:
//   C = (Ah+Al)[M,K] @ (Wh+Wl)[N,K]^T + bias  (3-pass: hh + hl + lh)
//   MODE 0: +bias  1: +bias+residual  2: +bias,relu  3: +bias,softmax16
//   OSPLIT: write C as split bf16 planes (Ch, Cl) instead of fp32
//   CTA 64(M) x 128(N), 256 thr (warp tile 32x32), K-chunk 64,
//   2 cp.async stages (48KB each) -> 2 CTAs/SM.
// =====================================================================
#define KC 64
#define A_TILE_B (64 * 64 * 2)         // 8 KB
#define B_TILE_B (128 * 64 * 2)        // 16 KB
#define STAGE_B (2 * A_TILE_B + 2 * B_TILE_B)  // 48 KB
#define GEMM_SMEM (2 * STAGE_B)        // 96 KB

template <int MODE, bool OSPLIT>
__global__ void __launch_bounds__(256, 2)
tc_gemm(const __nv_bfloat16* __restrict__ Ah, const __nv_bfloat16* __restrict__ Al,
        const __nv_bfloat16* __restrict__ Wh, const __nv_bfloat16* __restrict__ Wl,
        const float* __restrict__ bias, const float* __restrict__ R,
        float* __restrict__ C, __nv_bfloat16* __restrict__ Ch, __nv_bfloat16* __restrict__ Cl,
        int M, int N, int K) {
    extern __shared__ char smem[];
    const uint32_t sbase = smem_u32(smem);
    const int tid = threadIdx.x;
    const int wid = tid >> 5;
    const int lane = tid & 31;
    const int rowBase = blockIdx.y * 64;
    const int colBase = blockIdx.x * 128;
    const int warpM = wid >> 2;
    const int warpN = wid & 3;

    float acc[2][4][4];
#pragma unroll
    for (int mi = 0; mi < 2; mi++)
#pragma unroll
        for (int ni = 0; ni < 4; ni++)
#pragma unroll
            for (int j = 0; j < 4; j++) acc[mi][ni][j] = 0.f;

    // ldmatrix per-lane offsets; swizzle XORs reduce to (lane&7)<<4
    const uint32_t swX = (uint32_t)((lane & 7) << 4);
    const int aKB0 = (lane >> 4) * 16;
    uint32_t aRowOff[2];
#pragma unroll
    for (int mi = 0; mi < 2; mi++)
        aRowOff[mi] = (uint32_t)((warpM * 32 + mi * 16 + (lane & 15)) * 128);
    const int grp = lane >> 3;
    const int bKB0 = (grp & 1) * 16;
    uint32_t bRowOff[2];
#pragma unroll
    for (int np = 0; np < 2; np++)
        bRowOff[np] = (uint32_t)((warpN * 32 + np * 16 + ((grp >> 1) << 3) + (lane & 7)) * 128);

    const int nChunks = K / KC;

    auto copy_chunk = [&](int kt, uint32_t stg) {
        const int k0 = kt * KC;
        // A planes: 64 rows x 8 chunks of 16B, per thread 2
#pragma unroll
        for (int i = 0; i < 2; i++) {
            int idx = tid + i * 256;
            int r = idx >> 3, c = idx & 7;
            uint32_t off = (uint32_t)(r * 128 + ((c * 16) ^ ((r & 7) << 4)));
            int gr = rowBase + r;
            bool v = gr < M;
            int cr = v ? gr : (M - 1);
            cpa16z(stg + off, Ah + (size_t)cr * K + k0 + c * 8, v);
            cpa16z(stg + A_TILE_B + off, Al + (size_t)cr * K + k0 + c * 8, v);
        }
        // B planes: 128 rows x 8 chunks, per thread 4 (N always multiple of 128)
#pragma unroll
        for (int i = 0; i < 4; i++) {
            int idx = tid + i * 256;
            int r = idx >> 3, c = idx & 7;
            uint32_t off = (uint32_t)(r * 128 + ((c * 16) ^ ((r & 7) << 4)));
            cpa16(stg + 2 * A_TILE_B + off, Wh + (size_t)(colBase + r) * K + k0 + c * 8);
            cpa16(stg + 2 * A_TILE_B + B_TILE_B + off,
                  Wl + (size_t)(colBase + r) * K + k0 + c * 8);
        }
    };

    copy_chunk(0, sbase);
    asm volatile("cp.async.commit_group;");

    for (int kt = 0; kt < nChunks; kt++) {
        if (kt + 1 < nChunks) {
            copy_chunk(kt + 1, sbase + (uint32_t)(((kt + 1) & 1) * STAGE_B));
            asm volatile("cp.async.commit_group;");
            asm volatile("cp.async.wait_group 1;");
        } else {
            asm volatile("cp.async.wait_group 0;");
        }
        __syncthreads();
        const uint32_t stg = sbase + (uint32_t)((kt & 1) * STAGE_B);
        const uint32_t AhS = stg, AlS = stg + A_TILE_B;
        const uint32_t BhS = stg + 2 * A_TILE_B, BlS = BhS + B_TILE_B;
#pragma unroll
        for (int kst = 0; kst < 4; kst++) {
            uint32_t ah[2][4], al[2][4];
#pragma unroll
            for (int mi = 0; mi < 2; mi++) {
                uint32_t off = aRowOff[mi] + (uint32_t)((aKB0 + kst * 32) ^ swX);
                ldm_x4(AhS + off, ah[mi][0], ah[mi][1], ah[mi][2], ah[mi][3]);
                ldm_x4(AlS + off, al[mi][0], al[mi][1], al[mi][2], al[mi][3]);
            }
            uint32_t bh[4][2], bl[4][2];
#pragma unroll
            for (int np = 0; np < 2; np++) {
                uint32_t off = bRowOff[np] + (uint32_t)((bKB0 + kst * 32) ^ swX);
                uint32_t r0, r1, r2, r3;
                ldm_x4(BhS + off, r0, r1, r2, r3);
                bh[np * 2][0] = r0; bh[np * 2][1] = r1;
                bh[np * 2 + 1][0] = r2; bh[np * 2 + 1][1] = r3;
                ldm_x4(BlS + off, r0, r1, r2, r3);
                bl[np * 2][0] = r0; bl[np * 2][1] = r1;
                bl[np * 2 + 1][0] = r2; bl[np * 2 + 1][1] = r3;
            }
#pragma unroll
            for (int mi = 0; mi < 2; mi++)
#pragma unroll
                for (int ni = 0; ni < 4; ni++) mma_bf16(acc[mi][ni], ah[mi], bh[ni]);
#pragma unroll
            for (int mi = 0; mi < 2; mi++)
#pragma unroll
                for (int ni = 0; ni < 4; ni++) mma_bf16(acc[mi][ni], ah[mi], bl[ni]);
#pragma unroll
            for (int mi = 0; mi < 2; mi++)
#pragma unroll
                for (int ni = 0; ni < 4; ni++) mma_bf16(acc[mi][ni], al[mi], bh[ni]);
        }
        if (kt + 1 < nChunks) __syncthreads();
    }

    // ---- epilogue ----
    const int qrow = lane >> 2;
    const int qcol = (lane & 3) * 2;
#pragma unroll
    for (int ni = 0; ni < 4; ni++) {
        int col = colBase + warpN * 32 + ni * 8 + qcol;
        float b0 = __ldg(bias + col), b1 = __ldg(bias + col + 1);
#pragma unroll
        for (int mi = 0; mi < 2; mi++) {
            acc[mi][ni][0] += b0; acc[mi][ni][1] += b1;
            acc[mi][ni][2] += b0; acc[mi][ni][3] += b1;
        }
    }
    if (MODE == 3) {
#pragma unroll
        for (int mi = 0; mi < 2; mi++)
#pragma unroll
            for (int g = 0; g < 2; g++)
#pragma unroll
                for (int rh = 0; rh < 2; rh++) {
                    float v0 = acc[mi][2 * g][rh * 2], v1 = acc[mi][2 * g][rh * 2 + 1];
                    float v2 = acc[mi][2 * g + 1][rh * 2], v3 = acc[mi][2 * g + 1][rh * 2 + 1];
                    float mx = fmaxf(fmaxf(v0, v1), fmaxf(v2, v3));
                    mx = fmaxf(mx, __shfl_xor_sync(0xffffffffu, mx, 1));
                    mx = fmaxf(mx, __shfl_xor_sync(0xffffffffu, mx, 2));
                    v0 = expf(v0 - mx); v1 = expf(v1 - mx);
                    v2 = expf(v2 - mx); v3 = expf(v3 - mx);
                    float s = v0 + v1 + v2 + v3;
                    s += __shfl_xor_sync(0xffffffffu, s, 1);
                    s += __shfl_xor_sync(0xffffffffu, s, 2);
                    float inv = 1.f / s;
                    acc[mi][2 * g][rh * 2] = v0 * inv; acc[mi][2 * g][rh * 2 + 1] = v1 * inv;
                    acc[mi][2 * g + 1][rh * 2] = v2 * inv; acc[mi][2 * g + 1][rh * 2 + 1] = v3 * inv;
                }
    }
#pragma unroll
    for (int mi = 0; mi < 2; mi++)
#pragma unroll
        for (int rh = 0; rh < 2; rh++) {
            int row = rowBase + warpM * 32 + mi * 16 + qrow + rh * 8;
            if (row >= M) continue;
#pragma unroll
            for (int ni = 0; ni < 4; ni++) {
                int col = colBase + warpN * 32 + ni * 8 + qcol;
                float v0 = acc[mi][ni][rh * 2], v1 = acc[mi][ni][rh * 2 + 1];
                if (MODE == 1) {
                    const float2 rr = *(const float2*)(R + (size_t)row * N + col);
                    v0 += rr.x; v1 += rr.y;
                }
                if (MODE == 2) { v0 = fmaxf(v0, 0.f); v1 = fmaxf(v1, 0.f); }
                if (OSPLIT) {
                    uint32_t lo;
                    uint32_t hi = split2(v0, v1, lo);
                    *(uint32_t*)(Ch + (size_t)row * N + col) = hi;
                    *(uint32_t*)(Cl + (size_t)row * N + col) = lo;
                } else {
                    *(float2*)(C + (size_t)row * N + col) = make_float2(v0, v1);
                }
            }
        }
}

// ---------------- fp32 -> bf16 hi/lo split converters ----------------
__global__ void conv_split(const float* __restrict__ s, __nv_bfloat16* __restrict__ h,
                           __nv_bfloat16* __restrict__ l, int n4) {
    int i = blockIdx.x * blockDim.x + threadIdx.x;
    if (i >= n4) return;
    float4 v = ((const float4*)s)[i];
    uint2 hh, ll;
    split4(v, hh, ll);
    ((uint2*)h)[i] = hh;
    ((uint2*)l)[i] = ll;
}
__global__ void convadd_split(const float* __restrict__ a, const float* __restrict__ b,
                              __nv_bfloat16* __restrict__ h, __nv_bfloat16* __restrict__ l,
                              int n4) {
    int i = blockIdx.x * blockDim.x + threadIdx.x;
    if (i >= n4) return;
    float4 va = ((const float4*)a)[i];
    float4 vb = ((const float4*)b)[i];
    va.x += vb.x; va.y += vb.y; va.z += vb.z; va.w += vb.w;
    uint2 hh, ll;
    split4(va, hh, ll);
    ((uint2*)h)[i] = hh;
    ((uint2*)l)[i] = ll;
}

// ---------------- multi-scale deformable sampling (split bf16 out) ----------------
__global__ void msdeform_kernel(const float* __restrict__ value, const float* __restrict__ offs,
                                const float* __restrict__ aw, const float* __restrict__ ref,
                                __nv_bfloat16* __restrict__ outh, __nv_bfloat16* __restrict__ outl) {
    int gw = (blockIdx.x * blockDim.x + threadIdx.x) >> 5;
    int lane = threadIdx.x & 31;
    if (gw >= NTOK * NH) return;
    int token = gw >> 3, h = gw & 7;
    int b = (token >= LQ_C) ? 1 : 0;

    int p = lane & 15;
    int l = p >> 2;
    int Wl = c_W[l], Hl = c_H[l];
    float Wf = (float)Wl, Hf = (float)Hl;
    float rx = __ldg(ref + (size_t)token * 8 + l * 2);
    float ry = __ldg(ref + (size_t)token * 8 + l * 2 + 1);
    float ox = __ldg(offs + (size_t)token * 256 + h * 32 + p * 2);
    float oy = __ldg(offs + (size_t)token * 256 + h * 32 + p * 2 + 1);
    float wA = __ldg(aw + (size_t)token * 128 + h * 16 + p);

    float X = (rx + ox / Wf) * Wf - 0.5f;
    float Y = (ry + oy / Hf) * Hf - 0.5f;
    float x0f = floorf(X), y0f = floorf(Y);
    float lx = X - x0f, ly = Y - y0f;
    int x0 = (int)x0f, y0 = (int)y0f;
    int x1 = x0 + 1, y1 = y0 + 1;
    bool vx0 = (x0 >= 0) & (x0 < Wl), vx1 = (x1 >= 0) & (x1 < Wl);
    bool vy0 = (y0 >= 0) & (y0 < Hl), vy1 = (y1 >= 0) & (y1 < Hl);
    int cx0 = min(max(x0, 0), Wl - 1), cx1 = min(max(x1, 0), Wl - 1);
    int cy0 = min(max(y0, 0), Hl - 1), cy1 = min(max(y1, 0), Hl - 1);
    int base = b * LQ_C + c_St[l];
    int r00 = base + cy0 * Wl + cx0;
    int r01 = base + cy0 * Wl + cx1;
    int r10 = base + cy1 * Wl + cx0;
    int r11 = base + cy1 * Wl + cx1;
    float w00 = wA * (1.f - lx) * (1.f - ly) * (float)(vx0 & vy0);
    float w01 = wA * lx * (1.f - ly) * (float)(vx1 & vy0);
    float w10 = wA * (1.f - lx) * ly * (float)(vx0 & vy1);
    float w11 = wA * lx * ly * (float)(vx1 & vy1);

    const float* vb = value + h * 32 + lane;
    float acc = 0.f;
#pragma unroll
    for (int pp = 0; pp < 16; pp++) {
        int s00 = __shfl_sync(0xffffffffu, r00, pp);
        int s01 = __shfl_sync(0xffffffffu, r01, pp);
        int s10 = __shfl_sync(0xffffffffu, r10, pp);
        int s11 = __shfl_sync(0xffffffffu, r11, pp);
        float u00 = __shfl_sync(0xffffffffu, w00, pp);
        float u01 = __shfl_sync(0xffffffffu, w01, pp);
        float u10 = __shfl_sync(0xffffffffu, w10, pp);
        float u11 = __shfl_sync(0xffffffffu, w11, pp);
        acc += u00 * __ldg(vb + (size_t)s00 * 256);
        acc += u01 * __ldg(vb + (size_t)s01 * 256);
        acc += u10 * __ldg(vb + (size_t)s10 * 256);
        acc += u11 * __ldg(vb + (size_t)s11 * 256);
    }
    __nv_bfloat16 hb = __float2bfloat16_rn(acc);
    __nv_bfloat16 lb = __float2bfloat16_rn(acc - __bfloat162float(hb));
    outh[(size_t)token * 256 + h * 32 + lane] = hb;
    outl[(size_t)token * 256 + h * 32 + lane] = lb;
}

// ---------------- layernorm: warp per row; optional (out+P) split bf16 ----------------
__global__ void ln_kernel(const float* __restrict__ in, const float* __restrict__ g,
                          const float* __restrict__ b, float* __restrict__ out,
                          const float* __restrict__ P,
                          __nv_bfloat16* __restrict__ oh, __nv_bfloat16* __restrict__ ol,
                          int rows) {
    int warp = (blockIdx.x * blockDim.x + threadIdx.x) >> 5;
    int lane = threadIdx.x & 31;
    if (warp >= rows) return;
    const float* x = in + (size_t)warp * 256;
    float v[8];
    float s = 0.f;
#pragma unroll
    for (int j = 0; j < 8; j++) { v[j] = x[j * 32 + lane]; s += v[j]; }
#pragma unroll
    for (int o = 16; o; o >>= 1) s += __shfl_xor_sync(0xffffffffu, s, o);
    float m = s * (1.f / 256.f);
    float s2 = 0.f;
#pragma unroll
    for (int j = 0; j < 8; j++) { float d = v[j] - m; s2 += d * d; }
#pragma unroll
    for (int o = 16; o; o >>= 1) s2 += __shfl_xor_sync(0xffffffffu, s2, o);
    float rstd = rsqrtf(s2 * (1.f / 256.f) + 1e-5f);
#pragma unroll
    for (int j = 0; j < 8; j++) {
        int col = j * 32 + lane;
        float y = (v[j] - m) * rstd * g[col] + b[col];
        out[(size_t)warp * 256 + col] = y;
        if (oh) {
            float t = P ? y + P[(size_t)warp * 256 + col] : y;
            __nv_bfloat16 hb = __float2bfloat16_rn(t);
            oh[(size_t)warp * 256 + col] = hb;
            ol[(size_t)warp * 256 + col] = __float2bfloat16_rn(t - __bfloat162float(hb));
        }
    }
}

// ---------------- text K/V projection (40 rows) ----------------
__global__ void kv_proj_kernel(const float* __restrict__ text, const float* __restrict__ ipw,
                               const float* __restrict__ ipb, float* __restrict__ kh,
                               float* __restrict__ vh) {
    int row = blockIdx.x;
    int c = threadIdx.x;
    const float* t = text + (size_t)row * 256;
    const float* wk = ipw + (size_t)(256 + c) * 256;
    const float* wv = ipw + (size_t)(512 + c) * 256;
    float sk = ipb[256 + c], sv = ipb[512 + c];
    for (int k = 0; k < 256; k++) {
        float tv = t[k];
        sk += tv * wk[k];
        sv += tv * wv[k];
    }
    kh[(size_t)row * 256 + c] = sk;
    vh[(size_t)row * 256 + c] = sv;
}

// ---------------- text cross-attention: thread per (token, head); split bf16 out ----------------
__global__ void cross_attn_kernel(const float* __restrict__ qh, const float* __restrict__ kh,
                                  const float* __restrict__ vh,
                                  __nv_bfloat16* __restrict__ ch, __nv_bfloat16* __restrict__ cl) {
    int idx = blockIdx.x * blockDim.x + threadIdx.x;
    if (idx >= NTOK * NH) return;
    int token = idx >> 3, h = idx & 7;
    int b = (token >= LQ_C) ? 1 : 0;
    const float4* q = (const float4*)(qh + (size_t)token * 256 + h * 32);
    float4 qv[8];
#pragma unroll
    for (int j = 0; j < 8; j++) qv[j] = q[j];

    float sc[LT];
    float mx = -1e30f;
    const float scale = 0.17677669529663687f;
#pragma unroll 4
    for (int k = 0; k < LT; k++) {
        const float4* kp = (const float4*)(kh + (size_t)(b * LT + k) * 256 + h * 32);
        float s = 0.f;
#pragma unroll
        for (int j = 0; j < 8; j++) {
            float4 kv = kp[j];
            s += qv[j].x * kv.x + qv[j].y * kv.y + qv[j].z * kv.z + qv[j].w * kv.w;
        }
        s *= scale;
        sc[k] = s;
        mx = fmaxf(mx, s);
    }
    float denom = 0.f;
#pragma unroll
    for (int k = 0; k < LT; k++) { sc[k] = expf(sc[k] - mx); denom += sc[k]; }
    float inv = 1.f / denom;
    float4 o[8];
#pragma unroll
    for (int j = 0; j < 8; j++) o[j] = make_float4(0.f, 0.f, 0.f, 0.f);
#pragma unroll 4
    for (int k = 0; k < LT; k++) {
        float pw = sc[k] * inv;
        const float4* vp = (const float4*)(vh + (size_t)(b * LT + k) * 256 + h * 32);
#pragma unroll
        for (int j = 0; j < 8; j++) {
            float4 vv = vp[j];
            o[j].x += pw * vv.x; o[j].y += pw * vv.y;
            o[j].z += pw * vv.z; o[j].w += pw * vv.w;
        }
    }
#pragma unroll
    for (int j = 0; j < 8; j++) {
        uint2 hh, ll;
        split4(o[j], hh, ll);
        *(uint2*)(ch + (size_t)token * 256 + h * 32 + j * 4) = hh;
        *(uint2*)(cl + (size_t)token * 256 + h * 32 + j * 4) = ll;
    }
}

// ---------------- launch ----------------
extern "C" void kernel_launch(void* const* d_in, const int* in_sizes, int n_in,
                              void* d_out, int out_size) {
    const float* src   = (const float*)d_in[0];
    const float* pos   = (const float*)d_in[1];
    const float* refp  = (const float*)d_in[2];
    const float* text  = (const float*)d_in[5];
    const float* so_w  = (const float*)d_in[7];
    const float* so_b  = (const float*)d_in[8];
    const float* aw_w  = (const float*)d_in[9];
    const float* aw_b  = (const float*)d_in[10];
    const float* vp_w  = (const float*)d_in[11];
    const float* vp_b  = (const float*)d_in[12];
    const float* op_w  = (const float*)d_in[13];
    const float* op_b  = (const float*)d_in[14];
    const float* ln1_g = (const float*)d_in[15];
    const float* ln1_b = (const float*)d_in[16];
    const float* ipw   = (const float*)d_in[17];
    const float* ipb   = (const float*)d_in[18];
    const float* mo_w  = (const float*)d_in[19];
    const float* mo_b  = (const float*)d_in[20];
    const float* ln3_g = (const float*)d_in[21];
    const float* ln3_b = (const float*)d_in[22];
    const float* l1_w  = (const float*)d_in[23];
    const float* l1_b  = (const float*)d_in[24];
    const float* l2_w  = (const float*)d_in[25];
    const float* l2_b  = (const float*)d_in[26];
    const float* ln2_g = (const float*)d_in[27];
    const float* ln2_b = (const float*)d_in[28];

    float* out_x = (float*)d_out;
    float* out_text = out_x + (size_t)NTOK * D_MODEL;

    float *q, *val, *offs, *aw, *kh, *vh;
    cudaGetSymbolAddress((void**)&q, g_q);
    cudaGetSymbolAddress((void**)&val, g_value);
    cudaGetSymbolAddress((void**)&offs, g_offs);
    cudaGetSymbolAddress((void**)&aw, g_aw);
    cudaGetSymbolAddress((void**)&kh, g_kh);
    cudaGetSymbolAddress((void**)&vh, g_vh);
    __nv_bfloat16 *Ah, *Al, *Bh, *Bl, *hh, *hl;
    cudaGetSymbolAddress((void**)&Ah, g_Ah);
    cudaGetSymbolAddress((void**)&Al, g_Al);
    cudaGetSymbolAddress((void**)&Bh, g_Bh);
    cudaGetSymbolAddress((void**)&Bl, g_Bl);
    cudaGetSymbolAddress((void**)&hh, g_hh);
    cudaGetSymbolAddress((void**)&hl, g_hl);
    __nv_bfloat16 *vpwh, *vpwl, *sowh, *sowl, *awwh, *awwl, *opwh, *opwl;
    __nv_bfloat16 *wqwh, *wqwl, *mowh, *mowl, *l1wh, *l1wl, *l2wh, *l2wl;
    cudaGetSymbolAddress((void**)&vpwh, g_vpw_h); cudaGetSymbolAddress((void**)&vpwl, g_vpw_l);
    cudaGetSymbolAddress((void**)&sowh, g_sow_h); cudaGetSymbolAddress((void**)&sowl, g_sow_l);
    cudaGetSymbolAddress((void**)&awwh, g_aww_h); cudaGetSymbolAddress((void**)&awwl, g_aww_l);
    cudaGetSymbolAddress((void**)&opwh, g_opw_h); cudaGetSymbolAddress((void**)&opwl, g_opw_l);
    cudaGetSymbolAddress((void**)&wqwh, g_wqw_h); cudaGetSymbolAddress((void**)&wqwl, g_wqw_l);
    cudaGetSymbolAddress((void**)&mowh, g_mow_h); cudaGetSymbolAddress((void**)&mowl, g_mow_l);
    cudaGetSymbolAddress((void**)&l1wh, g_l1w_h); cudaGetSymbolAddress((void**)&l1wl, g_l1w_l);
    cudaGetSymbolAddress((void**)&l2wh, g_l2w_h); cudaGetSymbolAddress((void**)&l2wl, g_l2w_l);

    cudaFuncSetAttribute(tc_gemm<0, false>, cudaFuncAttributeMaxDynamicSharedMemorySize, GEMM_SMEM);
    cudaFuncSetAttribute(tc_gemm<1, false>, cudaFuncAttributeMaxDynamicSharedMemorySize, GEMM_SMEM);
    cudaFuncSetAttribute(tc_gemm<2, true>, cudaFuncAttributeMaxDynamicSharedMemorySize, GEMM_SMEM);
    cudaFuncSetAttribute(tc_gemm<3, false>, cudaFuncAttributeMaxDynamicSharedMemorySize, GEMM_SMEM);

    const int M = NTOK;
    const int mTiles = cdiv(M, 64);
    dim3 g256(2, mTiles), g128(1, mTiles), g1024(8, mTiles);
    const int nAct4 = M * D_MODEL / 4;

    // ---- weight conversions (once per launch; tiny) ----
    conv_split<<<cdiv(65536 / 4, 256), 256>>>(vp_w, vpwh, vpwl, 65536 / 4);
    conv_split<<<cdiv(65536 / 4, 256), 256>>>(so_w, sowh, sowl, 65536 / 4);
    conv_split<<<cdiv(32768 / 4, 256), 256>>>(aw_w, awwh, awwl, 32768 / 4);
    conv_split<<<cdiv(65536 / 4, 256), 256>>>(op_w, opwh, opwl, 65536 / 4);
    conv_split<<<cdiv(65536 / 4, 256), 256>>>(ipw, wqwh, wqwl, 65536 / 4);
    conv_split<<<cdiv(65536 / 4, 256), 256>>>(mo_w, mowh, mowl, 65536 / 4);
    conv_split<<<cdiv(262144 / 4, 256), 256>>>(l1_w, l1wh, l1wl, 262144 / 4);
    conv_split<<<cdiv(262144 / 4, 256), 256>>>(l2_w, l2wh, l2wl, 262144 / 4);
    // ---- activation conversions ----
    conv_split<<<cdiv(nAct4, 256), 256>>>(src, Ah, Al, nAct4);             // src for vp
    convadd_split<<<cdiv(nAct4, 256), 256>>>(src, pos, Bh, Bl, nAct4);     // q = src+pos

    // 1) value = src @ vp^T + b
    tc_gemm<0, false><<<g256, 256, GEMM_SMEM>>>(Ah, Al, vpwh, vpwl, vp_b, nullptr, val,
                                                nullptr, nullptr, M, 256, 256);
    // 2) offs = q @ so^T + b
    tc_gemm<0, false><<<g256, 256, GEMM_SMEM>>>(Bh, Bl, sowh, sowl, so_b, nullptr, offs,
                                                nullptr, nullptr, M, 256, 256);
    // 3) aw = softmax16(q @ aw^T + b)
    tc_gemm<3, false><<<g128, 256, GEMM_SMEM>>>(Bh, Bl, awwh, awwl, aw_b, nullptr, aw,
                                                nullptr, nullptr, M, 128, 256);
    // 4) deformable sampling -> ms (split bf16 into A planes; free after step 1)
    msdeform_kernel<<<cdiv(M * NH * 32, 256), 256>>>(val, offs, aw, refp, Ah, Al);
    // 5) preLN1 = ms @ op^T + b + src ; LN1 -> out_x + (out+pos) split into B planes
    tc_gemm<1, false><<<g256, 256, GEMM_SMEM>>>(Ah, Al, opwh, opwl, op_b, src, offs,
                                                nullptr, nullptr, M, 256, 256);
    ln_kernel<<<cdiv(M * 32, 256), 256>>>(offs, ln1_g, ln1_b, out_x, pos, Bh, Bl, M);
    // 6) text K/V
    kv_proj_kernel<<<B_SZ * LT, 256>>>(text, ipw, ipb, kh, vh);
    // 7) qh = (x+pos) @ wq^T + bq
    tc_gemm<0, false><<<g256, 256, GEMM_SMEM>>>(Bh, Bl, wqwh, wqwl, ipb, nullptr, q,
                                                nullptr, nullptr, M, 256, 256);
    // 8) cross attention -> ctx (split bf16 into A planes)
    cross_attn_kernel<<<cdiv(M * NH, 256), 256>>>(q, kh, vh, Ah, Al);
    // 9) preLN3 = ctx @ mo^T + b + x ; LN3 -> out_x + split into B planes
    tc_gemm<1, false><<<g256, 256, GEMM_SMEM>>>(Ah, Al, mowh, mowl, mo_b, out_x, val,
                                                nullptr, nullptr, M, 256, 256);
    ln_kernel<<<cdiv(M * 32, 256), 256>>>(val, ln3_g, ln3_b, out_x, nullptr, Bh, Bl, M);
    // 10) FFN: hid = relu(x @ l1^T + b1) as split bf16; preLN2 = hid @ l2^T + b2 + x
    tc_gemm<2, true><<<g1024, 256, GEMM_SMEM>>>(Bh, Bl, l1wh, l1wl, l1_b, nullptr, nullptr,
                                                hh, hl, M, DFF, 256);
    tc_gemm<1, false><<<g256, 256, GEMM_SMEM>>>(hh, hl, l2wh, l2wl, l2_b, out_x, val,
                                                nullptr, nullptr, M, 256, DFF);
    ln_kernel<<<cdiv(M * 32, 256), 256>>>(val, ln2_g, ln2_b, out_x, nullptr, nullptr, nullptr, M);
    // 11) pass-through text_memory
    cudaMemcpyAsync(out_text, text, (size_t)B_SZ * LT * D_MODEL * sizeof(float),
                    cudaMemcpyDeviceToDevice, 0);
}

// round 8
// speedup vs baseline: 1.0259x; 1.0259x over previous
#include <cuda_runtime.h>
#include <cuda_bf16.h>
#include <cstdint>
#include <math.h>

// ---------------- problem constants ----------------
#define D_MODEL 256
#define NH 8
#define HD 32
#define NL 4
#define NP 4
#define DFF 1024
#define B_SZ 2
#define LT 20
#define LQ_C 20197
#define NTOK (B_SZ * LQ_C)   // 40394

__device__ __constant__ int c_H[NL]  = {100, 50, 25, 13};
__device__ __constant__ int c_W[NL]  = {152, 76, 38, 19};
__device__ __constant__ int c_St[NL] = {0, 15200, 19000, 19950};

// ---------------- scratch (static device globals; no allocation) ----------------
__device__ float g_q[NTOK * D_MODEL];
__device__ float g_value[NTOK * D_MODEL];
__device__ float g_offs[NTOK * D_MODEL];
__device__ float g_aw[NTOK * 128];
__device__ float g_kh[B_SZ * LT * D_MODEL];
__device__ float g_vh[B_SZ * LT * D_MODEL];
// bf16 split activation planes
__device__ __nv_bfloat16 g_Ah[NTOK * D_MODEL], g_Al[NTOK * D_MODEL];
__device__ __nv_bfloat16 g_Bh[NTOK * D_MODEL], g_Bl[NTOK * D_MODEL];
__device__ __nv_bfloat16 g_hh[NTOK * DFF], g_hl[NTOK * DFF];
// bf16 split weight planes
__device__ __nv_bfloat16 g_vpw_h[65536], g_vpw_l[65536];
__device__ __nv_bfloat16 g_sow_h[65536], g_sow_l[65536];
__device__ __nv_bfloat16 g_aww_h[32768], g_aww_l[32768];
__device__ __nv_bfloat16 g_opw_h[65536], g_opw_l[65536];
__device__ __nv_bfloat16 g_wqw_h[65536], g_wqw_l[65536];
__device__ __nv_bfloat16 g_mow_h[65536], g_mow_l[65536];
__device__ __nv_bfloat16 g_l1w_h[262144], g_l1w_l[262144];
__device__ __nv_bfloat16 g_l2w_h[262144], g_l2w_l[262144];

static inline int cdiv(int a, int b) { return (a + b - 1) / b; }

__device__ __forceinline__ uint32_t smem_u32(const void* p) {
    uint32_t a;
    asm("{ .reg .u64 t; cvta.to.shared.u64 t, %1; cvt.u32.u64 %0, t; }" : "=r"(a) : "l"(p));
    return a;
}

__device__ __forceinline__ void ldm_x4(uint32_t addr, uint32_t& r0, uint32_t& r1,
                                       uint32_t& r2, uint32_t& r3) {
    asm volatile("ldmatrix.sync.aligned.m8n8.x4.shared.b16 {%0,%1,%2,%3}, [%4];"
                 : "=r"(r0), "=r"(r1), "=r"(r2), "=r"(r3) : "r"(addr));
}

__device__ __forceinline__ void mma_bf16(float* c, const uint32_t* a, const uint32_t* b) {
    asm volatile(
        "mma.sync.aligned.m16n8k16.row.col.f32.bf16.bf16.f32 "
        "{%0,%1,%2,%3}, {%4,%5,%6,%7}, {%8,%9}, {%0,%1,%2,%3};"
        : "+f"(c[0]), "+f"(c[1]), "+f"(c[2]), "+f"(c[3])
        : "r"(a[0]), "r"(a[1]), "r"(a[2]), "r"(a[3]), "r"(b[0]), "r"(b[1]));
}

__device__ __forceinline__ void split4(float4 v, uint2& h, uint2& l) {
    union U { __nv_bfloat16 b[4]; uint2 u; } H, L;
    H.b[0] = __float2bfloat16_rn(v.x);
    H.b[1] = __float2bfloat16_rn(v.y);
    H.b[2] = __float2bfloat16_rn(v.z);
    H.b[3] = __float2bfloat16_rn(v.w);
    L.b[0] = __float2bfloat16_rn(v.x - __bfloat162float(H.b[0]));
    L.b[1] = __float2bfloat16_rn(v.y - __bfloat162float(H.b[1]));
    L.b[2] = __float2bfloat16_rn(v.z - __bfloat162float(H.b[2]));
    L.b[3] = __float2bfloat16_rn(v.w - __bfloat162float(H.b[3]));
    h = H.u; l = L.u;
}
__device__ __forceinline__ uint32_t split2(float v0, float v1, uint32_t& lo) {
    union U { __nv_bfloat16 b[2]; uint32_t u; } H, L;
    H.b[0] = __float2bfloat16_rn(v0);
    H.b[1] = __float2bfloat16_rn(v1);
    L.b[0] = __float2bfloat16_rn(v0 - __bfloat162float(H.b[0]));
    L.b[1] = __float2bfloat16_rn(v1 - __bfloat162float(H.b[1]));
    lo = L.u;
    return H.u;
}

__device__ __forceinline__ void cpa16(uint32_t dst, const void* src) {
    asm volatile("cp.async.cg.shared.global [%0], [%1], 16;" :: "r"(dst), "l"(src));
}
__device__ __forceinline__ void cpa16z(uint32_t dst, const void* src, bool v) {
    int sz = v ? 16 : 0;
    asm volatile("cp.async.cg.shared.global [%0], [%1], 16, %2;"
                 :: "r"(dst), "l"(src), "r"(sz));
}

// =====================================================================
// bf16-split tensor-core GEMM on PRE-SPLIT operands:
//   C = (Ah+Al)[M,K] @ (Wh+Wl)[N,K]^T + bias  (3-pass: hh + hl + lh)
//   MODE 0: +bias  1: +bias+residual  2: +bias,relu  3: +bias,softmax16
//   OSPLIT: write C as split bf16 planes (Ch, Cl)
//   CTA 64(M) x 128(N), 256 thr (warp tile 32x32), K-chunk 64,
//   2 cp.async stages (48KB each) -> 2 CTAs/SM.
// =====================================================================
#define KC 64
#define A_TILE_B (64 * 64 * 2)         // 8 KB
#define B_TILE_B (128 * 64 * 2)        // 16 KB
#define STAGE_B (2 * A_TILE_B + 2 * B_TILE_B)  // 48 KB
#define GEMM_SMEM (2 * STAGE_B)        // 96 KB

template <int MODE, bool OSPLIT>
__global__ void __launch_bounds__(256, 2)
tc_gemm(const __nv_bfloat16* __restrict__ Ah, const __nv_bfloat16* __restrict__ Al,
        const __nv_bfloat16* __restrict__ Wh, const __nv_bfloat16* __restrict__ Wl,
        const float* __restrict__ bias, const float* __restrict__ R,
        float* __restrict__ C, __nv_bfloat16* __restrict__ Ch, __nv_bfloat16* __restrict__ Cl,
        int M, int N, int K) {
    extern __shared__ char smem[];
    const uint32_t sbase = smem_u32(smem);
    const int tid = threadIdx.x;
    const int wid = tid >> 5;
    const int lane = tid & 31;
    const int rowBase = blockIdx.y * 64;
    const int colBase = blockIdx.x * 128;
    const int warpM = wid >> 2;
    const int warpN = wid & 3;

    float acc[2][4][4];
#pragma unroll
    for (int mi = 0; mi < 2; mi++)
#pragma unroll
        for (int ni = 0; ni < 4; ni++)
#pragma unroll
            for (int j = 0; j < 4; j++) acc[mi][ni][j] = 0.f;

    const uint32_t swX = (uint32_t)((lane & 7) << 4);
    const int aKB0 = (lane >> 4) * 16;
    uint32_t aRowOff[2];
#pragma unroll
    for (int mi = 0; mi < 2; mi++)
        aRowOff[mi] = (uint32_t)((warpM * 32 + mi * 16 + (lane & 15)) * 128);
    const int grp = lane >> 3;
    const int bKB0 = (grp & 1) * 16;
    uint32_t bRowOff[2];
#pragma unroll
    for (int np = 0; np < 2; np++)
        bRowOff[np] = (uint32_t)((warpN * 32 + np * 16 + ((grp >> 1) << 3) + (lane & 7)) * 128);

    const int nChunks = K / KC;

    auto copy_chunk = [&](int kt, uint32_t stg) {
        const int k0 = kt * KC;
        // B planes first (2x data; issue earliest)
#pragma unroll
        for (int i = 0; i < 4; i++) {
            int idx = tid + i * 256;
            int r = idx >> 3, c = idx & 7;
            uint32_t off = (uint32_t)(r * 128 + ((c * 16) ^ ((r & 7) << 4)));
            cpa16(stg + 2 * A_TILE_B + off, Wh + (size_t)(colBase + r) * K + k0 + c * 8);
            cpa16(stg + 2 * A_TILE_B + B_TILE_B + off,
                  Wl + (size_t)(colBase + r) * K + k0 + c * 8);
        }
#pragma unroll
        for (int i = 0; i < 2; i++) {
            int idx = tid + i * 256;
            int r = idx >> 3, c = idx & 7;
            uint32_t off = (uint32_t)(r * 128 + ((c * 16) ^ ((r & 7) << 4)));
            int gr = rowBase + r;
            bool v = gr < M;
            int cr = v ? gr : (M - 1);
            cpa16z(stg + off, Ah + (size_t)cr * K + k0 + c * 8, v);
            cpa16z(stg + A_TILE_B + off, Al + (size_t)cr * K + k0 + c * 8, v);
        }
    };

    copy_chunk(0, sbase);
    asm volatile("cp.async.commit_group;");

    for (int kt = 0; kt < nChunks; kt++) {
        if (kt + 1 < nChunks) {
            copy_chunk(kt + 1, sbase + (uint32_t)(((kt + 1) & 1) * STAGE_B));
            asm volatile("cp.async.commit_group;");
            asm volatile("cp.async.wait_group 1;");
        } else {
            asm volatile("cp.async.wait_group 0;");
        }
        __syncthreads();
        const uint32_t stg = sbase + (uint32_t)((kt & 1) * STAGE_B);
        const uint32_t AhS = stg, AlS = stg + A_TILE_B;
        const uint32_t BhS = stg + 2 * A_TILE_B, BlS = BhS + B_TILE_B;
#pragma unroll
        for (int kst = 0; kst < 4; kst++) {
            uint32_t ah[2][4], al[2][4];
#pragma unroll
            for (int mi = 0; mi < 2; mi++) {
                uint32_t off = aRowOff[mi] + (uint32_t)((aKB0 + kst * 32) ^ swX);
                ldm_x4(AhS + off, ah[mi][0], ah[mi][1], ah[mi][2], ah[mi][3]);
                ldm_x4(AlS + off, al[mi][0], al[mi][1], al[mi][2], al[mi][3]);
            }
            uint32_t bh[4][2], bl[4][2];
#pragma unroll
            for (int np = 0; np < 2; np++) {
                uint32_t off = bRowOff[np] + (uint32_t)((bKB0 + kst * 32) ^ swX);
                uint32_t r0, r1, r2, r3;
                ldm_x4(BhS + off, r0, r1, r2, r3);
                bh[np * 2][0] = r0; bh[np * 2][1] = r1;
                bh[np * 2 + 1][0] = r2; bh[np * 2 + 1][1] = r3;
                ldm_x4(BlS + off, r0, r1, r2, r3);
                bl[np * 2][0] = r0; bl[np * 2][1] = r1;
                bl[np * 2 + 1][0] = r2; bl[np * 2 + 1][1] = r3;
            }
#pragma unroll
            for (int mi = 0; mi < 2; mi++)
#pragma unroll
                for (int ni = 0; ni < 4; ni++) mma_bf16(acc[mi][ni], ah[mi], bh[ni]);
#pragma unroll
            for (int mi = 0; mi < 2; mi++)
#pragma unroll
                for (int ni = 0; ni < 4; ni++) mma_bf16(acc[mi][ni], ah[mi], bl[ni]);
#pragma unroll
            for (int mi = 0; mi < 2; mi++)
#pragma unroll
                for (int ni = 0; ni < 4; ni++) mma_bf16(acc[mi][ni], al[mi], bh[ni]);
        }
        if (kt + 1 < nChunks) __syncthreads();
    }

    // ---- epilogue ----
    const int qrow = lane >> 2;
    const int qcol = (lane & 3) * 2;
#pragma unroll
    for (int ni = 0; ni < 4; ni++) {
        int col = colBase + warpN * 32 + ni * 8 + qcol;
        float b0 = __ldg(bias + col), b1 = __ldg(bias + col + 1);
#pragma unroll
        for (int mi = 0; mi < 2; mi++) {
            acc[mi][ni][0] += b0; acc[mi][ni][1] += b1;
            acc[mi][ni][2] += b0; acc[mi][ni][3] += b1;
        }
    }
    if (MODE == 3) {
#pragma unroll
        for (int mi = 0; mi < 2; mi++)
#pragma unroll
            for (int g = 0; g < 2; g++)
#pragma unroll
                for (int rh = 0; rh < 2; rh++) {
                    float v0 = acc[mi][2 * g][rh * 2], v1 = acc[mi][2 * g][rh * 2 + 1];
                    float v2 = acc[mi][2 * g + 1][rh * 2], v3 = acc[mi][2 * g + 1][rh * 2 + 1];
                    float mx = fmaxf(fmaxf(v0, v1), fmaxf(v2, v3));
                    mx = fmaxf(mx, __shfl_xor_sync(0xffffffffu, mx, 1));
                    mx = fmaxf(mx, __shfl_xor_sync(0xffffffffu, mx, 2));
                    v0 = expf(v0 - mx); v1 = expf(v1 - mx);
                    v2 = expf(v2 - mx); v3 = expf(v3 - mx);
                    float s = v0 + v1 + v2 + v3;
                    s += __shfl_xor_sync(0xffffffffu, s, 1);
                    s += __shfl_xor_sync(0xffffffffu, s, 2);
                    float inv = 1.f / s;
                    acc[mi][2 * g][rh * 2] = v0 * inv; acc[mi][2 * g][rh * 2 + 1] = v1 * inv;
                    acc[mi][2 * g + 1][rh * 2] = v2 * inv; acc[mi][2 * g + 1][rh * 2 + 1] = v3 * inv;
                }
    }
#pragma unroll
    for (int mi = 0; mi < 2; mi++)
#pragma unroll
        for (int rh = 0; rh < 2; rh++) {
            int row = rowBase + warpM * 32 + mi * 16 + qrow + rh * 8;
            if (row >= M) continue;
#pragma unroll
            for (int ni = 0; ni < 4; ni++) {
                int col = colBase + warpN * 32 + ni * 8 + qcol;
                float v0 = acc[mi][ni][rh * 2], v1 = acc[mi][ni][rh * 2 + 1];
                if (MODE == 1) {
                    const float2 rr = *(const float2*)(R + (size_t)row * N + col);
                    v0 += rr.x; v1 += rr.y;
                }
                if (MODE == 2) { v0 = fmaxf(v0, 0.f); v1 = fmaxf(v1, 0.f); }
                if (OSPLIT) {
                    uint32_t lo;
                    uint32_t hi = split2(v0, v1, lo);
                    *(uint32_t*)(Ch + (size_t)row * N + col) = hi;
                    *(uint32_t*)(Cl + (size_t)row * N + col) = lo;
                } else {
                    *(float2*)(C + (size_t)row * N + col) = make_float2(v0, v1);
                }
            }
        }
}

// ---------------- batched weight conversion: all 8 weights in one launch ----------------
struct WJob { const float* s; __nv_bfloat16* h; __nv_bfloat16* l; int n4; };
struct WJobs { WJob j[8]; };

__global__ void wconv_kernel(WJobs J) {
    int i = blockIdx.x * blockDim.x + threadIdx.x;
#pragma unroll
    for (int k = 0; k < 8; k++) {
        int n = J.j[k].n4;
        if (i < n) {
            float4 v = ((const float4*)J.j[k].s)[i];
            uint2 h, l;
            split4(v, h, l);
            ((uint2*)J.j[k].h)[i] = h;
            ((uint2*)J.j[k].l)[i] = l;
            return;
        }
        i -= n;
    }
}

// ---------------- activation conversion: src and src+pos in one launch ----------------
__global__ void actconv_kernel(const float* __restrict__ src, const float* __restrict__ pos,
                               __nv_bfloat16* __restrict__ Ah, __nv_bfloat16* __restrict__ Al,
                               __nv_bfloat16* __restrict__ Bh, __nv_bfloat16* __restrict__ Bl,
                               int n4) {
    int i = blockIdx.x * blockDim.x + threadIdx.x;
    if (i >= n4) return;
    float4 s = ((const float4*)src)[i];
    float4 p = ((const float4*)pos)[i];
    uint2 h, l;
    split4(s, h, l);
    ((uint2*)Ah)[i] = h;
    ((uint2*)Al)[i] = l;
    s.x += p.x; s.y += p.y; s.z += p.z; s.w += p.w;
    split4(s, h, l);
    ((uint2*)Bh)[i] = h;
    ((uint2*)Bl)[i] = l;
}

// ---------------- multi-scale deformable sampling (split bf16 out) ----------------
__global__ void msdeform_kernel(const float* __restrict__ value, const float* __restrict__ offs,
                                const float* __restrict__ aw, const float* __restrict__ ref,
                                __nv_bfloat16* __restrict__ outh, __nv_bfloat16* __restrict__ outl) {
    int gw = (blockIdx.x * blockDim.x + threadIdx.x) >> 5;
    int lane = threadIdx.x & 31;
    if (gw >= NTOK * NH) return;
    int token = gw >> 3, h = gw & 7;
    int b = (token >= LQ_C) ? 1 : 0;

    int p = lane & 15;
    int l = p >> 2;
    int Wl = c_W[l], Hl = c_H[l];
    float Wf = (float)Wl, Hf = (float)Hl;
    float rx = __ldg(ref + (size_t)token * 8 + l * 2);
    float ry = __ldg(ref + (size_t)token * 8 + l * 2 + 1);
    float ox = __ldg(offs + (size_t)token * 256 + h * 32 + p * 2);
    float oy = __ldg(offs + (size_t)token * 256 + h * 32 + p * 2 + 1);
    float wA = __ldg(aw + (size_t)token * 128 + h * 16 + p);

    float X = (rx + ox / Wf) * Wf - 0.5f;
    float Y = (ry + oy / Hf) * Hf - 0.5f;
    float x0f = floorf(X), y0f = floorf(Y);
    float lx = X - x0f, ly = Y - y0f;
    int x0 = (int)x0f, y0 = (int)y0f;
    int x1 = x0 + 1, y1 = y0 + 1;
    bool vx0 = (x0 >= 0) & (x0 < Wl), vx1 = (x1 >= 0) & (x1 < Wl);
    bool vy0 = (y0 >= 0) & (y0 < Hl), vy1 = (y1 >= 0) & (y1 < Hl);
    int cx0 = min(max(x0, 0), Wl - 1), cx1 = min(max(x1, 0), Wl - 1);
    int cy0 = min(max(y0, 0), Hl - 1), cy1 = min(max(y1, 0), Hl - 1);
    int base = b * LQ_C + c_St[l];
    int r00 = base + cy0 * Wl + cx0;
    int r01 = base + cy0 * Wl + cx1;
    int r10 = base + cy1 * Wl + cx0;
    int r11 = base + cy1 * Wl + cx1;
    float w00 = wA * (1.f - lx) * (1.f - ly) * (float)(vx0 & vy0);
    float w01 = wA * lx * (1.f - ly) * (float)(vx1 & vy0);
    float w10 = wA * (1.f - lx) * ly * (float)(vx0 & vy1);
    float w11 = wA * lx * ly * (float)(vx1 & vy1);

    const float* vb = value + h * 32 + lane;
    float acc = 0.f;
#pragma unroll
    for (int pp = 0; pp < 16; pp++) {
        int s00 = __shfl_sync(0xffffffffu, r00, pp);
        int s01 = __shfl_sync(0xffffffffu, r01, pp);
        int s10 = __shfl_sync(0xffffffffu, r10, pp);
        int s11 = __shfl_sync(0xffffffffu, r11, pp);
        float u00 = __shfl_sync(0xffffffffu, w00, pp);
        float u01 = __shfl_sync(0xffffffffu, w01, pp);
        float u10 = __shfl_sync(0xffffffffu, w10, pp);
        float u11 = __shfl_sync(0xffffffffu, w11, pp);
        acc += u00 * __ldg(vb + (size_t)s00 * 256);
        acc += u01 * __ldg(vb + (size_t)s01 * 256);
        acc += u10 * __ldg(vb + (size_t)s10 * 256);
        acc += u11 * __ldg(vb + (size_t)s11 * 256);
    }
    __nv_bfloat16 hb = __float2bfloat16_rn(acc);
    __nv_bfloat16 lb = __float2bfloat16_rn(acc - __bfloat162float(hb));
    outh[(size_t)token * 256 + h * 32 + lane] = hb;
    outl[(size_t)token * 256 + h * 32 + lane] = lb;
}

// ---------------- layernorm: warp per row; optional (out+P) split bf16 ----------------
__global__ void ln_kernel(const float* __restrict__ in, const float* __restrict__ g,
                          const float* __restrict__ b, float* __restrict__ out,
                          const float* __restrict__ P,
                          __nv_bfloat16* __restrict__ oh, __nv_bfloat16* __restrict__ ol,
                          int rows) {
    int warp = (blockIdx.x * blockDim.x + threadIdx.x) >> 5;
    int lane = threadIdx.x & 31;
    if (warp >= rows) return;
    const float* x = in + (size_t)warp * 256;
    float v[8];
    float s = 0.f;
#pragma unroll
    for (int j = 0; j < 8; j++) { v[j] = x[j * 32 + lane]; s += v[j]; }
#pragma unroll
    for (int o = 16; o; o >>= 1) s += __shfl_xor_sync(0xffffffffu, s, o);
    float m = s * (1.f / 256.f);
    float s2 = 0.f;
#pragma unroll
    for (int j = 0; j < 8; j++) { float d = v[j] - m; s2 += d * d; }
#pragma unroll
    for (int o = 16; o; o >>= 1) s2 += __shfl_xor_sync(0xffffffffu, s2, o);
    float rstd = rsqrtf(s2 * (1.f / 256.f) + 1e-5f);
#pragma unroll
    for (int j = 0; j < 8; j++) {
        int col = j * 32 + lane;
        float y = (v[j] - m) * rstd * g[col] + b[col];
        out[(size_t)warp * 256 + col] = y;
        if (oh) {
            float t = P ? y + P[(size_t)warp * 256 + col] : y;
            __nv_bfloat16 hb = __float2bfloat16_rn(t);
            oh[(size_t)warp * 256 + col] = hb;
            ol[(size_t)warp * 256 + col] = __float2bfloat16_rn(t - __bfloat162float(hb));
        }
    }
}

// ---------------- text K/V projection (40 rows) ----------------
__global__ void kv_proj_kernel(const float* __restrict__ text, const float* __restrict__ ipw,
                               const float* __restrict__ ipb, float* __restrict__ kh,
                               float* __restrict__ vh) {
    int row = blockIdx.x;
    int c = threadIdx.x;
    const float* t = text + (size_t)row * 256;
    const float* wk = ipw + (size_t)(256 + c) * 256;
    const float* wv = ipw + (size_t)(512 + c) * 256;
    float sk = ipb[256 + c], sv = ipb[512 + c];
    for (int k = 0; k < 256; k++) {
        float tv = t[k];
        sk += tv * wk[k];
        sv += tv * wv[k];
    }
    kh[(size_t)row * 256 + c] = sk;
    vh[(size_t)row * 256 + c] = sv;
}

// ---------------- text cross-attention: thread per (token, head); split bf16 out ----------------
__global__ void cross_attn_kernel(const float* __restrict__ qh, const float* __restrict__ kh,
                                  const float* __restrict__ vh,
                                  __nv_bfloat16* __restrict__ ch, __nv_bfloat16* __restrict__ cl) {
    int idx = blockIdx.x * blockDim.x + threadIdx.x;
    if (idx >= NTOK * NH) return;
    int token = idx >> 3, h = idx & 7;
    int b = (token >= LQ_C) ? 1 : 0;
    const float4* q = (const float4*)(qh + (size_t)token * 256 + h * 32);
    float4 qv[8];
#pragma unroll
    for (int j = 0; j < 8; j++) qv[j] = q[j];

    float sc[LT];
    float mx = -1e30f;
    const float scale = 0.17677669529663687f;
#pragma unroll 4
    for (int k = 0; k < LT; k++) {
        const float4* kp = (const float4*)(kh + (size_t)(b * LT + k) * 256 + h * 32);
        float s = 0.f;
#pragma unroll
        for (int j = 0; j < 8; j++) {
            float4 kv = kp[j];
            s += qv[j].x * kv.x + qv[j].y * kv.y + qv[j].z * kv.z + qv[j].w * kv.w;
        }
        s *= scale;
        sc[k] = s;
        mx = fmaxf(mx, s);
    }
    float denom = 0.f;
#pragma unroll
    for (int k = 0; k < LT; k++) { sc[k] = expf(sc[k] - mx); denom += sc[k]; }
    float inv = 1.f / denom;
    float4 o[8];
#pragma unroll
    for (int j = 0; j < 8; j++) o[j] = make_float4(0.f, 0.f, 0.f, 0.f);
#pragma unroll 4
    for (int k = 0; k < LT; k++) {
        float pw = sc[k] * inv;
        const float4* vp = (const float4*)(vh + (size_t)(b * LT + k) * 256 + h * 32);
#pragma unroll
        for (int j = 0; j < 8; j++) {
            float4 vv = vp[j];
            o[j].x += pw * vv.x; o[j].y += pw * vv.y;
            o[j].z += pw * vv.z; o[j].w += pw * vv.w;
        }
    }
#pragma unroll
    for (int j = 0; j < 8; j++) {
        uint2 hh, ll;
        split4(o[j], hh, ll);
        *(uint2*)(ch + (size_t)token * 256 + h * 32 + j * 4) = hh;
        *(uint2*)(cl + (size_t)token * 256 + h * 32 + j * 4) = ll;
    }
}

// ---------------- launch ----------------
extern "C" void kernel_launch(void* const* d_in, const int* in_sizes, int n_in,
                              void* d_out, int out_size) {
    const float* src   = (const float*)d_in[0];
    const float* pos   = (const float*)d_in[1];
    const float* refp  = (const float*)d_in[2];
    const float* text  = (const float*)d_in[5];
    const float* so_w  = (const float*)d_in[7];
    const float* so_b  = (const float*)d_in[8];
    const float* aw_w  = (const float*)d_in[9];
    const float* aw_b  = (const float*)d_in[10];
    const float* vp_w  = (const float*)d_in[11];
    const float* vp_b  = (const float*)d_in[12];
    const float* op_w  = (const float*)d_in[13];
    const float* op_b  = (const float*)d_in[14];
    const float* ln1_g = (const float*)d_in[15];
    const float* ln1_b = (const float*)d_in[16];
    const float* ipw   = (const float*)d_in[17];
    const float* ipb   = (const float*)d_in[18];
    const float* mo_w  = (const float*)d_in[19];
    const float* mo_b  = (const float*)d_in[20];
    const float* ln3_g = (const float*)d_in[21];
    const float* ln3_b = (const float*)d_in[22];
    const float* l1_w  = (const float*)d_in[23];
    const float* l1_b  = (const float*)d_in[24];
    const float* l2_w  = (const float*)d_in[25];
    const float* l2_b  = (const float*)d_in[26];
    const float* ln2_g = (const float*)d_in[27];
    const float* ln2_b = (const float*)d_in[28];

    float* out_x = (float*)d_out;
    float* out_text = out_x + (size_t)NTOK * D_MODEL;

    float *q, *val, *offs, *aw, *kh, *vh;
    cudaGetSymbolAddress((void**)&q, g_q);
    cudaGetSymbolAddress((void**)&val, g_value);
    cudaGetSymbolAddress((void**)&offs, g_offs);
    cudaGetSymbolAddress((void**)&aw, g_aw);
    cudaGetSymbolAddress((void**)&kh, g_kh);
    cudaGetSymbolAddress((void**)&vh, g_vh);
    __nv_bfloat16 *Ah, *Al, *Bh, *Bl, *hh, *hl;
    cudaGetSymbolAddress((void**)&Ah, g_Ah);
    cudaGetSymbolAddress((void**)&Al, g_Al);
    cudaGetSymbolAddress((void**)&Bh, g_Bh);
    cudaGetSymbolAddress((void**)&Bl, g_Bl);
    cudaGetSymbolAddress((void**)&hh, g_hh);
    cudaGetSymbolAddress((void**)&hl, g_hl);
    __nv_bfloat16 *vpwh, *vpwl, *sowh, *sowl, *awwh, *awwl, *opwh, *opwl;
    __nv_bfloat16 *wqwh, *wqwl, *mowh, *mowl, *l1wh, *l1wl, *l2wh, *l2wl;
    cudaGetSymbolAddress((void**)&vpwh, g_vpw_h); cudaGetSymbolAddress((void**)&vpwl, g_vpw_l);
    cudaGetSymbolAddress((void**)&sowh, g_sow_h); cudaGetSymbolAddress((void**)&sowl, g_sow_l);
    cudaGetSymbolAddress((void**)&awwh, g_aww_h); cudaGetSymbolAddress((void**)&awwl, g_aww_l);
    cudaGetSymbolAddress((void**)&opwh, g_opw_h); cudaGetSymbolAddress((void**)&opwl, g_opw_l);
    cudaGetSymbolAddress((void**)&wqwh, g_wqw_h); cudaGetSymbolAddress((void**)&wqwl, g_wqw_l);
    cudaGetSymbolAddress((void**)&mowh, g_mow_h); cudaGetSymbolAddress((void**)&mowl, g_mow_l);
    cudaGetSymbolAddress((void**)&l1wh, g_l1w_h); cudaGetSymbolAddress((void**)&l1wl, g_l1w_l);
    cudaGetSymbolAddress((void**)&l2wh, g_l2w_h); cudaGetSymbolAddress((void**)&l2wl, g_l2w_l);

    cudaFuncSetAttribute(tc_gemm<0, false>, cudaFuncAttributeMaxDynamicSharedMemorySize, GEMM_SMEM);
    cudaFuncSetAttribute(tc_gemm<1, false>, cudaFuncAttributeMaxDynamicSharedMemorySize, GEMM_SMEM);
    cudaFuncSetAttribute(tc_gemm<2, true>, cudaFuncAttributeMaxDynamicSharedMemorySize, GEMM_SMEM);
    cudaFuncSetAttribute(tc_gemm<3, false>, cudaFuncAttributeMaxDynamicSharedMemorySize, GEMM_SMEM);

    const int M = NTOK;
    const int mTiles = cdiv(M, 64);
    dim3 g256(2, mTiles), g128(1, mTiles), g1024(8, mTiles);
    const int nAct4 = M * D_MODEL / 4;

    // ---- launch 1: all weight conversions batched ----
    WJobs J;
    J.j[0] = {vp_w, vpwh, vpwl, 65536 / 4};
    J.j[1] = {so_w, sowh, sowl, 65536 / 4};
    J.j[2] = {aw_w, awwh, awwl, 32768 / 4};
    J.j[3] = {op_w, opwh, opwl, 65536 / 4};
    J.j[4] = {ipw,  wqwh, wqwl, 65536 / 4};
    J.j[5] = {mo_w, mowh, mowl, 65536 / 4};
    J.j[6] = {l1_w, l1wh, l1wl, 262144 / 4};
    J.j[7] = {l2_w, l2wh, l2wl, 262144 / 4};
    int totW4 = (65536 * 5 + 32768 + 262144 * 2) / 4;
    wconv_kernel<<<cdiv(totW4, 256), 256>>>(J);
    // ---- launch 2: activation conversions (src -> A planes, src+pos -> B planes) ----
    actconv_kernel<<<cdiv(nAct4, 256), 256>>>(src, pos, Ah, Al, Bh, Bl, nAct4);
    // ---- launch 3: text K/V (independent; early for profiler window alignment) ----
    kv_proj_kernel<<<B_SZ * LT, 256>>>(text, ipw, ipb, kh, vh);
    // ---- launch 4: value = src @ vp^T + b ----
    tc_gemm<0, false><<<g256, 256, GEMM_SMEM>>>(Ah, Al, vpwh, vpwl, vp_b, nullptr, val,
                                                nullptr, nullptr, M, 256, 256);
    // ---- launch 5: offs = q @ so^T + b ----
    tc_gemm<0, false><<<g256, 256, GEMM_SMEM>>>(Bh, Bl, sowh, sowl, so_b, nullptr, offs,
                                                nullptr, nullptr, M, 256, 256);
    // ---- launch 6: aw = softmax16(q @ aw^T + b) ----
    tc_gemm<3, false><<<g128, 256, GEMM_SMEM>>>(Bh, Bl, awwh, awwl, aw_b, nullptr, aw,
                                                nullptr, nullptr, M, 128, 256);
    // 7) deformable sampling -> ms (split bf16 into A planes)
    msdeform_kernel<<<cdiv(M * NH * 32, 256), 256>>>(val, offs, aw, refp, Ah, Al);
    // 8) preLN1 = ms @ op^T + b + src ; LN1 -> out_x + (out+pos) split into B planes
    tc_gemm<1, false><<<g256, 256, GEMM_SMEM>>>(Ah, Al, opwh, opwl, op_b, src, offs,
                                                nullptr, nullptr, M, 256, 256);
    ln_kernel<<<cdiv(M * 32, 256), 256>>>(offs, ln1_g, ln1_b, out_x, pos, Bh, Bl, M);
    // 9) qh = (x+pos) @ wq^T + bq
    tc_gemm<0, false><<<g256, 256, GEMM_SMEM>>>(Bh, Bl, wqwh, wqwl, ipb, nullptr, q,
                                                nullptr, nullptr, M, 256, 256);
    // 10) cross attention -> ctx (split bf16 into A planes)
    cross_attn_kernel<<<cdiv(M * NH, 256), 256>>>(q, kh, vh, Ah, Al);
    // 11) preLN3 = ctx @ mo^T + b + x ; LN3 -> out_x + split into B planes
    tc_gemm<1, false><<<g256, 256, GEMM_SMEM>>>(Ah, Al, mowh, mowl, mo_b, out_x, val,
                                                nullptr, nullptr, M, 256, 256);
    ln_kernel<<<cdiv(M * 32, 256), 256>>>(val, ln3_g, ln3_b, out_x, nullptr, Bh, Bl, M);
    // 12) FFN
    tc_gemm<2, true><<<g1024, 256, GEMM_SMEM>>>(Bh, Bl, l1wh, l1wl, l1_b, nullptr, nullptr,
                                                hh, hl, M, DFF, 256);
    tc_gemm<1, false><<<g256, 256, GEMM_SMEM>>>(hh, hl, l2wh, l2wl, l2_b, out_x, val,
                                                nullptr, nullptr, M, 256, DFF);
    ln_kernel<<<cdiv(M * 32, 256), 256>>>(val, ln2_g, ln2_b, out_x, nullptr, nullptr, nullptr, M);
    // 13) pass-through text_memory
    cudaMemcpyAsync(out_text, text, (size_t)B_SZ * LT * D_MODEL * sizeof(float),
                    cudaMemcpyDeviceToDevice, 0);
}

// round 9
// speedup vs baseline: 1.0537x; 1.0270x over previous
#include <cuda_runtime.h>
#include <cuda_bf16.h>
#include <cstdint>
#include <math.h>

// ---------------- problem constants ----------------
#define D_MODEL 256
#define NH 8
#define HD 32
#define NL 4
#define NP 4
#define DFF 1024
#define B_SZ 2
#define LT 20
#define LQ_C 20197
#define NTOK (B_SZ * LQ_C)   // 40394

__device__ __constant__ int c_H[NL]  = {100, 50, 25, 13};
__device__ __constant__ int c_W[NL]  = {152, 76, 38, 19};
__device__ __constant__ int c_St[NL] = {0, 15200, 19000, 19950};

// ---------------- scratch (static device globals; no allocation) ----------------
__device__ float g_q[NTOK * D_MODEL];
__device__ float g_value[NTOK * D_MODEL];
__device__ float g_offs[NTOK * D_MODEL];
__device__ float g_aw[NTOK * 128];
__device__ float g_kh[B_SZ * LT * D_MODEL];
__device__ float g_vh[B_SZ * LT * D_MODEL];
// bf16 split activation planes
__device__ __nv_bfloat16 g_Ah[NTOK * D_MODEL], g_Al[NTOK * D_MODEL];
__device__ __nv_bfloat16 g_Bh[NTOK * D_MODEL], g_Bl[NTOK * D_MODEL];
__device__ __nv_bfloat16 g_hh[NTOK * DFF], g_hl[NTOK * DFF];
// bf16 split weight planes
__device__ __nv_bfloat16 g_vpw_h[65536], g_vpw_l[65536];
__device__ __nv_bfloat16 g_sow_h[65536], g_sow_l[65536];
__device__ __nv_bfloat16 g_aww_h[32768], g_aww_l[32768];
__device__ __nv_bfloat16 g_opw_h[65536], g_opw_l[65536];
__device__ __nv_bfloat16 g_wqw_h[65536], g_wqw_l[65536];
__device__ __nv_bfloat16 g_mow_h[65536], g_mow_l[65536];
__device__ __nv_bfloat16 g_l1w_h[262144], g_l1w_l[262144];
__device__ __nv_bfloat16 g_l2w_h[262144], g_l2w_l[262144];

static inline int cdiv(int a, int b) { return (a + b - 1) / b; }

__device__ __forceinline__ uint32_t smem_u32(const void* p) {
    uint32_t a;
    asm("{ .reg .u64 t; cvta.to.shared.u64 t, %1; cvt.u32.u64 %0, t; }" : "=r"(a) : "l"(p));
    return a;
}

__device__ __forceinline__ void ldm_x4(uint32_t addr, uint32_t& r0, uint32_t& r1,
                                       uint32_t& r2, uint32_t& r3) {
    asm volatile("ldmatrix.sync.aligned.m8n8.x4.shared.b16 {%0,%1,%2,%3}, [%4];"
                 : "=r"(r0), "=r"(r1), "=r"(r2), "=r"(r3) : "r"(addr));
}

__device__ __forceinline__ void mma_bf16(float* c, const uint32_t* a, const uint32_t* b) {
    asm volatile(
        "mma.sync.aligned.m16n8k16.row.col.f32.bf16.bf16.f32 "
        "{%0,%1,%2,%3}, {%4,%5,%6,%7}, {%8,%9}, {%0,%1,%2,%3};"
        : "+f"(c[0]), "+f"(c[1]), "+f"(c[2]), "+f"(c[3])
        : "r"(a[0]), "r"(a[1]), "r"(a[2]), "r"(a[3]), "r"(b[0]), "r"(b[1]));
}

__device__ __forceinline__ void split4(float4 v, uint2& h, uint2& l) {
    union U { __nv_bfloat16 b[4]; uint2 u; } H, L;
    H.b[0] = __float2bfloat16_rn(v.x);
    H.b[1] = __float2bfloat16_rn(v.y);
    H.b[2] = __float2bfloat16_rn(v.z);
    H.b[3] = __float2bfloat16_rn(v.w);
    L.b[0] = __float2bfloat16_rn(v.x - __bfloat162float(H.b[0]));
    L.b[1] = __float2bfloat16_rn(v.y - __bfloat162float(H.b[1]));
    L.b[2] = __float2bfloat16_rn(v.z - __bfloat162float(H.b[2]));
    L.b[3] = __float2bfloat16_rn(v.w - __bfloat162float(H.b[3]));
    h = H.u; l = L.u;
}
__device__ __forceinline__ uint32_t split2(float v0, float v1, uint32_t& lo) {
    union U { __nv_bfloat16 b[2]; uint32_t u; } H, L;
    H.b[0] = __float2bfloat16_rn(v0);
    H.b[1] = __float2bfloat16_rn(v1);
    L.b[0] = __float2bfloat16_rn(v0 - __bfloat162float(H.b[0]));
    L.b[1] = __float2bfloat16_rn(v1 - __bfloat162float(H.b[1]));
    lo = L.u;
    return H.u;
}

__device__ __forceinline__ void cpa16(uint32_t dst, const void* src) {
    asm volatile("cp.async.cg.shared.global [%0], [%1], 16;" :: "r"(dst), "l"(src));
}
__device__ __forceinline__ void cpa16z(uint32_t dst, const void* src, bool v) {
    int sz = v ? 16 : 0;
    asm volatile("cp.async.cg.shared.global [%0], [%1], 16, %2;"
                 :: "r"(dst), "l"(src), "r"(sz));
}

// =====================================================================
// bf16-split tensor-core GEMM on PRE-SPLIT operands:
//   C = (Ah+Al)[M,K] @ (Wh+Wl)[N,K]^T + bias  (3-pass: hh + hl + lh)
//   MODE 0: +bias  1: +bias+residual  2: +bias,relu
//   MODE 4: fused dual output — blocks x<2: C (stride N) +bias;
//           block x==2: W2/bias2 -> softmax16 -> C2 (stride 128)
//   OSPLIT: write C as split bf16 planes (Ch, Cl)
//   CTA 64(M) x 128(N), 256 thr (warp tile 32x32), K-chunk 32,
//   3 cp.async stages (24KB each; h|l interleaved in 128B rows),
//   ONE __syncthreads per chunk -> 2 CTAs/SM.
// =====================================================================
#define KC 32
#define A_TILE_B 8192                   // 64 rows x 128B (h|l)
#define B_TILE_B 16384                  // 128 rows x 128B (h|l)
#define STAGE_B (A_TILE_B + B_TILE_B)   // 24 KB
#define NSTAGE 3
#define GEMM_SMEM (NSTAGE * STAGE_B)    // 72 KB

template <int MODE, bool OSPLIT>
__global__ void __launch_bounds__(256, 2)
tc_gemm(const __nv_bfloat16* __restrict__ Ah, const __nv_bfloat16* __restrict__ Al,
        const __nv_bfloat16* __restrict__ Wh, const __nv_bfloat16* __restrict__ Wl,
        const __nv_bfloat16* __restrict__ W2h, const __nv_bfloat16* __restrict__ W2l,
        const float* __restrict__ bias, const float* __restrict__ bias2,
        const float* __restrict__ R, float* __restrict__ C, float* __restrict__ C2,
        __nv_bfloat16* __restrict__ Ch, __nv_bfloat16* __restrict__ Cl,
        int M, int N, int K) {
    extern __shared__ char smem[];
    const uint32_t sbase = smem_u32(smem);
    const int tid = threadIdx.x;
    const int wid = tid >> 5;
    const int lane = tid & 31;
    const int rowBase = blockIdx.y * 64;
    const int colBase = blockIdx.x * 128;
    const int warpM = wid >> 2;
    const int warpN = wid & 3;
    const bool isAw = (MODE == 4) && (blockIdx.x == 2);

    // effective weight-plane base pointers for this column block
    const __nv_bfloat16* bWh = isAw ? W2h : (Wh + (size_t)colBase * K);
    const __nv_bfloat16* bWl = isAw ? W2l : (Wl + (size_t)colBase * K);

    float acc[2][4][4];
#pragma unroll
    for (int mi = 0; mi < 2; mi++)
#pragma unroll
        for (int ni = 0; ni < 4; ni++)
#pragma unroll
            for (int j = 0; j < 4; j++) acc[mi][ni][j] = 0.f;

    // ldmatrix per-lane offsets; swizzle XOR reduces to (lane&7)<<4
    const uint32_t swX = (uint32_t)((lane & 7) << 4);
    const int aKB0 = (lane >> 4) * 16;
    uint32_t aRowOff[2];
#pragma unroll
    for (int mi = 0; mi < 2; mi++)
        aRowOff[mi] = (uint32_t)((warpM * 32 + mi * 16 + (lane & 15)) * 128);
    const int grp = lane >> 3;
    const int bKB0 = (grp & 1) * 16;
    uint32_t bRowOff[2];
#pragma unroll
    for (int np = 0; np < 2; np++)
        bRowOff[np] = (uint32_t)((warpN * 32 + np * 16 + ((grp >> 1) << 3) + (lane & 7)) * 128);

    const int nChunks = K / KC;

    // per-thread copy coords: A: r=tid>>2 (0..63), c=tid&3; B: idx-based
    const int cA_r = tid >> 2, cA_c = tid & 3;
    const uint32_t cA_offH = (uint32_t)(cA_r * 128 + ((cA_c * 16) ^ ((cA_r & 7) << 4)));
    const uint32_t cA_offL = (uint32_t)(cA_r * 128 + (((cA_c + 4) * 16) ^ ((cA_r & 7) << 4)));
    const int gA = rowBase + cA_r;
    const bool vA = gA < M;
    const int cAr = vA ? gA : (M - 1);

    auto copy_chunk = [&](int kt, uint32_t stg) {
        const int k0 = kt * KC;
        // B: 128 rows x 4 chunks x 2 planes -> 2 iters of (h,l) per thread
#pragma unroll
        for (int i = 0; i < 2; i++) {
            int idx = tid + i * 256;
            int r = idx >> 2, c = idx & 3;
            uint32_t oh = (uint32_t)(r * 128 + ((c * 16) ^ ((r & 7) << 4)));
            uint32_t ol = (uint32_t)(r * 128 + (((c + 4) * 16) ^ ((r & 7) << 4)));
            const size_t gsrc = (size_t)r * K + k0 + c * 8;
            cpa16(stg + A_TILE_B + oh, bWh + gsrc);
            cpa16(stg + A_TILE_B + ol, bWl + gsrc);
        }
        // A: 64 rows x 4 chunks x 2 planes -> 1 iter of (h,l) per thread
        {
            const size_t gsrc = (size_t)cAr * K + k0 + cA_c * 8;
            cpa16z(stg + cA_offH, Ah + gsrc, vA);
            cpa16z(stg + cA_offL, Al + gsrc, vA);
        }
    };

    // prologue: 2 chunks in flight
    copy_chunk(0, sbase);
    asm volatile("cp.async.commit_group;");
    if (nChunks > 1) {
        copy_chunk(1, sbase + STAGE_B);
        asm volatile("cp.async.commit_group;");
    }

    int stgIdx = 0;
    for (int kt = 0; kt < nChunks; kt++) {
        if (kt + 1 < nChunks) {
            asm volatile("cp.async.wait_group 1;");
        } else {
            asm volatile("cp.async.wait_group 0;");
        }
        __syncthreads();
        if (kt + 2 < nChunks) {
            int ws = stgIdx + 2;
            if (ws >= NSTAGE) ws -= NSTAGE;
            copy_chunk(kt + 2, sbase + (uint32_t)(ws * STAGE_B));
            asm volatile("cp.async.commit_group;");
        }
        const uint32_t AS = sbase + (uint32_t)(stgIdx * STAGE_B);
        const uint32_t BS = AS + A_TILE_B;
#pragma unroll
        for (int kst = 0; kst < 2; kst++) {
            uint32_t ah[2][4], al[2][4];
#pragma unroll
            for (int mi = 0; mi < 2; mi++) {
                uint32_t kb = (uint32_t)(aKB0 + kst * 32);
                ldm_x4(AS + aRowOff[mi] + (kb ^ swX),
                       ah[mi][0], ah[mi][1], ah[mi][2], ah[mi][3]);
                ldm_x4(AS + aRowOff[mi] + ((kb + 64) ^ swX),
                       al[mi][0], al[mi][1], al[mi][2], al[mi][3]);
            }
            uint32_t bh[4][2], bl[4][2];
#pragma unroll
            for (int np = 0; np < 2; np++) {
                uint32_t kb = (uint32_t)(bKB0 + kst * 32);
                uint32_t r0, r1, r2, r3;
                ldm_x4(BS + bRowOff[np] + (kb ^ swX), r0, r1, r2, r3);
                bh[np * 2][0] = r0; bh[np * 2][1] = r1;
                bh[np * 2 + 1][0] = r2; bh[np * 2 + 1][1] = r3;
                ldm_x4(BS + bRowOff[np] + ((kb + 64) ^ swX), r0, r1, r2, r3);
                bl[np * 2][0] = r0; bl[np * 2][1] = r1;
                bl[np * 2 + 1][0] = r2; bl[np * 2 + 1][1] = r3;
            }
#pragma unroll
            for (int mi = 0; mi < 2; mi++)
#pragma unroll
                for (int ni = 0; ni < 4; ni++) mma_bf16(acc[mi][ni], ah[mi], bh[ni]);
#pragma unroll
            for (int mi = 0; mi < 2; mi++)
#pragma unroll
                for (int ni = 0; ni < 4; ni++) mma_bf16(acc[mi][ni], ah[mi], bl[ni]);
#pragma unroll
            for (int mi = 0; mi < 2; mi++)
#pragma unroll
                for (int ni = 0; ni < 4; ni++) mma_bf16(acc[mi][ni], al[mi], bh[ni]);
        }
        stgIdx++;
        if (stgIdx == NSTAGE) stgIdx = 0;
    }

    // ---- epilogue ----
    const int qrow = lane >> 2;
    const int qcol = (lane & 3) * 2;
#pragma unroll
    for (int ni = 0; ni < 4; ni++) {
        int cl_ = warpN * 32 + ni * 8 + qcol;
        int bcol = isAw ? cl_ : (colBase + cl_);
        const float* bp = isAw ? bias2 : bias;
        float b0 = __ldg(bp + bcol), b1 = __ldg(bp + bcol + 1);
#pragma unroll
        for (int mi = 0; mi < 2; mi++) {
            acc[mi][ni][0] += b0; acc[mi][ni][1] += b1;
            acc[mi][ni][2] += b0; acc[mi][ni][3] += b1;
        }
    }
    if (isAw) {
        // softmax over 16-col groups: group g covers n-tiles 2g, 2g+1
#pragma unroll
        for (int mi = 0; mi < 2; mi++)
#pragma unroll
            for (int g = 0; g < 2; g++)
#pragma unroll
                for (int rh = 0; rh < 2; rh++) {
                    float v0 = acc[mi][2 * g][rh * 2], v1 = acc[mi][2 * g][rh * 2 + 1];
                    float v2 = acc[mi][2 * g + 1][rh * 2], v3 = acc[mi][2 * g + 1][rh * 2 + 1];
                    float mx = fmaxf(fmaxf(v0, v1), fmaxf(v2, v3));
                    mx = fmaxf(mx, __shfl_xor_sync(0xffffffffu, mx, 1));
                    mx = fmaxf(mx, __shfl_xor_sync(0xffffffffu, mx, 2));
                    v0 = expf(v0 - mx); v1 = expf(v1 - mx);
                    v2 = expf(v2 - mx); v3 = expf(v3 - mx);
                    float s = v0 + v1 + v2 + v3;
                    s += __shfl_xor_sync(0xffffffffu, s, 1);
                    s += __shfl_xor_sync(0xffffffffu, s, 2);
                    float inv = 1.f / s;
                    acc[mi][2 * g][rh * 2] = v0 * inv; acc[mi][2 * g][rh * 2 + 1] = v1 * inv;
                    acc[mi][2 * g + 1][rh * 2] = v2 * inv; acc[mi][2 * g + 1][rh * 2 + 1] = v3 * inv;
                }
    }
#pragma unroll
    for (int mi = 0; mi < 2; mi++)
#pragma unroll
        for (int rh = 0; rh < 2; rh++) {
            int row = rowBase + warpM * 32 + mi * 16 + qrow + rh * 8;
            if (row >= M) continue;
#pragma unroll
            for (int ni = 0; ni < 4; ni++) {
                int cl_ = warpN * 32 + ni * 8 + qcol;
                float v0 = acc[mi][ni][rh * 2], v1 = acc[mi][ni][rh * 2 + 1];
                if (MODE == 1) {
                    int col = colBase + cl_;
                    const float2 rr = *(const float2*)(R + (size_t)row * N + col);
                    v0 += rr.x; v1 += rr.y;
                }
                if (MODE == 2) { v0 = fmaxf(v0, 0.f); v1 = fmaxf(v1, 0.f); }
                if (OSPLIT) {
                    uint32_t lo;
                    uint32_t hi = split2(v0, v1, lo);
                    *(uint32_t*)(Ch + (size_t)row * N + colBase + cl_) = hi;
                    *(uint32_t*)(Cl + (size_t)row * N + colBase + cl_) = lo;
                } else if (isAw) {
                    *(float2*)(C2 + (size_t)row * 128 + cl_) = make_float2(v0, v1);
                } else {
                    *(float2*)(C + (size_t)row * N + colBase + cl_) = make_float2(v0, v1);
                }
            }
        }
}

// ---------------- batched weight conversion: all 8 weights in one launch ----------------
struct WJob { const float* s; __nv_bfloat16* h; __nv_bfloat16* l; int n4; };
struct WJobs { WJob j[8]; };

__global__ void wconv_kernel(WJobs J) {
    int i = blockIdx.x * blockDim.x + threadIdx.x;
#pragma unroll
    for (int k = 0; k < 8; k++) {
        int n = J.j[k].n4;
        if (i < n) {
            float4 v = ((const float4*)J.j[k].s)[i];
            uint2 h, l;
            split4(v, h, l);
            ((uint2*)J.j[k].h)[i] = h;
            ((uint2*)J.j[k].l)[i] = l;
            return;
        }
        i -= n;
    }
}

// ---------------- activation conversion: src and src+pos in one launch ----------------
__global__ void actconv_kernel(const float* __restrict__ src, const float* __restrict__ pos,
                               __nv_bfloat16* __restrict__ Ah, __nv_bfloat16* __restrict__ Al,
                               __nv_bfloat16* __restrict__ Bh, __nv_bfloat16* __restrict__ Bl,
                               int n4) {
    int i = blockIdx.x * blockDim.x + threadIdx.x;
    if (i >= n4) return;
    float4 s = ((const float4*)src)[i];
    float4 p = ((const float4*)pos)[i];
    uint2 h, l;
    split4(s, h, l);
    ((uint2*)Ah)[i] = h;
    ((uint2*)Al)[i] = l;
    s.x += p.x; s.y += p.y; s.z += p.z; s.w += p.w;
    split4(s, h, l);
    ((uint2*)Bh)[i] = h;
    ((uint2*)Bl)[i] = l;
}

// ---------------- multi-scale deformable sampling (split bf16 out) ----------------
__global__ void msdeform_kernel(const float* __restrict__ value, const float* __restrict__ offs,
                                const float* __restrict__ aw, const float* __restrict__ ref,
                                __nv_bfloat16* __restrict__ outh, __nv_bfloat16* __restrict__ outl) {
    int gw = (blockIdx.x * blockDim.x + threadIdx.x) >> 5;
    int lane = threadIdx.x & 31;
    if (gw >= NTOK * NH) return;
    int token = gw >> 3, h = gw & 7;
    int b = (token >= LQ_C) ? 1 : 0;

    int p = lane & 15;
    int l = p >> 2;
    int Wl = c_W[l], Hl = c_H[l];
    float Wf = (float)Wl, Hf = (float)Hl;
    float rx = __ldg(ref + (size_t)token * 8 + l * 2);
    float ry = __ldg(ref + (size_t)token * 8 + l * 2 + 1);
    float ox = __ldg(offs + (size_t)token * 256 + h * 32 + p * 2);
    float oy = __ldg(offs + (size_t)token * 256 + h * 32 + p * 2 + 1);
    float wA = __ldg(aw + (size_t)token * 128 + h * 16 + p);

    float X = (rx + ox / Wf) * Wf - 0.5f;
    float Y = (ry + oy / Hf) * Hf - 0.5f;
    float x0f = floorf(X), y0f = floorf(Y);
    float lx = X - x0f, ly = Y - y0f;
    int x0 = (int)x0f, y0 = (int)y0f;
    int x1 = x0 + 1, y1 = y0 + 1;
    bool vx0 = (x0 >= 0) & (x0 < Wl), vx1 = (x1 >= 0) & (x1 < Wl);
    bool vy0 = (y0 >= 0) & (y0 < Hl), vy1 = (y1 >= 0) & (y1 < Hl);
    int cx0 = min(max(x0, 0), Wl - 1), cx1 = min(max(x1, 0), Wl - 1);
    int cy0 = min(max(y0, 0), Hl - 1), cy1 = min(max(y1, 0), Hl - 1);
    int base = b * LQ_C + c_St[l];
    int r00 = base + cy0 * Wl + cx0;
    int r01 = base + cy0 * Wl + cx1;
    int r10 = base + cy1 * Wl + cx0;
    int r11 = base + cy1 * Wl + cx1;
    float w00 = wA * (1.f - lx) * (1.f - ly) * (float)(vx0 & vy0);
    float w01 = wA * lx * (1.f - ly) * (float)(vx1 & vy0);
    float w10 = wA * (1.f - lx) * ly * (float)(vx0 & vy1);
    float w11 = wA * lx * ly * (float)(vx1 & vy1);

    const float* vb = value + h * 32 + lane;
    float acc = 0.f;
#pragma unroll
    for (int pp = 0; pp < 16; pp++) {
        int s00 = __shfl_sync(0xffffffffu, r00, pp);
        int s01 = __shfl_sync(0xffffffffu, r01, pp);
        int s10 = __shfl_sync(0xffffffffu, r10, pp);
        int s11 = __shfl_sync(0xffffffffu, r11, pp);
        float u00 = __shfl_sync(0xffffffffu, w00, pp);
        float u01 = __shfl_sync(0xffffffffu, w01, pp);
        float u10 = __shfl_sync(0xffffffffu, w10, pp);
        float u11 = __shfl_sync(0xffffffffu, w11, pp);
        acc += u00 * __ldg(vb + (size_t)s00 * 256);
        acc += u01 * __ldg(vb + (size_t)s01 * 256);
        acc += u10 * __ldg(vb + (size_t)s10 * 256);
        acc += u11 * __ldg(vb + (size_t)s11 * 256);
    }
    __nv_bfloat16 hb = __float2bfloat16_rn(acc);
    __nv_bfloat16 lb = __float2bfloat16_rn(acc - __bfloat162float(hb));
    outh[(size_t)token * 256 + h * 32 + lane] = hb;
    outl[(size_t)token * 256 + h * 32 + lane] = lb;
}

// ---------------- layernorm: warp per row; optional (out+P) split bf16 ----------------
__global__ void ln_kernel(const float* __restrict__ in, const float* __restrict__ g,
                          const float* __restrict__ b, float* __restrict__ out,
                          const float* __restrict__ P,
                          __nv_bfloat16* __restrict__ oh, __nv_bfloat16* __restrict__ ol,
                          int rows) {
    int warp = (blockIdx.x * blockDim.x + threadIdx.x) >> 5;
    int lane = threadIdx.x & 31;
    if (warp >= rows) return;
    const float* x = in + (size_t)warp * 256;
    float v[8];
    float s = 0.f;
#pragma unroll
    for (int j = 0; j < 8; j++) { v[j] = x[j * 32 + lane]; s += v[j]; }
#pragma unroll
    for (int o = 16; o; o >>= 1) s += __shfl_xor_sync(0xffffffffu, s, o);
    float m = s * (1.f / 256.f);
    float s2 = 0.f;
#pragma unroll
    for (int j = 0; j < 8; j++) { float d = v[j] - m; s2 += d * d; }
#pragma unroll
    for (int o = 16; o; o >>= 1) s2 += __shfl_xor_sync(0xffffffffu, s2, o);
    float rstd = rsqrtf(s2 * (1.f / 256.f) + 1e-5f);
#pragma unroll
    for (int j = 0; j < 8; j++) {
        int col = j * 32 + lane;
        float y = (v[j] - m) * rstd * g[col] + b[col];
        out[(size_t)warp * 256 + col] = y;
        if (oh) {
            float t = P ? y + P[(size_t)warp * 256 + col] : y;
            __nv_bfloat16 hb = __float2bfloat16_rn(t);
            oh[(size_t)warp * 256 + col] = hb;
            ol[(size_t)warp * 256 + col] = __float2bfloat16_rn(t - __bfloat162float(hb));
        }
    }
}

// ---------------- text K/V projection (40 rows) ----------------
__global__ void kv_proj_kernel(const float* __restrict__ text, const float* __restrict__ ipw,
                               const float* __restrict__ ipb, float* __restrict__ kh,
                               float* __restrict__ vh) {
    int row = blockIdx.x;
    int c = threadIdx.x;
    const float* t = text + (size_t)row * 256;
    const float* wk = ipw + (size_t)(256 + c) * 256;
    const float* wv = ipw + (size_t)(512 + c) * 256;
    float sk = ipb[256 + c], sv = ipb[512 + c];
    for (int k = 0; k < 256; k++) {
        float tv = t[k];
        sk += tv * wk[k];
        sv += tv * wv[k];
    }
    kh[(size_t)row * 256 + c] = sk;
    vh[(size_t)row * 256 + c] = sv;
}

// ---------------- text cross-attention: thread per (token, head); split bf16 out ----------------
__global__ void cross_attn_kernel(const float* __restrict__ qh, const float* __restrict__ kh,
                                  const float* __restrict__ vh,
                                  __nv_bfloat16* __restrict__ ch, __nv_bfloat16* __restrict__ cl) {
    int idx = blockIdx.x * blockDim.x + threadIdx.x;
    if (idx >= NTOK * NH) return;
    int token = idx >> 3, h = idx & 7;
    int b = (token >= LQ_C) ? 1 : 0;
    const float4* q = (const float4*)(qh + (size_t)token * 256 + h * 32);
    float4 qv[8];
#pragma unroll
    for (int j = 0; j < 8; j++) qv[j] = q[j];

    float sc[LT];
    float mx = -1e30f;
    const float scale = 0.17677669529663687f;
#pragma unroll 4
    for (int k = 0; k < LT; k++) {
        const float4* kp = (const float4*)(kh + (size_t)(b * LT + k) * 256 + h * 32);
        float s = 0.f;
#pragma unroll
        for (int j = 0; j < 8; j++) {
            float4 kv = kp[j];
            s += qv[j].x * kv.x + qv[j].y * kv.y + qv[j].z * kv.z + qv[j].w * kv.w;
        }
        s *= scale;
        sc[k] = s;
        mx = fmaxf(mx, s);
    }
    float denom = 0.f;
#pragma unroll
    for (int k = 0; k < LT; k++) { sc[k] = expf(sc[k] - mx); denom += sc[k]; }
    float inv = 1.f / denom;
    float4 o[8];
#pragma unroll
    for (int j = 0; j < 8; j++) o[j] = make_float4(0.f, 0.f, 0.f, 0.f);
#pragma unroll 4
    for (int k = 0; k < LT; k++) {
        float pw = sc[k] * inv;
        const float4* vp = (const float4*)(vh + (size_t)(b * LT + k) * 256 + h * 32);
#pragma unroll
        for (int j = 0; j < 8; j++) {
            float4 vv = vp[j];
            o[j].x += pw * vv.x; o[j].y += pw * vv.y;
            o[j].z += pw * vv.z; o[j].w += pw * vv.w;
        }
    }
#pragma unroll
    for (int j = 0; j < 8; j++) {
        uint2 hh, ll;
        split4(o[j], hh, ll);
        *(uint2*)(ch + (size_t)token * 256 + h * 32 + j * 4) = hh;
        *(uint2*)(cl + (size_t)token * 256 + h * 32 + j * 4) = ll;
    }
}

// ---------------- launch ----------------
extern "C" void kernel_launch(void* const* d_in, const int* in_sizes, int n_in,
                              void* d_out, int out_size) {
    const float* src   = (const float*)d_in[0];
    const float* pos   = (const float*)d_in[1];
    const float* refp  = (const float*)d_in[2];
    const float* text  = (const float*)d_in[5];
    const float* so_w  = (const float*)d_in[7];
    const float* so_b  = (const float*)d_in[8];
    const float* aw_w  = (const float*)d_in[9];
    const float* aw_b  = (const float*)d_in[10];
    const float* vp_w  = (const float*)d_in[11];
    const float* vp_b  = (const float*)d_in[12];
    const float* op_w  = (const float*)d_in[13];
    const float* op_b  = (const float*)d_in[14];
    const float* ln1_g = (const float*)d_in[15];
    const float* ln1_b = (const float*)d_in[16];
    const float* ipw   = (const float*)d_in[17];
    const float* ipb   = (const float*)d_in[18];
    const float* mo_w  = (const float*)d_in[19];
    const float* mo_b  = (const float*)d_in[20];
    const float* ln3_g = (const float*)d_in[21];
    const float* ln3_b = (const float*)d_in[22];
    const float* l1_w  = (const float*)d_in[23];
    const float* l1_b  = (const float*)d_in[24];
    const float* l2_w  = (const float*)d_in[25];
    const float* l2_b  = (const float*)d_in[26];
    const float* ln2_g = (const float*)d_in[27];
    const float* ln2_b = (const float*)d_in[28];

    float* out_x = (float*)d_out;
    float* out_text = out_x + (size_t)NTOK * D_MODEL;

    float *q, *val, *offs, *aw, *kh, *vh;
    cudaGetSymbolAddress((void**)&q, g_q);
    cudaGetSymbolAddress((void**)&val, g_value);
    cudaGetSymbolAddress((void**)&offs, g_offs);
    cudaGetSymbolAddress((void**)&aw, g_aw);
    cudaGetSymbolAddress((void**)&kh, g_kh);
    cudaGetSymbolAddress((void**)&vh, g_vh);
    __nv_bfloat16 *Ah, *Al, *Bh, *Bl, *hh, *hl;
    cudaGetSymbolAddress((void**)&Ah, g_Ah);
    cudaGetSymbolAddress((void**)&Al, g_Al);
    cudaGetSymbolAddress((void**)&Bh, g_Bh);
    cudaGetSymbolAddress((void**)&Bl, g_Bl);
    cudaGetSymbolAddress((void**)&hh, g_hh);
    cudaGetSymbolAddress((void**)&hl, g_hl);
    __nv_bfloat16 *vpwh, *vpwl, *sowh, *sowl, *awwh, *awwl, *opwh, *opwl;
    __nv_bfloat16 *wqwh, *wqwl, *mowh, *mowl, *l1wh, *l1wl, *l2wh, *l2wl;
    cudaGetSymbolAddress((void**)&vpwh, g_vpw_h); cudaGetSymbolAddress((void**)&vpwl, g_vpw_l);
    cudaGetSymbolAddress((void**)&sowh, g_sow_h); cudaGetSymbolAddress((void**)&sowl, g_sow_l);
    cudaGetSymbolAddress((void**)&awwh, g_aww_h); cudaGetSymbolAddress((void**)&awwl, g_aww_l);
    cudaGetSymbolAddress((void**)&opwh, g_opw_h); cudaGetSymbolAddress((void**)&opwl, g_opw_l);
    cudaGetSymbolAddress((void**)&wqwh, g_wqw_h); cudaGetSymbolAddress((void**)&wqwl, g_wqw_l);
    cudaGetSymbolAddress((void**)&mowh, g_mow_h); cudaGetSymbolAddress((void**)&mowl, g_mow_l);
    cudaGetSymbolAddress((void**)&l1wh, g_l1w_h); cudaGetSymbolAddress((void**)&l1wl, g_l1w_l);
    cudaGetSymbolAddress((void**)&l2wh, g_l2w_h); cudaGetSymbolAddress((void**)&l2wl, g_l2w_l);

    cudaFuncSetAttribute(tc_gemm<0, false>, cudaFuncAttributeMaxDynamicSharedMemorySize, GEMM_SMEM);
    cudaFuncSetAttribute(tc_gemm<1, false>, cudaFuncAttributeMaxDynamicSharedMemorySize, GEMM_SMEM);
    cudaFuncSetAttribute(tc_gemm<2, true>, cudaFuncAttributeMaxDynamicSharedMemorySize, GEMM_SMEM);
    cudaFuncSetAttribute(tc_gemm<4, false>, cudaFuncAttributeMaxDynamicSharedMemorySize, GEMM_SMEM);

    const int M = NTOK;
    const int mTiles = cdiv(M, 64);
    dim3 g256(2, mTiles), g384(3, mTiles), g1024(8, mTiles);
    const int nAct4 = M * D_MODEL / 4;

    // ---- 1: all weight conversions batched ----
    WJobs J;
    J.j[0] = {vp_w, vpwh, vpwl, 65536 / 4};
    J.j[1] = {so_w, sowh, sowl, 65536 / 4};
    J.j[2] = {aw_w, awwh, awwl, 32768 / 4};
    J.j[3] = {op_w, opwh, opwl, 65536 / 4};
    J.j[4] = {ipw,  wqwh, wqwl, 65536 / 4};
    J.j[5] = {mo_w, mowh, mowl, 65536 / 4};
    J.j[6] = {l1_w, l1wh, l1wl, 262144 / 4};
    J.j[7] = {l2_w, l2wh, l2wl, 262144 / 4};
    int totW4 = (65536 * 5 + 32768 + 262144 * 2) / 4;
    wconv_kernel<<<cdiv(totW4, 256), 256>>>(J);
    // ---- 2: activation conversions ----
    actconv_kernel<<<cdiv(nAct4, 256), 256>>>(src, pos, Ah, Al, Bh, Bl, nAct4);
    // ---- 3: text K/V ----
    kv_proj_kernel<<<B_SZ * LT, 256>>>(text, ipw, ipb, kh, vh);
    // ---- 4: value = src @ vp^T + b ----
    tc_gemm<0, false><<<g256, 256, GEMM_SMEM>>>(Ah, Al, vpwh, vpwl, nullptr, nullptr, vp_b,
                                                nullptr, nullptr, val, nullptr, nullptr, nullptr,
                                                M, 256, 256);
    // ---- 5: FUSED offs + aw: blocks 0-1 -> offs; block 2 -> softmax16 -> aw ----
    tc_gemm<4, false><<<g384, 256, GEMM_SMEM>>>(Bh, Bl, sowh, sowl, awwh, awwl, so_b, aw_b,
                                                nullptr, offs, aw, nullptr, nullptr,
                                                M, 256, 256);
    // 6: deformable sampling -> ms (split bf16 into A planes)
    msdeform_kernel<<<cdiv(M * NH * 32, 256), 256>>>(val, offs, aw, refp, Ah, Al);
    // 7: preLN1 = ms @ op^T + b + src ; 8: LN1 -> out_x + (out+pos) split into B planes
    tc_gemm<1, false><<<g256, 256, GEMM_SMEM>>>(Ah, Al, opwh, opwl, nullptr, nullptr, op_b,
                                                nullptr, src, offs, nullptr, nullptr, nullptr,
                                                M, 256, 256);
    ln_kernel<<<cdiv(M * 32, 256), 256>>>(offs, ln1_g, ln1_b, out_x, pos, Bh, Bl, M);
    // 9: qh = (x+pos) @ wq^T + bq
    tc_gemm<0, false><<<g256, 256, GEMM_SMEM>>>(Bh, Bl, wqwh, wqwl, nullptr, nullptr, ipb,
                                                nullptr, nullptr, q, nullptr, nullptr, nullptr,
                                                M, 256, 256);
    // 10: cross attention -> ctx (split bf16 into A planes)
    cross_attn_kernel<<<cdiv(M * NH, 256), 256>>>(q, kh, vh, Ah, Al);
    // 11: preLN3 = ctx @ mo^T + b + x ; 12: LN3 -> out_x + split into B planes
    tc_gemm<1, false><<<g256, 256, GEMM_SMEM>>>(Ah, Al, mowh, mowl, nullptr, nullptr, mo_b,
                                                nullptr, out_x, val, nullptr, nullptr, nullptr,
                                                M, 256, 256);
    ln_kernel<<<cdiv(M * 32, 256), 256>>>(val, ln3_g, ln3_b, out_x, nullptr, Bh, Bl, M);
    // 13-15: FFN + LN2
    tc_gemm<2, true><<<g1024, 256, GEMM_SMEM>>>(Bh, Bl, l1wh, l1wl, nullptr, nullptr, l1_b,
                                                nullptr, nullptr, nullptr, nullptr, hh, hl,
                                                M, DFF, 256);
    tc_gemm<1, false><<<g256, 256, GEMM_SMEM>>>(hh, hl, l2wh, l2wl, nullptr, nullptr, l2_b,
                                                nullptr, out_x, val, nullptr, nullptr, nullptr,
                                                M, 256, DFF);
    ln_kernel<<<cdiv(M * 32, 256), 256>>>(val, ln2_g, ln2_b, out_x, nullptr, nullptr, nullptr, M);
    // 16: pass-through text_memory
    cudaMemcpyAsync(out_text, text, (size_t)B_SZ * LT * D_MODEL * sizeof(float),
                    cudaMemcpyDeviceToDevice, 0);
}

// round 10
// speedup vs baseline: 1.0584x; 1.0045x over previous
#include <cuda_runtime.h>
#include <cuda_bf16.h>
#include <cuda_fp16.h>
#include <cstdint>
#include <math.h>

// ---------------- problem constants ----------------
#define D_MODEL 256
#define NH 8
#define HD 32
#define NL 4
#define NP 4
#define DFF 1024
#define B_SZ 2
#define LT 20
#define LQ_C 20197
#define NTOK (B_SZ * LQ_C)   // 40394

__device__ __constant__ int c_H[NL]  = {100, 50, 25, 13};
__device__ __constant__ int c_W[NL]  = {152, 76, 38, 19};
__device__ __constant__ int c_St[NL] = {0, 15200, 19000, 19950};

// ---------------- scratch (static device globals; no allocation) ----------------
__device__ float g_q[NTOK * D_MODEL];
__device__ float g_value[NTOK * D_MODEL];   // holds __half value after proj
__device__ float g_offs[NTOK * D_MODEL];
__device__ float g_aw[NTOK * 128];
__device__ float g_kh[B_SZ * LT * D_MODEL];
__device__ float g_vh[B_SZ * LT * D_MODEL];
__device__ __nv_bfloat16 g_Ah[NTOK * D_MODEL], g_Al[NTOK * D_MODEL];
__device__ __nv_bfloat16 g_Bh[NTOK * D_MODEL], g_Bl[NTOK * D_MODEL];
__device__ __nv_bfloat16 g_hh[NTOK * DFF], g_hl[NTOK * DFF];
__device__ __nv_bfloat16 g_vpw_h[65536], g_vpw_l[65536];
__device__ __nv_bfloat16 g_sow_h[65536], g_sow_l[65536];
__device__ __nv_bfloat16 g_aww_h[32768], g_aww_l[32768];
__device__ __nv_bfloat16 g_opw_h[65536], g_opw_l[65536];
__device__ __nv_bfloat16 g_wqw_h[65536], g_wqw_l[65536];
__device__ __nv_bfloat16 g_mow_h[65536], g_mow_l[65536];
__device__ __nv_bfloat16 g_l1w_h[262144], g_l1w_l[262144];
__device__ __nv_bfloat16 g_l2w_h[262144], g_l2w_l[262144];

static inline int cdiv(int a, int b) { return (a + b - 1) / b; }

__device__ __forceinline__ uint32_t smem_u32(const void* p) {
    uint32_t a;
    asm("{ .reg .u64 t; cvta.to.shared.u64 t, %1; cvt.u32.u64 %0, t; }" : "=r"(a) : "l"(p));
    return a;
}
__device__ __forceinline__ void ldm_x4(uint32_t addr, uint32_t& r0, uint32_t& r1,
                                       uint32_t& r2, uint32_t& r3) {
    asm volatile("ldmatrix.sync.aligned.m8n8.x4.shared.b16 {%0,%1,%2,%3}, [%4];"
                 : "=r"(r0), "=r"(r1), "=r"(r2), "=r"(r3) : "r"(addr));
}
__device__ __forceinline__ void mma_bf16(float* c, const uint32_t* a, const uint32_t* b) {
    asm volatile(
        "mma.sync.aligned.m16n8k16.row.col.f32.bf16.bf16.f32 "
        "{%0,%1,%2,%3}, {%4,%5,%6,%7}, {%8,%9}, {%0,%1,%2,%3};"
        : "+f"(c[0]), "+f"(c[1]), "+f"(c[2]), "+f"(c[3])
        : "r"(a[0]), "r"(a[1]), "r"(a[2]), "r"(a[3]), "r"(b[0]), "r"(b[1]));
}
__device__ __forceinline__ void split4(float4 v, uint2& h, uint2& l) {
    union U { __nv_bfloat16 b[4]; uint2 u; } H, L;
    H.b[0] = __float2bfloat16_rn(v.x);
    H.b[1] = __float2bfloat16_rn(v.y);
    H.b[2] = __float2bfloat16_rn(v.z);
    H.b[3] = __float2bfloat16_rn(v.w);
    L.b[0] = __float2bfloat16_rn(v.x - __bfloat162float(H.b[0]));
    L.b[1] = __float2bfloat16_rn(v.y - __bfloat162float(H.b[1]));
    L.b[2] = __float2bfloat16_rn(v.z - __bfloat162float(H.b[2]));
    L.b[3] = __float2bfloat16_rn(v.w - __bfloat162float(H.b[3]));
    h = H.u; l = L.u;
}
__device__ __forceinline__ uint32_t split2(float v0, float v1, uint32_t& lo) {
    union U { __nv_bfloat16 b[2]; uint32_t u; } H, L;
    H.b[0] = __float2bfloat16_rn(v0);
    H.b[1] = __float2bfloat16_rn(v1);
    L.b[0] = __float2bfloat16_rn(v0 - __bfloat162float(H.b[0]));
    L.b[1] = __float2bfloat16_rn(v1 - __bfloat162float(H.b[1]));
    lo = L.u;
    return H.u;
}
__device__ __forceinline__ void cpa16(uint32_t dst, const void* src) {
    asm volatile("cp.async.cg.shared.global [%0], [%1], 16;" :: "r"(dst), "l"(src));
}
__device__ __forceinline__ void cpa16z(uint32_t dst, const void* src, bool v) {
    int sz = v ? 16 : 0;
    asm volatile("cp.async.cg.shared.global [%0], [%1], 16, %2;"
                 :: "r"(dst), "l"(src), "r"(sz));
}

// =====================================================================
// tc_gemm: bf16-split GEMM (3-pass), CTA 64x128, KC=32, 3-stage, 1 sync.
//   MODE 0: +bias   2: +bias,relu   4: fused dual (cols<256->C; block2->softmax16->C2)
//   OSPLIT: write split bf16 planes. OHALF: write __half (C cast).
// =====================================================================
#define KC 32
#define A_TILE_B 8192
#define B_TILE_B 16384
#define STAGE_B (A_TILE_B + B_TILE_B)   // 24 KB
#define NSTAGE 3
#define GEMM_SMEM (NSTAGE * STAGE_B)    // 72 KB

template <int MODE, bool OSPLIT, bool OHALF>
__global__ void __launch_bounds__(256, 2)
tc_gemm(const __nv_bfloat16* __restrict__ Ah, const __nv_bfloat16* __restrict__ Al,
        const __nv_bfloat16* __restrict__ Wh, const __nv_bfloat16* __restrict__ Wl,
        const __nv_bfloat16* __restrict__ W2h, const __nv_bfloat16* __restrict__ W2l,
        const float* __restrict__ bias, const float* __restrict__ bias2,
        float* __restrict__ C, float* __restrict__ C2,
        __nv_bfloat16* __restrict__ Ch, __nv_bfloat16* __restrict__ Cl,
        int M, int N, int K) {
    extern __shared__ char smem[];
    const uint32_t sbase = smem_u32(smem);
    const int tid = threadIdx.x;
    const int wid = tid >> 5;
    const int lane = tid & 31;
    const int rowBase = blockIdx.y * 64;
    const int colBase = blockIdx.x * 128;
    const int warpM = wid >> 2;
    const int warpN = wid & 3;
    const bool isAw = (MODE == 4) && (blockIdx.x == 2);

    const __nv_bfloat16* bWh = isAw ? W2h : (Wh + (size_t)colBase * K);
    const __nv_bfloat16* bWl = isAw ? W2l : (Wl + (size_t)colBase * K);

    float acc[2][4][4];
#pragma unroll
    for (int mi = 0; mi < 2; mi++)
#pragma unroll
        for (int ni = 0; ni < 4; ni++)
#pragma unroll
            for (int j = 0; j < 4; j++) acc[mi][ni][j] = 0.f;

    const uint32_t swX = (uint32_t)((lane & 7) << 4);
    const int aKB0 = (lane >> 4) * 16;
    uint32_t aRowOff[2];
#pragma unroll
    for (int mi = 0; mi < 2; mi++)
        aRowOff[mi] = (uint32_t)((warpM * 32 + mi * 16 + (lane & 15)) * 128);
    const int grp = lane >> 3;
    const int bKB0 = (grp & 1) * 16;
    uint32_t bRowOff[2];
#pragma unroll
    for (int np = 0; np < 2; np++)
        bRowOff[np] = (uint32_t)((warpN * 32 + np * 16 + ((grp >> 1) << 3) + (lane & 7)) * 128);

    const int nChunks = K / KC;
    const int cA_r = tid >> 2, cA_c = tid & 3;
    const uint32_t cA_offH = (uint32_t)(cA_r * 128 + ((cA_c * 16) ^ ((cA_r & 7) << 4)));
    const uint32_t cA_offL = (uint32_t)(cA_r * 128 + (((cA_c + 4) * 16) ^ ((cA_r & 7) << 4)));
    const int gA = rowBase + cA_r;
    const bool vA = gA < M;
    const int cAr = vA ? gA : (M - 1);

    auto copy_chunk = [&](int kt, uint32_t stg) {
        const int k0 = kt * KC;
#pragma unroll
        for (int i = 0; i < 2; i++) {
            int idx = tid + i * 256;
            int r = idx >> 2, c = idx & 3;
            uint32_t oh = (uint32_t)(r * 128 + ((c * 16) ^ ((r & 7) << 4)));
            uint32_t ol = (uint32_t)(r * 128 + (((c + 4) * 16) ^ ((r & 7) << 4)));
            const size_t gs = (size_t)r * K + k0 + c * 8;
            cpa16(stg + A_TILE_B + oh, bWh + gs);
            cpa16(stg + A_TILE_B + ol, bWl + gs);
        }
        {
            const size_t gs = (size_t)cAr * K + k0 + cA_c * 8;
            cpa16z(stg + cA_offH, Ah + gs, vA);
            cpa16z(stg + cA_offL, Al + gs, vA);
        }
    };

    copy_chunk(0, sbase);
    asm volatile("cp.async.commit_group;");
    if (nChunks > 1) {
        copy_chunk(1, sbase + STAGE_B);
        asm volatile("cp.async.commit_group;");
    }
    int stgIdx = 0;
    for (int kt = 0; kt < nChunks; kt++) {
        if (kt + 1 < nChunks) asm volatile("cp.async.wait_group 1;");
        else asm volatile("cp.async.wait_group 0;");
        __syncthreads();
        if (kt + 2 < nChunks) {
            int ws = stgIdx + 2;
            if (ws >= NSTAGE) ws -= NSTAGE;
            copy_chunk(kt + 2, sbase + (uint32_t)(ws * STAGE_B));
            asm volatile("cp.async.commit_group;");
        }
        const uint32_t AS = sbase + (uint32_t)(stgIdx * STAGE_B);
        const uint32_t BS = AS + A_TILE_B;
#pragma unroll
        for (int kst = 0; kst < 2; kst++) {
            uint32_t ah[2][4], al[2][4];
#pragma unroll
            for (int mi = 0; mi < 2; mi++) {
                uint32_t kb = (uint32_t)(aKB0 + kst * 32);
                ldm_x4(AS + aRowOff[mi] + (kb ^ swX),
                       ah[mi][0], ah[mi][1], ah[mi][2], ah[mi][3]);
                ldm_x4(AS + aRowOff[mi] + ((kb + 64) ^ swX),
                       al[mi][0], al[mi][1], al[mi][2], al[mi][3]);
            }
            uint32_t bh[4][2], bl[4][2];
#pragma unroll
            for (int np = 0; np < 2; np++) {
                uint32_t kb = (uint32_t)(bKB0 + kst * 32);
                uint32_t r0, r1, r2, r3;
                ldm_x4(BS + bRowOff[np] + (kb ^ swX), r0, r1, r2, r3);
                bh[np * 2][0] = r0; bh[np * 2][1] = r1;
                bh[np * 2 + 1][0] = r2; bh[np * 2 + 1][1] = r3;
                ldm_x4(BS + bRowOff[np] + ((kb + 64) ^ swX), r0, r1, r2, r3);
                bl[np * 2][0] = r0; bl[np * 2][1] = r1;
                bl[np * 2 + 1][0] = r2; bl[np * 2 + 1][1] = r3;
            }
#pragma unroll
            for (int mi = 0; mi < 2; mi++)
#pragma unroll
                for (int ni = 0; ni < 4; ni++) mma_bf16(acc[mi][ni], ah[mi], bh[ni]);
#pragma unroll
            for (int mi = 0; mi < 2; mi++)
#pragma unroll
                for (int ni = 0; ni < 4; ni++) mma_bf16(acc[mi][ni], ah[mi], bl[ni]);
#pragma unroll
            for (int mi = 0; mi < 2; mi++)
#pragma unroll
                for (int ni = 0; ni < 4; ni++) mma_bf16(acc[mi][ni], al[mi], bh[ni]);
        }
        stgIdx++;
        if (stgIdx == NSTAGE) stgIdx = 0;
    }

    const int qrow = lane >> 2;
    const int qcol = (lane & 3) * 2;
#pragma unroll
    for (int ni = 0; ni < 4; ni++) {
        int cl_ = warpN * 32 + ni * 8 + qcol;
        int bcol = isAw ? cl_ : (colBase + cl_);
        const float* bp = isAw ? bias2 : bias;
        float b0 = __ldg(bp + bcol), b1 = __ldg(bp + bcol + 1);
#pragma unroll
        for (int mi = 0; mi < 2; mi++) {
            acc[mi][ni][0] += b0; acc[mi][ni][1] += b1;
            acc[mi][ni][2] += b0; acc[mi][ni][3] += b1;
        }
    }
    if (isAw) {
#pragma unroll
        for (int mi = 0; mi < 2; mi++)
#pragma unroll
            for (int g = 0; g < 2; g++)
#pragma unroll
                for (int rh = 0; rh < 2; rh++) {
                    float v0 = acc[mi][2 * g][rh * 2], v1 = acc[mi][2 * g][rh * 2 + 1];
                    float v2 = acc[mi][2 * g + 1][rh * 2], v3 = acc[mi][2 * g + 1][rh * 2 + 1];
                    float mx = fmaxf(fmaxf(v0, v1), fmaxf(v2, v3));
                    mx = fmaxf(mx, __shfl_xor_sync(0xffffffffu, mx, 1));
                    mx = fmaxf(mx, __shfl_xor_sync(0xffffffffu, mx, 2));
                    v0 = expf(v0 - mx); v1 = expf(v1 - mx);
                    v2 = expf(v2 - mx); v3 = expf(v3 - mx);
                    float s = v0 + v1 + v2 + v3;
                    s += __shfl_xor_sync(0xffffffffu, s, 1);
                    s += __shfl_xor_sync(0xffffffffu, s, 2);
                    float inv = 1.f / s;
                    acc[mi][2 * g][rh * 2] = v0 * inv; acc[mi][2 * g][rh * 2 + 1] = v1 * inv;
                    acc[mi][2 * g + 1][rh * 2] = v2 * inv; acc[mi][2 * g + 1][rh * 2 + 1] = v3 * inv;
                }
    }
#pragma unroll
    for (int mi = 0; mi < 2; mi++)
#pragma unroll
        for (int rh = 0; rh < 2; rh++) {
            int row = rowBase + warpM * 32 + mi * 16 + qrow + rh * 8;
            if (row >= M) continue;
#pragma unroll
            for (int ni = 0; ni < 4; ni++) {
                int cl_ = warpN * 32 + ni * 8 + qcol;
                float v0 = acc[mi][ni][rh * 2], v1 = acc[mi][ni][rh * 2 + 1];
                if (MODE == 2) { v0 = fmaxf(v0, 0.f); v1 = fmaxf(v1, 0.f); }
                if (OSPLIT) {
                    uint32_t lo;
                    uint32_t hi = split2(v0, v1, lo);
                    *(uint32_t*)(Ch + (size_t)row * N + colBase + cl_) = hi;
                    *(uint32_t*)(Cl + (size_t)row * N + colBase + cl_) = lo;
                } else if (OHALF) {
                    *(__half2*)((__half*)C + (size_t)row * N + colBase + cl_) =
                        __floats2half2_rn(v0, v1);
                } else if (isAw) {
                    *(float2*)(C2 + (size_t)row * 128 + cl_) = make_float2(v0, v1);
                } else {
                    *(float2*)(C + (size_t)row * N + colBase + cl_) = make_float2(v0, v1);
                }
            }
        }
}

// =====================================================================
// tc_gemm_ln: GEMM + residual + fused LayerNorm. CTA 64x256 (full rows),
//   8 warps (warp tile 32x64), KC=32, 2 stages (40KB) + 2 syncs/chunk.
//   out = LN(A@W^T + bias + R); writes fp32 out; optionally split bf16
//   planes of (out [+ P]).
// =====================================================================
#define LA_TILE_B 8192                  // 64 rows x 128B
#define LB_TILE_B 32768                 // 256 rows x 128B
#define LSTAGE_B (LA_TILE_B + LB_TILE_B)
#define GEMM_LN_SMEM (2 * LSTAGE_B)     // 80 KB

template <bool WANTSPLIT, bool HASP>
__global__ void __launch_bounds__(256, 2)
tc_gemm_ln(const __nv_bfloat16* __restrict__ Ah, const __nv_bfloat16* __restrict__ Al,
           const __nv_bfloat16* __restrict__ Wh, const __nv_bfloat16* __restrict__ Wl,
           const float* __restrict__ bias, const float* __restrict__ R,
           const float* __restrict__ lng, const float* __restrict__ lnb,
           const float* __restrict__ P, float* __restrict__ Cout,
           __nv_bfloat16* __restrict__ Sh, __nv_bfloat16* __restrict__ Sl,
           int M, int K) {
    extern __shared__ char smem[];
    const uint32_t sbase = smem_u32(smem);
    const int tid = threadIdx.x;
    const int wid = tid >> 5;
    const int lane = tid & 31;
    const int rowBase = blockIdx.x * 64;
    const int warpM = wid >> 2;       // 0..1
    const int warpN = wid & 3;        // 0..3 -> 64-col span

    float acc[2][8][4];
#pragma unroll
    for (int mi = 0; mi < 2; mi++)
#pragma unroll
        for (int ni = 0; ni < 8; ni++)
#pragma unroll
            for (int j = 0; j < 4; j++) acc[mi][ni][j] = 0.f;

    const uint32_t swX = (uint32_t)((lane & 7) << 4);
    const int aKB0 = (lane >> 4) * 16;
    uint32_t aRowOff[2];
#pragma unroll
    for (int mi = 0; mi < 2; mi++)
        aRowOff[mi] = (uint32_t)((warpM * 32 + mi * 16 + (lane & 15)) * 128);
    const int grp = lane >> 3;
    const int bKB0 = (grp & 1) * 16;
    uint32_t bRowOff[4];
#pragma unroll
    for (int np = 0; np < 4; np++)
        bRowOff[np] = (uint32_t)((warpN * 64 + np * 16 + ((grp >> 1) << 3) + (lane & 7)) * 128);

    const int nChunks = K / KC;
    const int cA_r = tid >> 2, cA_c = tid & 3;
    const uint32_t cA_offH = (uint32_t)(cA_r * 128 + ((cA_c * 16) ^ ((cA_r & 7) << 4)));
    const uint32_t cA_offL = (uint32_t)(cA_r * 128 + (((cA_c + 4) * 16) ^ ((cA_r & 7) << 4)));
    const int gA = rowBase + cA_r;
    const bool vA = gA < M;
    const int cAr = vA ? gA : (M - 1);

    auto copy_chunk = [&](int kt, uint32_t stg) {
        const int k0 = kt * KC;
#pragma unroll
        for (int i = 0; i < 4; i++) {
            int idx = tid + i * 256;
            int r = idx >> 2, c = idx & 3;
            uint32_t oh = (uint32_t)(r * 128 + ((c * 16) ^ ((r & 7) << 4)));
            uint32_t ol = (uint32_t)(r * 128 + (((c + 4) * 16) ^ ((r & 7) << 4)));
            const size_t gs = (size_t)r * K + k0 + c * 8;
            cpa16(stg + LA_TILE_B + oh, Wh + gs);
            cpa16(stg + LA_TILE_B + ol, Wl + gs);
        }
        {
            const size_t gs = (size_t)cAr * K + k0 + cA_c * 8;
            cpa16z(stg + cA_offH, Ah + gs, vA);
            cpa16z(stg + cA_offL, Al + gs, vA);
        }
    };

    copy_chunk(0, sbase);
    asm volatile("cp.async.commit_group;");
    for (int kt = 0; kt < nChunks; kt++) {
        if (kt + 1 < nChunks) {
            copy_chunk(kt + 1, sbase + (uint32_t)(((kt + 1) & 1) * LSTAGE_B));
            asm volatile("cp.async.commit_group;");
            asm volatile("cp.async.wait_group 1;");
        } else {
            asm volatile("cp.async.wait_group 0;");
        }
        __syncthreads();
        const uint32_t AS = sbase + (uint32_t)((kt & 1) * LSTAGE_B);
        const uint32_t BS = AS + LA_TILE_B;
#pragma unroll
        for (int kst = 0; kst < 2; kst++) {
            uint32_t ah[2][4], al[2][4];
#pragma unroll
            for (int mi = 0; mi < 2; mi++) {
                uint32_t kb = (uint32_t)(aKB0 + kst * 32);
                ldm_x4(AS + aRowOff[mi] + (kb ^ swX),
                       ah[mi][0], ah[mi][1], ah[mi][2], ah[mi][3]);
                ldm_x4(AS + aRowOff[mi] + ((kb + 64) ^ swX),
                       al[mi][0], al[mi][1], al[mi][2], al[mi][3]);
            }
#pragma unroll
            for (int np = 0; np < 4; np++) {
                uint32_t kb = (uint32_t)(bKB0 + kst * 32);
                uint32_t h0, h1, h2, h3, l0, l1, l2, l3;
                ldm_x4(BS + bRowOff[np] + (kb ^ swX), h0, h1, h2, h3);
                ldm_x4(BS + bRowOff[np] + ((kb + 64) ^ swX), l0, l1, l2, l3);
                uint32_t bh0[2] = {h0, h1}, bh1[2] = {h2, h3};
                uint32_t bl0[2] = {l0, l1}, bl1[2] = {l2, l3};
#pragma unroll
                for (int mi = 0; mi < 2; mi++) {
                    mma_bf16(acc[mi][2 * np], ah[mi], bh0);
                    mma_bf16(acc[mi][2 * np + 1], ah[mi], bh1);
                    mma_bf16(acc[mi][2 * np], ah[mi], bl0);
                    mma_bf16(acc[mi][2 * np + 1], ah[mi], bl1);
                    mma_bf16(acc[mi][2 * np], al[mi], bh0);
                    mma_bf16(acc[mi][2 * np + 1], al[mi], bh1);
                }
            }
        }
        if (kt + 1 < nChunks) __syncthreads();
    }

    // ---- fused epilogue: bias + residual + LayerNorm ----
    __syncthreads();                       // stage smem free for reduction
    float* red = (float*)smem;             // [64 rows][4 warpN][2]
    const int qrow = lane >> 2;
    const int qcol = (lane & 3) * 2;

#pragma unroll
    for (int mi = 0; mi < 2; mi++)
#pragma unroll
        for (int rh = 0; rh < 2; rh++) {
            int rloc = warpM * 32 + mi * 16 + rh * 8 + qrow;
            int row = rowBase + rloc;
            bool ok = row < M;
            float s = 0.f, qsum = 0.f;
#pragma unroll
            for (int ni = 0; ni < 8; ni++) {
                int col = warpN * 64 + ni * 8 + qcol;
                float b0 = __ldg(bias + col), b1 = __ldg(bias + col + 1);
                float v0 = acc[mi][ni][rh * 2] + b0;
                float v1 = acc[mi][ni][rh * 2 + 1] + b1;
                if (ok) {
                    const float2 rr = *(const float2*)(R + (size_t)row * 256 + col);
                    v0 += rr.x; v1 += rr.y;
                }
                acc[mi][ni][rh * 2] = v0;
                acc[mi][ni][rh * 2 + 1] = v1;
                s += v0 + v1;
                qsum += v0 * v0 + v1 * v1;
            }
            s += __shfl_xor_sync(0xffffffffu, s, 1);
            s += __shfl_xor_sync(0xffffffffu, s, 2);
            qsum += __shfl_xor_sync(0xffffffffu, qsum, 1);
            qsum += __shfl_xor_sync(0xffffffffu, qsum, 2);
            if ((lane & 3) == 0) {
                red[(rloc << 3) + (warpN << 1)] = s;
                red[(rloc << 3) + (warpN << 1) + 1] = qsum;
            }
        }
    __syncthreads();
#pragma unroll
    for (int mi = 0; mi < 2; mi++)
#pragma unroll
        for (int rh = 0; rh < 2; rh++) {
            int rloc = warpM * 32 + mi * 16 + rh * 8 + qrow;
            int row = rowBase + rloc;
            if (row >= M) continue;
            float s = red[(rloc << 3)] + red[(rloc << 3) + 2] +
                      red[(rloc << 3) + 4] + red[(rloc << 3) + 6];
            float qsum = red[(rloc << 3) + 1] + red[(rloc << 3) + 3] +
                         red[(rloc << 3) + 5] + red[(rloc << 3) + 7];
            float mean = s * (1.f / 256.f);
            float var = qsum * (1.f / 256.f) - mean * mean;
            float rstd = rsqrtf(var + 1e-5f);
#pragma unroll
            for (int ni = 0; ni < 8; ni++) {
                int col = warpN * 64 + ni * 8 + qcol;
                float g0 = __ldg(lng + col), g1 = __ldg(lng + col + 1);
                float c0 = __ldg(lnb + col), c1 = __ldg(lnb + col + 1);
                float y0 = (acc[mi][ni][rh * 2] - mean) * rstd * g0 + c0;
                float y1 = (acc[mi][ni][rh * 2 + 1] - mean) * rstd * g1 + c1;
                *(float2*)(Cout + (size_t)row * 256 + col) = make_float2(y0, y1);
                if (WANTSPLIT) {
                    float t0 = y0, t1 = y1;
                    if (HASP) {
                        const float2 pp = *(const float2*)(P + (size_t)row * 256 + col);
                        t0 += pp.x; t1 += pp.y;
                    }
                    uint32_t lo;
                    uint32_t hi = split2(t0, t1, lo);
                    *(uint32_t*)(Sh + (size_t)row * 256 + col) = hi;
                    *(uint32_t*)(Sl + (size_t)row * 256 + col) = lo;
                }
            }
        }
}

// ---------------- batched weight conversion ----------------
struct WJob { const float* s; __nv_bfloat16* h; __nv_bfloat16* l; int n4; };
struct WJobs { WJob j[8]; };
__global__ void wconv_kernel(WJobs J) {
    int i = blockIdx.x * blockDim.x + threadIdx.x;
#pragma unroll
    for (int k = 0; k < 8; k++) {
        int n = J.j[k].n4;
        if (i < n) {
            float4 v = ((const float4*)J.j[k].s)[i];
            uint2 h, l;
            split4(v, h, l);
            ((uint2*)J.j[k].h)[i] = h;
            ((uint2*)J.j[k].l)[i] = l;
            return;
        }
        i -= n;
    }
}
__global__ void actconv_kernel(const float* __restrict__ src, const float* __restrict__ pos,
                               __nv_bfloat16* __restrict__ Ah, __nv_bfloat16* __restrict__ Al,
                               __nv_bfloat16* __restrict__ Bh, __nv_bfloat16* __restrict__ Bl,
                               int n4) {
    int i = blockIdx.x * blockDim.x + threadIdx.x;
    if (i >= n4) return;
    float4 s = ((const float4*)src)[i];
    float4 p = ((const float4*)pos)[i];
    uint2 h, l;
    split4(s, h, l);
    ((uint2*)Ah)[i] = h;
    ((uint2*)Al)[i] = l;
    s.x += p.x; s.y += p.y; s.z += p.z; s.w += p.w;
    split4(s, h, l);
    ((uint2*)Bh)[i] = h;
    ((uint2*)Bl)[i] = l;
}

// ---------------- multi-scale deformable sampling (fp16 value; split bf16 out) ----
__global__ void msdeform_kernel(const __half* __restrict__ value, const float* __restrict__ offs,
                                const float* __restrict__ aw, const float* __restrict__ ref,
                                __nv_bfloat16* __restrict__ outh, __nv_bfloat16* __restrict__ outl) {
    int gw = (blockIdx.x * blockDim.x + threadIdx.x) >> 5;
    int lane = threadIdx.x & 31;
    if (gw >= NTOK * NH) return;
    int token = gw >> 3, h = gw & 7;
    int b = (token >= LQ_C) ? 1 : 0;

    int p = lane & 15;
    int l = p >> 2;
    int Wl = c_W[l], Hl = c_H[l];
    float Wf = (float)Wl, Hf = (float)Hl;
    float rx = __ldg(ref + (size_t)token * 8 + l * 2);
    float ry = __ldg(ref + (size_t)token * 8 + l * 2 + 1);
    float ox = __ldg(offs + (size_t)token * 256 + h * 32 + p * 2);
    float oy = __ldg(offs + (size_t)token * 256 + h * 32 + p * 2 + 1);
    float wA = __ldg(aw + (size_t)token * 128 + h * 16 + p);

    float X = (rx + ox / Wf) * Wf - 0.5f;
    float Y = (ry + oy / Hf) * Hf - 0.5f;
    float x0f = floorf(X), y0f = floorf(Y);
    float lx = X - x0f, ly = Y - y0f;
    int x0 = (int)x0f, y0 = (int)y0f;
    int x1 = x0 + 1, y1 = y0 + 1;
    bool vx0 = (x0 >= 0) & (x0 < Wl), vx1 = (x1 >= 0) & (x1 < Wl);
    bool vy0 = (y0 >= 0) & (y0 < Hl), vy1 = (y1 >= 0) & (y1 < Hl);
    int cx0 = min(max(x0, 0), Wl - 1), cx1 = min(max(x1, 0), Wl - 1);
    int cy0 = min(max(y0, 0), Hl - 1), cy1 = min(max(y1, 0), Hl - 1);
    int base = b * LQ_C + c_St[l];
    int r00 = base + cy0 * Wl + cx0;
    int r01 = base + cy0 * Wl + cx1;
    int r10 = base + cy1 * Wl + cx0;
    int r11 = base + cy1 * Wl + cx1;
    float w00 = wA * (1.f - lx) * (1.f - ly) * (float)(vx0 & vy0);
    float w01 = wA * lx * (1.f - ly) * (float)(vx1 & vy0);
    float w10 = wA * (1.f - lx) * ly * (float)(vx0 & vy1);
    float w11 = wA * lx * ly * (float)(vx1 & vy1);

    const __half* vb = value + h * 32 + lane;
    float acc = 0.f;
#pragma unroll
    for (int pp = 0; pp < 16; pp++) {
        int s00 = __shfl_sync(0xffffffffu, r00, pp);
        int s01 = __shfl_sync(0xffffffffu, r01, pp);
        int s10 = __shfl_sync(0xffffffffu, r10, pp);
        int s11 = __shfl_sync(0xffffffffu, r11, pp);
        float u00 = __shfl_sync(0xffffffffu, w00, pp);
        float u01 = __shfl_sync(0xffffffffu, w01, pp);
        float u10 = __shfl_sync(0xffffffffu, w10, pp);
        float u11 = __shfl_sync(0xffffffffu, w11, pp);
        acc += u00 * __half2float(__ldg(vb + (size_t)s00 * 256));
        acc += u01 * __half2float(__ldg(vb + (size_t)s01 * 256));
        acc += u10 * __half2float(__ldg(vb + (size_t)s10 * 256));
        acc += u11 * __half2float(__ldg(vb + (size_t)s11 * 256));
    }
    __nv_bfloat16 hb = __float2bfloat16_rn(acc);
    __nv_bfloat16 lb = __float2bfloat16_rn(acc - __bfloat162float(hb));
    outh[(size_t)token * 256 + h * 32 + lane] = hb;
    outl[(size_t)token * 256 + h * 32 + lane] = lb;
}

// ---------------- text K/V projection ----------------
__global__ void kv_proj_kernel(const float* __restrict__ text, const float* __restrict__ ipw,
                               const float* __restrict__ ipb, float* __restrict__ kh,
                               float* __restrict__ vh) {
    int row = blockIdx.x;
    int c = threadIdx.x;
    const float* t = text + (size_t)row * 256;
    const float* wk = ipw + (size_t)(256 + c) * 256;
    const float* wv = ipw + (size_t)(512 + c) * 256;
    float sk = ipb[256 + c], sv = ipb[512 + c];
    for (int k = 0; k < 256; k++) {
        float tv = t[k];
        sk += tv * wk[k];
        sv += tv * wv[k];
    }
    kh[(size_t)row * 256 + c] = sk;
    vh[(size_t)row * 256 + c] = sv;
}

// ---------------- text cross-attention ----------------
__global__ void cross_attn_kernel(const float* __restrict__ qh, const float* __restrict__ kh,
                                  const float* __restrict__ vh,
                                  __nv_bfloat16* __restrict__ ch, __nv_bfloat16* __restrict__ cl) {
    int idx = blockIdx.x * blockDim.x + threadIdx.x;
    if (idx >= NTOK * NH) return;
    int token = idx >> 3, h = idx & 7;
    int b = (token >= LQ_C) ? 1 : 0;
    const float4* q = (const float4*)(qh + (size_t)token * 256 + h * 32);
    float4 qv[8];
#pragma unroll
    for (int j = 0; j < 8; j++) qv[j] = q[j];

    float sc[LT];
    float mx = -1e30f;
    const float scale = 0.17677669529663687f;
#pragma unroll 4
    for (int k = 0; k < LT; k++) {
        const float4* kp = (const float4*)(kh + (size_t)(b * LT + k) * 256 + h * 32);
        float s = 0.f;
#pragma unroll
        for (int j = 0; j < 8; j++) {
            float4 kv = kp[j];
            s += qv[j].x * kv.x + qv[j].y * kv.y + qv[j].z * kv.z + qv[j].w * kv.w;
        }
        s *= scale;
        sc[k] = s;
        mx = fmaxf(mx, s);
    }
    float denom = 0.f;
#pragma unroll
    for (int k = 0; k < LT; k++) { sc[k] = expf(sc[k] - mx); denom += sc[k]; }
    float inv = 1.f / denom;
    float4 o[8];
#pragma unroll
    for (int j = 0; j < 8; j++) o[j] = make_float4(0.f, 0.f, 0.f, 0.f);
#pragma unroll 4
    for (int k = 0; k < LT; k++) {
        float pw = sc[k] * inv;
        const float4* vp = (const float4*)(vh + (size_t)(b * LT + k) * 256 + h * 32);
#pragma unroll
        for (int j = 0; j < 8; j++) {
            float4 vv = vp[j];
            o[j].x += pw * vv.x; o[j].y += pw * vv.y;
            o[j].z += pw * vv.z; o[j].w += pw * vv.w;
        }
    }
#pragma unroll
    for (int j = 0; j < 8; j++) {
        uint2 hh, ll;
        split4(o[j], hh, ll);
        *(uint2*)(ch + (size_t)token * 256 + h * 32 + j * 4) = hh;
        *(uint2*)(cl + (size_t)token * 256 + h * 32 + j * 4) = ll;
    }
}

// ---------------- launch ----------------
extern "C" void kernel_launch(void* const* d_in, const int* in_sizes, int n_in,
                              void* d_out, int out_size) {
    const float* src   = (const float*)d_in[0];
    const float* pos   = (const float*)d_in[1];
    const float* refp  = (const float*)d_in[2];
    const float* text  = (const float*)d_in[5];
    const float* so_w  = (const float*)d_in[7];
    const float* so_b  = (const float*)d_in[8];
    const float* aw_w  = (const float*)d_in[9];
    const float* aw_b  = (const float*)d_in[10];
    const float* vp_w  = (const float*)d_in[11];
    const float* vp_b  = (const float*)d_in[12];
    const float* op_w  = (const float*)d_in[13];
    const float* op_b  = (const float*)d_in[14];
    const float* ln1_g = (const float*)d_in[15];
    const float* ln1_b = (const float*)d_in[16];
    const float* ipw   = (const float*)d_in[17];
    const float* ipb   = (const float*)d_in[18];
    const float* mo_w  = (const float*)d_in[19];
    const float* mo_b  = (const float*)d_in[20];
    const float* ln3_g = (const float*)d_in[21];
    const float* ln3_b = (const float*)d_in[22];
    const float* l1_w  = (const float*)d_in[23];
    const float* l1_b  = (const float*)d_in[24];
    const float* l2_w  = (const float*)d_in[25];
    const float* l2_b  = (const float*)d_in[26];
    const float* ln2_g = (const float*)d_in[27];
    const float* ln2_b = (const float*)d_in[28];

    float* out_x = (float*)d_out;
    float* out_text = out_x + (size_t)NTOK * D_MODEL;

    float *q, *val, *offs, *aw, *kh, *vh;
    cudaGetSymbolAddress((void**)&q, g_q);
    cudaGetSymbolAddress((void**)&val, g_value);
    cudaGetSymbolAddress((void**)&offs, g_offs);
    cudaGetSymbolAddress((void**)&aw, g_aw);
    cudaGetSymbolAddress((void**)&kh, g_kh);
    cudaGetSymbolAddress((void**)&vh, g_vh);
    __nv_bfloat16 *Ah, *Al, *Bh, *Bl, *hh, *hl;
    cudaGetSymbolAddress((void**)&Ah, g_Ah);
    cudaGetSymbolAddress((void**)&Al, g_Al);
    cudaGetSymbolAddress((void**)&Bh, g_Bh);
    cudaGetSymbolAddress((void**)&Bl, g_Bl);
    cudaGetSymbolAddress((void**)&hh, g_hh);
    cudaGetSymbolAddress((void**)&hl, g_hl);
    __nv_bfloat16 *vpwh, *vpwl, *sowh, *sowl, *awwh, *awwl, *opwh, *opwl;
    __nv_bfloat16 *wqwh, *wqwl, *mowh, *mowl, *l1wh, *l1wl, *l2wh, *l2wl;
    cudaGetSymbolAddress((void**)&vpwh, g_vpw_h); cudaGetSymbolAddress((void**)&vpwl, g_vpw_l);
    cudaGetSymbolAddress((void**)&sowh, g_sow_h); cudaGetSymbolAddress((void**)&sowl, g_sow_l);
    cudaGetSymbolAddress((void**)&awwh, g_aww_h); cudaGetSymbolAddress((void**)&awwl, g_aww_l);
    cudaGetSymbolAddress((void**)&opwh, g_opw_h); cudaGetSymbolAddress((void**)&opwl, g_opw_l);
    cudaGetSymbolAddress((void**)&wqwh, g_wqw_h); cudaGetSymbolAddress((void**)&wqwl, g_wqw_l);
    cudaGetSymbolAddress((void**)&mowh, g_mow_h); cudaGetSymbolAddress((void**)&mowl, g_mow_l);
    cudaGetSymbolAddress((void**)&l1wh, g_l1w_h); cudaGetSymbolAddress((void**)&l1wl, g_l1w_l);
    cudaGetSymbolAddress((void**)&l2wh, g_l2w_h); cudaGetSymbolAddress((void**)&l2wl, g_l2w_l);

    cudaFuncSetAttribute((const void*)tc_gemm<0, false, false>,
                         cudaFuncAttributeMaxDynamicSharedMemorySize, GEMM_SMEM);
    cudaFuncSetAttribute((const void*)tc_gemm<0, false, true>,
                         cudaFuncAttributeMaxDynamicSharedMemorySize, GEMM_SMEM);
    cudaFuncSetAttribute((const void*)tc_gemm<2, true, false>,
                         cudaFuncAttributeMaxDynamicSharedMemorySize, GEMM_SMEM);
    cudaFuncSetAttribute((const void*)tc_gemm<4, false, false>,
                         cudaFuncAttributeMaxDynamicSharedMemorySize, GEMM_SMEM);
    cudaFuncSetAttribute((const void*)tc_gemm_ln<true, true>,
                         cudaFuncAttributeMaxDynamicSharedMemorySize, GEMM_LN_SMEM);
    cudaFuncSetAttribute((const void*)tc_gemm_ln<true, false>,
                         cudaFuncAttributeMaxDynamicSharedMemorySize, GEMM_LN_SMEM);
    cudaFuncSetAttribute((const void*)tc_gemm_ln<false, false>,
                         cudaFuncAttributeMaxDynamicSharedMemorySize, GEMM_LN_SMEM);

    const int M = NTOK;
    const int mTiles = cdiv(M, 64);
    dim3 g256(2, mTiles), g384(3, mTiles), g1024(8, mTiles);
    const int nAct4 = M * D_MODEL / 4;

    // 1: weight conversions
    WJobs J;
    J.j[0] = {vp_w, vpwh, vpwl, 65536 / 4};
    J.j[1] = {so_w, sowh, sowl, 65536 / 4};
    J.j[2] = {aw_w, awwh, awwl, 32768 / 4};
    J.j[3] = {op_w, opwh, opwl, 65536 / 4};
    J.j[4] = {ipw,  wqwh, wqwl, 65536 / 4};
    J.j[5] = {mo_w, mowh, mowl, 65536 / 4};
    J.j[6] = {l1_w, l1wh, l1wl, 262144 / 4};
    J.j[7] = {l2_w, l2wh, l2wl, 262144 / 4};
    int totW4 = (65536 * 5 + 32768 + 262144 * 2) / 4;
    wconv_kernel<<<cdiv(totW4, 256), 256>>>(J);
    // 2: activation conversions
    actconv_kernel<<<cdiv(nAct4, 256), 256>>>(src, pos, Ah, Al, Bh, Bl, nAct4);
    // 3: text K/V
    kv_proj_kernel<<<B_SZ * LT, 256>>>(text, ipw, ipb, kh, vh);
    // 4: value = src @ vp^T + b  -> fp16
    tc_gemm<0, false, true><<<g256, 256, GEMM_SMEM>>>(Ah, Al, vpwh, vpwl, nullptr, nullptr,
                                                      vp_b, nullptr, val, nullptr,
                                                      nullptr, nullptr, M, 256, 256);
    // 5: fused offs + aw
    tc_gemm<4, false, false><<<g384, 256, GEMM_SMEM>>>(Bh, Bl, sowh, sowl, awwh, awwl,
                                                       so_b, aw_b, offs, aw,
                                                       nullptr, nullptr, M, 256, 256);
    // 6: deformable sampling -> ms split planes (A)
    msdeform_kernel<<<cdiv(M * NH * 32, 256), 256>>>((const __half*)val, offs, aw, refp, Ah, Al);
    // 7: fused GEMM+LN1: x = LN(ms@op^T + b + src) -> out_x; (x+pos) -> B planes
    tc_gemm_ln<true, true><<<mTiles, 256, GEMM_LN_SMEM>>>(Ah, Al, opwh, opwl, op_b, src,
                                                          ln1_g, ln1_b, pos, out_x, Bh, Bl,
                                                          M, 256);
    // 8: qh = (x+pos) @ wq^T + bq
    tc_gemm<0, false, false><<<g256, 256, GEMM_SMEM>>>(Bh, Bl, wqwh, wqwl, nullptr, nullptr,
                                                       ipb, nullptr, q, nullptr,
                                                       nullptr, nullptr, M, 256, 256);
    // 9: cross attention -> ctx split planes (A)
    cross_attn_kernel<<<cdiv(M * NH, 256), 256>>>(q, kh, vh, Ah, Al);
    // 10: fused GEMM+LN3: x = LN(ctx@mo^T + b + x) -> out_x; x -> B planes
    tc_gemm_ln<true, false><<<mTiles, 256, GEMM_LN_SMEM>>>(Ah, Al, mowh, mowl, mo_b, out_x,
                                                           ln3_g, ln3_b, nullptr, out_x, Bh, Bl,
                                                           M, 256);
    // 11: hid = relu(x@l1^T + b1) split planes
    tc_gemm<2, true, false><<<g1024, 256, GEMM_SMEM>>>(Bh, Bl, l1wh, l1wl, nullptr, nullptr,
                                                       l1_b, nullptr, nullptr, nullptr,
                                                       hh, hl, M, DFF, 256);
    // 12: fused GEMM+LN2: out = LN(hid@l2^T + b2 + x) -> out_x
    tc_gemm_ln<false, false><<<mTiles, 256, GEMM_LN_SMEM>>>(hh, hl, l2wh, l2wl, l2_b, out_x,
                                                            ln2_g, ln2_b, nullptr, out_x,
                                                            nullptr, nullptr, M, 1024);
    // 13: pass-through text_memory
    cudaMemcpyAsync(out_text, text, (size_t)B_SZ * LT * D_MODEL * sizeof(float),
                    cudaMemcpyDeviceToDevice, 0);
}

// round 11
// speedup vs baseline: 1.3822x; 1.3059x over previous
#include <cuda_runtime.h>
#include <cuda_fp16.h>
#include <cstdint>
#include <math.h>

// ---------------- problem constants ----------------
#define D_MODEL 256
#define NH 8
#define HD 32
#define NL 4
#define NP 4
#define DFF 1024
#define B_SZ 2
#define LT 20
#define LQ_C 20197
#define NTOK (B_SZ * LQ_C)   // 40394

__device__ __constant__ int c_H[NL]  = {100, 50, 25, 13};
__device__ __constant__ int c_W[NL]  = {152, 76, 38, 19};
__device__ __constant__ int c_St[NL] = {0, 15200, 19000, 19950};

// ---------------- scratch (static device globals; no allocation) ----------------
__device__ float g_q[NTOK * D_MODEL];
__device__ float g_offs[NTOK * D_MODEL];
__device__ float g_aw[NTOK * 128];
__device__ float g_kh[B_SZ * LT * D_MODEL];
__device__ float g_vh[B_SZ * LT * D_MODEL];
__device__ __half g_val[NTOK * D_MODEL];
__device__ __half g_A[NTOK * D_MODEL];     // src -> ms -> ctx (fp16 GEMM A operand)
__device__ __half g_B[NTOK * D_MODEL];     // src+pos -> x+pos -> x
__device__ __half g_hid[NTOK * DFF];
__device__ __half g_vpw[65536];
__device__ __half g_sow[65536];
__device__ __half g_aww[32768];
__device__ __half g_opw[65536];
__device__ __half g_wqw[65536];
__device__ __half g_mow[65536];
__device__ __half g_l1w[262144];
__device__ __half g_l2w[262144];

static inline int cdiv(int a, int b) { return (a + b - 1) / b; }

__device__ __forceinline__ uint32_t smem_u32(const void* p) {
    uint32_t a;
    asm("{ .reg .u64 t; cvta.to.shared.u64 t, %1; cvt.u32.u64 %0, t; }" : "=r"(a) : "l"(p));
    return a;
}
__device__ __forceinline__ void ldm_x4(uint32_t addr, uint32_t& r0, uint32_t& r1,
                                       uint32_t& r2, uint32_t& r3) {
    asm volatile("ldmatrix.sync.aligned.m8n8.x4.shared.b16 {%0,%1,%2,%3}, [%4];"
                 : "=r"(r0), "=r"(r1), "=r"(r2), "=r"(r3) : "r"(addr));
}
__device__ __forceinline__ void mma_f16(float* c, const uint32_t* a, const uint32_t* b) {
    asm volatile(
        "mma.sync.aligned.m16n8k16.row.col.f32.f16.f16.f32 "
        "{%0,%1,%2,%3}, {%4,%5,%6,%7}, {%8,%9}, {%0,%1,%2,%3};"
        : "+f"(c[0]), "+f"(c[1]), "+f"(c[2]), "+f"(c[3])
        : "r"(a[0]), "r"(a[1]), "r"(a[2]), "r"(a[3]), "r"(b[0]), "r"(b[1]));
}
__device__ __forceinline__ uint2 f4_to_h4(float4 v) {
    union { __half2 h2[2]; uint2 u; } U;
    U.h2[0] = __floats2half2_rn(v.x, v.y);
    U.h2[1] = __floats2half2_rn(v.z, v.w);
    return U.u;
}
__device__ __forceinline__ void cpa16(uint32_t dst, const void* src) {
    asm volatile("cp.async.cg.shared.global [%0], [%1], 16;" :: "r"(dst), "l"(src));
}
__device__ __forceinline__ void cpa16z(uint32_t dst, const void* src, bool v) {
    int sz = v ? 16 : 0;
    asm volatile("cp.async.cg.shared.global [%0], [%1], 16, %2;"
                 :: "r"(dst), "l"(src), "r"(sz));
}

// =====================================================================
// tc_gemm: single-pass fp16 GEMM, fp32 accum. C = A[M,K] @ W[N,K]^T + bias
//   MODE 0: +bias   2: +bias,relu
//   MODE 4: fused dual (blocks 0,1 -> C fp32; block 2 -> W2 softmax16 -> C2)
//   OH: write __half to (half*)C instead of fp32.
//   CTA 64x128, 256 thr (warp 32x32), KC=64 (128B rows), 3 stages, 1 sync.
// =====================================================================
#define KC 64
#define A_TILE_B 8192                   // 64 rows x 128B
#define B_TILE_B 16384                  // 128 rows x 128B
#define STAGE_B (A_TILE_B + B_TILE_B)   // 24 KB
#define NSTAGE 3
#define GEMM_SMEM (NSTAGE * STAGE_B)    // 72 KB

template <int MODE, bool OH>
__global__ void __launch_bounds__(256, 2)
tc_gemm(const __half* __restrict__ A, const __half* __restrict__ W,
        const __half* __restrict__ W2, const float* __restrict__ bias,
        const float* __restrict__ bias2, float* __restrict__ C, float* __restrict__ C2,
        int M, int N, int K) {
    extern __shared__ char smem[];
    const uint32_t sbase = smem_u32(smem);
    const int tid = threadIdx.x;
    const int wid = tid >> 5;
    const int lane = tid & 31;
    const int rowBase = blockIdx.y * 64;
    const int colBase = blockIdx.x * 128;
    const int warpM = wid >> 2;
    const int warpN = wid & 3;
    const bool isAw = (MODE == 4) && (blockIdx.x == 2);

    const __half* bW = isAw ? W2 : (W + (size_t)colBase * K);

    float acc[2][4][4];
#pragma unroll
    for (int mi = 0; mi < 2; mi++)
#pragma unroll
        for (int ni = 0; ni < 4; ni++)
#pragma unroll
            for (int j = 0; j < 4; j++) acc[mi][ni][j] = 0.f;

    const uint32_t swX = (uint32_t)((lane & 7) << 4);
    const int aKB0 = (lane >> 4) * 16;
    uint32_t aRowOff[2];
#pragma unroll
    for (int mi = 0; mi < 2; mi++)
        aRowOff[mi] = (uint32_t)((warpM * 32 + mi * 16 + (lane & 15)) * 128);
    const int grp = lane >> 3;
    const int bKB0 = (grp & 1) * 16;
    uint32_t bRowOff[2];
#pragma unroll
    for (int np = 0; np < 2; np++)
        bRowOff[np] = (uint32_t)((warpN * 32 + np * 16 + ((grp >> 1) << 3) + (lane & 7)) * 128);

    const int nChunks = K / KC;
    // copy coords: 16B chunks; rows have 8 chunks
    const int cr = tid >> 3, cc = tid & 7;

    auto copy_chunk = [&](int kt, uint32_t stg) {
        const int k0 = kt * KC;
        // B: 128 rows x 8 chunks = 1024 -> 4 per thread
#pragma unroll
        for (int i = 0; i < 4; i++) {
            int idx = tid + i * 256;
            int r = idx >> 3, c = idx & 7;
            uint32_t off = (uint32_t)(r * 128 + ((c * 16) ^ ((r & 7) << 4)));
            cpa16(stg + A_TILE_B + off, bW + (size_t)r * K + k0 + c * 8);
        }
        // A: 64 rows x 8 chunks = 512 -> 2 per thread
#pragma unroll
        for (int i = 0; i < 2; i++) {
            int idx = tid + i * 256;
            int r = idx >> 3, c = idx & 7;
            uint32_t off = (uint32_t)(r * 128 + ((c * 16) ^ ((r & 7) << 4)));
            int gr = rowBase + r;
            bool v = gr < M;
            int crr = v ? gr : (M - 1);
            cpa16z(stg + off, A + (size_t)crr * K + k0 + c * 8, v);
        }
    };

    copy_chunk(0, sbase);
    asm volatile("cp.async.commit_group;");
    if (nChunks > 1) {
        copy_chunk(1, sbase + STAGE_B);
        asm volatile("cp.async.commit_group;");
    }
    int stgIdx = 0;
    for (int kt = 0; kt < nChunks; kt++) {
        if (kt + 1 < nChunks) asm volatile("cp.async.wait_group 1;");
        else asm volatile("cp.async.wait_group 0;");
        __syncthreads();
        if (kt + 2 < nChunks) {
            int ws = stgIdx + 2;
            if (ws >= NSTAGE) ws -= NSTAGE;
            copy_chunk(kt + 2, sbase + (uint32_t)(ws * STAGE_B));
            asm volatile("cp.async.commit_group;");
        }
        const uint32_t AS = sbase + (uint32_t)(stgIdx * STAGE_B);
        const uint32_t BS = AS + A_TILE_B;
#pragma unroll
        for (int kst = 0; kst < 4; kst++) {
            uint32_t a[2][4];
#pragma unroll
            for (int mi = 0; mi < 2; mi++) {
                uint32_t kb = (uint32_t)(aKB0 + kst * 32);
                ldm_x4(AS + aRowOff[mi] + (kb ^ swX), a[mi][0], a[mi][1], a[mi][2], a[mi][3]);
            }
            uint32_t b[4][2];
#pragma unroll
            for (int np = 0; np < 2; np++) {
                uint32_t kb = (uint32_t)(bKB0 + kst * 32);
                uint32_t r0, r1, r2, r3;
                ldm_x4(BS + bRowOff[np] + (kb ^ swX), r0, r1, r2, r3);
                b[np * 2][0] = r0; b[np * 2][1] = r1;
                b[np * 2 + 1][0] = r2; b[np * 2 + 1][1] = r3;
            }
#pragma unroll
            for (int mi = 0; mi < 2; mi++)
#pragma unroll
                for (int ni = 0; ni < 4; ni++) mma_f16(acc[mi][ni], a[mi], b[ni]);
        }
        stgIdx++;
        if (stgIdx == NSTAGE) stgIdx = 0;
    }

    const int qrow = lane >> 2;
    const int qcol = (lane & 3) * 2;
#pragma unroll
    for (int ni = 0; ni < 4; ni++) {
        int cl_ = warpN * 32 + ni * 8 + qcol;
        int bcol = isAw ? cl_ : (colBase + cl_);
        const float* bp = isAw ? bias2 : bias;
        float b0 = __ldg(bp + bcol), b1 = __ldg(bp + bcol + 1);
#pragma unroll
        for (int mi = 0; mi < 2; mi++) {
            acc[mi][ni][0] += b0; acc[mi][ni][1] += b1;
            acc[mi][ni][2] += b0; acc[mi][ni][3] += b1;
        }
    }
    if (isAw) {
#pragma unroll
        for (int mi = 0; mi < 2; mi++)
#pragma unroll
            for (int g = 0; g < 2; g++)
#pragma unroll
                for (int rh = 0; rh < 2; rh++) {
                    float v0 = acc[mi][2 * g][rh * 2], v1 = acc[mi][2 * g][rh * 2 + 1];
                    float v2 = acc[mi][2 * g + 1][rh * 2], v3 = acc[mi][2 * g + 1][rh * 2 + 1];
                    float mx = fmaxf(fmaxf(v0, v1), fmaxf(v2, v3));
                    mx = fmaxf(mx, __shfl_xor_sync(0xffffffffu, mx, 1));
                    mx = fmaxf(mx, __shfl_xor_sync(0xffffffffu, mx, 2));
                    v0 = expf(v0 - mx); v1 = expf(v1 - mx);
                    v2 = expf(v2 - mx); v3 = expf(v3 - mx);
                    float s = v0 + v1 + v2 + v3;
                    s += __shfl_xor_sync(0xffffffffu, s, 1);
                    s += __shfl_xor_sync(0xffffffffu, s, 2);
                    float inv = 1.f / s;
                    acc[mi][2 * g][rh * 2] = v0 * inv; acc[mi][2 * g][rh * 2 + 1] = v1 * inv;
                    acc[mi][2 * g + 1][rh * 2] = v2 * inv; acc[mi][2 * g + 1][rh * 2 + 1] = v3 * inv;
                }
    }
#pragma unroll
    for (int mi = 0; mi < 2; mi++)
#pragma unroll
        for (int rh = 0; rh < 2; rh++) {
            int row = rowBase + warpM * 32 + mi * 16 + qrow + rh * 8;
            if (row >= M) continue;
#pragma unroll
            for (int ni = 0; ni < 4; ni++) {
                int cl_ = warpN * 32 + ni * 8 + qcol;
                float v0 = acc[mi][ni][rh * 2], v1 = acc[mi][ni][rh * 2 + 1];
                if (MODE == 2) { v0 = fmaxf(v0, 0.f); v1 = fmaxf(v1, 0.f); }
                if (OH) {
                    *(__half2*)((__half*)C + (size_t)row * N + colBase + cl_) =
                        __floats2half2_rn(v0, v1);
                } else if (isAw) {
                    *(float2*)(C2 + (size_t)row * 128 + cl_) = make_float2(v0, v1);
                } else {
                    *(float2*)(C + (size_t)row * N + colBase + cl_) = make_float2(v0, v1);
                }
            }
        }
}

// =====================================================================
// tc_gemm_ln: fp16 GEMM + residual + fused LayerNorm. CTA 64x256 (full rows).
//   out = LN(A@W^T + bias + R) -> fp32 Cout; optional Sh = half(out [+P]).
// =====================================================================
#define LA_TILE_B 8192
#define LB_TILE_B 32768                 // 256 rows x 128B
#define LSTAGE_B (LA_TILE_B + LB_TILE_B)
#define GEMM_LN_SMEM (2 * LSTAGE_B)     // 80 KB

template <bool WANTH, bool HASP>
__global__ void __launch_bounds__(256, 2)
tc_gemm_ln(const __half* __restrict__ A, const __half* __restrict__ W,
           const float* __restrict__ bias, const float* __restrict__ R,
           const float* __restrict__ lng, const float* __restrict__ lnb,
           const float* __restrict__ P, float* __restrict__ Cout,
           __half* __restrict__ Sh, int M, int K) {
    extern __shared__ char smem[];
    const uint32_t sbase = smem_u32(smem);
    const int tid = threadIdx.x;
    const int wid = tid >> 5;
    const int lane = tid & 31;
    const int rowBase = blockIdx.x * 64;
    const int warpM = wid >> 2;
    const int warpN = wid & 3;

    float acc[2][8][4];
#pragma unroll
    for (int mi = 0; mi < 2; mi++)
#pragma unroll
        for (int ni = 0; ni < 8; ni++)
#pragma unroll
            for (int j = 0; j < 4; j++) acc[mi][ni][j] = 0.f;

    const uint32_t swX = (uint32_t)((lane & 7) << 4);
    const int aKB0 = (lane >> 4) * 16;
    uint32_t aRowOff[2];
#pragma unroll
    for (int mi = 0; mi < 2; mi++)
        aRowOff[mi] = (uint32_t)((warpM * 32 + mi * 16 + (lane & 15)) * 128);
    const int grp = lane >> 3;
    const int bKB0 = (grp & 1) * 16;
    uint32_t bRowOff[4];
#pragma unroll
    for (int np = 0; np < 4; np++)
        bRowOff[np] = (uint32_t)((warpN * 64 + np * 16 + ((grp >> 1) << 3) + (lane & 7)) * 128);

    const int nChunks = K / KC;

    auto copy_chunk = [&](int kt, uint32_t stg) {
        const int k0 = kt * KC;
        // B: 256 rows x 8 chunks = 2048 -> 8 per thread
#pragma unroll
        for (int i = 0; i < 8; i++) {
            int idx = tid + i * 256;
            int r = idx >> 3, c = idx & 7;
            uint32_t off = (uint32_t)(r * 128 + ((c * 16) ^ ((r & 7) << 4)));
            cpa16(stg + LA_TILE_B + off, W + (size_t)r * K + k0 + c * 8);
        }
        // A: 512 -> 2 per thread
#pragma unroll
        for (int i = 0; i < 2; i++) {
            int idx = tid + i * 256;
            int r = idx >> 3, c = idx & 7;
            uint32_t off = (uint32_t)(r * 128 + ((c * 16) ^ ((r & 7) << 4)));
            int gr = rowBase + r;
            bool v = gr < M;
            int crr = v ? gr : (M - 1);
            cpa16z(stg + off, A + (size_t)crr * K + k0 + c * 8, v);
        }
    };

    copy_chunk(0, sbase);
    asm volatile("cp.async.commit_group;");
    for (int kt = 0; kt < nChunks; kt++) {
        if (kt + 1 < nChunks) {
            copy_chunk(kt + 1, sbase + (uint32_t)(((kt + 1) & 1) * LSTAGE_B));
            asm volatile("cp.async.commit_group;");
            asm volatile("cp.async.wait_group 1;");
        } else {
            asm volatile("cp.async.wait_group 0;");
        }
        __syncthreads();
        const uint32_t AS = sbase + (uint32_t)((kt & 1) * LSTAGE_B);
        const uint32_t BS = AS + LA_TILE_B;
#pragma unroll
        for (int kst = 0; kst < 4; kst++) {
            uint32_t a[2][4];
#pragma unroll
            for (int mi = 0; mi < 2; mi++) {
                uint32_t kb = (uint32_t)(aKB0 + kst * 32);
                ldm_x4(AS + aRowOff[mi] + (kb ^ swX), a[mi][0], a[mi][1], a[mi][2], a[mi][3]);
            }
#pragma unroll
            for (int np = 0; np < 4; np++) {
                uint32_t kb = (uint32_t)(bKB0 + kst * 32);
                uint32_t r0, r1, r2, r3;
                ldm_x4(BS + bRowOff[np] + (kb ^ swX), r0, r1, r2, r3);
                uint32_t b0[2] = {r0, r1}, b1[2] = {r2, r3};
#pragma unroll
                for (int mi = 0; mi < 2; mi++) {
                    mma_f16(acc[mi][2 * np], a[mi], b0);
                    mma_f16(acc[mi][2 * np + 1], a[mi], b1);
                }
            }
        }
        if (kt + 1 < nChunks) __syncthreads();
    }

    // ---- fused epilogue: bias + residual + LayerNorm ----
    __syncthreads();
    float* red = (float*)smem;
    const int qrow = lane >> 2;
    const int qcol = (lane & 3) * 2;

#pragma unroll
    for (int mi = 0; mi < 2; mi++)
#pragma unroll
        for (int rh = 0; rh < 2; rh++) {
            int rloc = warpM * 32 + mi * 16 + rh * 8 + qrow;
            int row = rowBase + rloc;
            bool ok = row < M;
            float s = 0.f, qsum = 0.f;
#pragma unroll
            for (int ni = 0; ni < 8; ni++) {
                int col = warpN * 64 + ni * 8 + qcol;
                float b0 = __ldg(bias + col), b1 = __ldg(bias + col + 1);
                float v0 = acc[mi][ni][rh * 2] + b0;
                float v1 = acc[mi][ni][rh * 2 + 1] + b1;
                if (ok) {
                    const float2 rr = *(const float2*)(R + (size_t)row * 256 + col);
                    v0 += rr.x; v1 += rr.y;
                }
                acc[mi][ni][rh * 2] = v0;
                acc[mi][ni][rh * 2 + 1] = v1;
                s += v0 + v1;
                qsum += v0 * v0 + v1 * v1;
            }
            s += __shfl_xor_sync(0xffffffffu, s, 1);
            s += __shfl_xor_sync(0xffffffffu, s, 2);
            qsum += __shfl_xor_sync(0xffffffffu, qsum, 1);
            qsum += __shfl_xor_sync(0xffffffffu, qsum, 2);
            if ((lane & 3) == 0) {
                red[(rloc << 3) + (warpN << 1)] = s;
                red[(rloc << 3) + (warpN << 1) + 1] = qsum;
            }
        }
    __syncthreads();
#pragma unroll
    for (int mi = 0; mi < 2; mi++)
#pragma unroll
        for (int rh = 0; rh < 2; rh++) {
            int rloc = warpM * 32 + mi * 16 + rh * 8 + qrow;
            int row = rowBase + rloc;
            if (row >= M) continue;
            float s = red[(rloc << 3)] + red[(rloc << 3) + 2] +
                      red[(rloc << 3) + 4] + red[(rloc << 3) + 6];
            float qsum = red[(rloc << 3) + 1] + red[(rloc << 3) + 3] +
                         red[(rloc << 3) + 5] + red[(rloc << 3) + 7];
            float mean = s * (1.f / 256.f);
            float var = qsum * (1.f / 256.f) - mean * mean;
            float rstd = rsqrtf(var + 1e-5f);
#pragma unroll
            for (int ni = 0; ni < 8; ni++) {
                int col = warpN * 64 + ni * 8 + qcol;
                float g0 = __ldg(lng + col), g1 = __ldg(lng + col + 1);
                float c0 = __ldg(lnb + col), c1 = __ldg(lnb + col + 1);
                float y0 = (acc[mi][ni][rh * 2] - mean) * rstd * g0 + c0;
                float y1 = (acc[mi][ni][rh * 2 + 1] - mean) * rstd * g1 + c1;
                *(float2*)(Cout + (size_t)row * 256 + col) = make_float2(y0, y1);
                if (WANTH) {
                    float t0 = y0, t1 = y1;
                    if (HASP) {
                        const float2 pp = *(const float2*)(P + (size_t)row * 256 + col);
                        t0 += pp.x; t1 += pp.y;
                    }
                    *(__half2*)(Sh + (size_t)row * 256 + col) = __floats2half2_rn(t0, t1);
                }
            }
        }
}

// ---------------- batched weight conversion (fp32 -> fp16) ----------------
struct WJob { const float* s; __half* h; int n4; };
struct WJobs { WJob j[8]; };
__global__ void wconv_kernel(WJobs J) {
    int i = blockIdx.x * blockDim.x + threadIdx.x;
#pragma unroll
    for (int k = 0; k < 8; k++) {
        int n = J.j[k].n4;
        if (i < n) {
            ((uint2*)J.j[k].h)[i] = f4_to_h4(((const float4*)J.j[k].s)[i]);
            return;
        }
        i -= n;
    }
}
__global__ void actconv_kernel(const float* __restrict__ src, const float* __restrict__ pos,
                               __half* __restrict__ A, __half* __restrict__ B, int n4) {
    int i = blockIdx.x * blockDim.x + threadIdx.x;
    if (i >= n4) return;
    float4 s = ((const float4*)src)[i];
    float4 p = ((const float4*)pos)[i];
    ((uint2*)A)[i] = f4_to_h4(s);
    s.x += p.x; s.y += p.y; s.z += p.z; s.w += p.w;
    ((uint2*)B)[i] = f4_to_h4(s);
}

// ---------------- multi-scale deformable sampling (fp16 value; fp16 out) ----
__global__ void msdeform_kernel(const __half* __restrict__ value, const float* __restrict__ offs,
                                const float* __restrict__ aw, const float* __restrict__ ref,
                                __half* __restrict__ outh) {
    int gw = (blockIdx.x * blockDim.x + threadIdx.x) >> 5;
    int lane = threadIdx.x & 31;
    if (gw >= NTOK * NH) return;
    int token = gw >> 3, h = gw & 7;
    int b = (token >= LQ_C) ? 1 : 0;

    int p = lane & 15;
    int l = p >> 2;
    int Wl = c_W[l], Hl = c_H[l];
    float Wf = (float)Wl, Hf = (float)Hl;
    float rx = __ldg(ref + (size_t)token * 8 + l * 2);
    float ry = __ldg(ref + (size_t)token * 8 + l * 2 + 1);
    float ox = __ldg(offs + (size_t)token * 256 + h * 32 + p * 2);
    float oy = __ldg(offs + (size_t)token * 256 + h * 32 + p * 2 + 1);
    float wA = __ldg(aw + (size_t)token * 128 + h * 16 + p);

    float X = (rx + ox / Wf) * Wf - 0.5f;
    float Y = (ry + oy / Hf) * Hf - 0.5f;
    float x0f = floorf(X), y0f = floorf(Y);
    float lx = X - x0f, ly = Y - y0f;
    int x0 = (int)x0f, y0 = (int)y0f;
    int x1 = x0 + 1, y1 = y0 + 1;
    bool vx0 = (x0 >= 0) & (x0 < Wl), vx1 = (x1 >= 0) & (x1 < Wl);
    bool vy0 = (y0 >= 0) & (y0 < Hl), vy1 = (y1 >= 0) & (y1 < Hl);
    int cx0 = min(max(x0, 0), Wl - 1), cx1 = min(max(x1, 0), Wl - 1);
    int cy0 = min(max(y0, 0), Hl - 1), cy1 = min(max(y1, 0), Hl - 1);
    int base = b * LQ_C + c_St[l];
    int r00 = base + cy0 * Wl + cx0;
    int r01 = base + cy0 * Wl + cx1;
    int r10 = base + cy1 * Wl + cx0;
    int r11 = base + cy1 * Wl + cx1;
    float w00 = wA * (1.f - lx) * (1.f - ly) * (float)(vx0 & vy0);
    float w01 = wA * lx * (1.f - ly) * (float)(vx1 & vy0);
    float w10 = wA * (1.f - lx) * ly * (float)(vx0 & vy1);
    float w11 = wA * lx * ly * (float)(vx1 & vy1);

    const __half* vb = value + h * 32 + lane;
    float acc = 0.f;
#pragma unroll
    for (int pp = 0; pp < 16; pp++) {
        int s00 = __shfl_sync(0xffffffffu, r00, pp);
        int s01 = __shfl_sync(0xffffffffu, r01, pp);
        int s10 = __shfl_sync(0xffffffffu, r10, pp);
        int s11 = __shfl_sync(0xffffffffu, r11, pp);
        float u00 = __shfl_sync(0xffffffffu, w00, pp);
        float u01 = __shfl_sync(0xffffffffu, w01, pp);
        float u10 = __shfl_sync(0xffffffffu, w10, pp);
        float u11 = __shfl_sync(0xffffffffu, w11, pp);
        acc += u00 * __half2float(__ldg(vb + (size_t)s00 * 256));
        acc += u01 * __half2float(__ldg(vb + (size_t)s01 * 256));
        acc += u10 * __half2float(__ldg(vb + (size_t)s10 * 256));
        acc += u11 * __half2float(__ldg(vb + (size_t)s11 * 256));
    }
    outh[(size_t)token * 256 + h * 32 + lane] = __float2half_rn(acc);
}

// ---------------- text K/V projection ----------------
__global__ void kv_proj_kernel(const float* __restrict__ text, const float* __restrict__ ipw,
                               const float* __restrict__ ipb, float* __restrict__ kh,
                               float* __restrict__ vh) {
    int row = blockIdx.x;
    int c = threadIdx.x;
    const float* t = text + (size_t)row * 256;
    const float* wk = ipw + (size_t)(256 + c) * 256;
    const float* wv = ipw + (size_t)(512 + c) * 256;
    float sk = ipb[256 + c], sv = ipb[512 + c];
    for (int k = 0; k < 256; k++) {
        float tv = t[k];
        sk += tv * wk[k];
        sv += tv * wv[k];
    }
    kh[(size_t)row * 256 + c] = sk;
    vh[(size_t)row * 256 + c] = sv;
}

// ---------------- text cross-attention (fp16 out) ----------------
__global__ void cross_attn_kernel(const float* __restrict__ qh, const float* __restrict__ kh,
                                  const float* __restrict__ vh, __half* __restrict__ ch) {
    int idx = blockIdx.x * blockDim.x + threadIdx.x;
    if (idx >= NTOK * NH) return;
    int token = idx >> 3, h = idx & 7;
    int b = (token >= LQ_C) ? 1 : 0;
    const float4* q = (const float4*)(qh + (size_t)token * 256 + h * 32);
    float4 qv[8];
#pragma unroll
    for (int j = 0; j < 8; j++) qv[j] = q[j];

    float sc[LT];
    float mx = -1e30f;
    const float scale = 0.17677669529663687f;
#pragma unroll 4
    for (int k = 0; k < LT; k++) {
        const float4* kp = (const float4*)(kh + (size_t)(b * LT + k) * 256 + h * 32);
        float s = 0.f;
#pragma unroll
        for (int j = 0; j < 8; j++) {
            float4 kv = kp[j];
            s += qv[j].x * kv.x + qv[j].y * kv.y + qv[j].z * kv.z + qv[j].w * kv.w;
        }
        s *= scale;
        sc[k] = s;
        mx = fmaxf(mx, s);
    }
    float denom = 0.f;
#pragma unroll
    for (int k = 0; k < LT; k++) { sc[k] = expf(sc[k] - mx); denom += sc[k]; }
    float inv = 1.f / denom;
    float4 o[8];
#pragma unroll
    for (int j = 0; j < 8; j++) o[j] = make_float4(0.f, 0.f, 0.f, 0.f);
#pragma unroll 4
    for (int k = 0; k < LT; k++) {
        float pw = sc[k] * inv;
        const float4* vp = (const float4*)(vh + (size_t)(b * LT + k) * 256 + h * 32);
#pragma unroll
        for (int j = 0; j < 8; j++) {
            float4 vv = vp[j];
            o[j].x += pw * vv.x; o[j].y += pw * vv.y;
            o[j].z += pw * vv.z; o[j].w += pw * vv.w;
        }
    }
#pragma unroll
    for (int j = 0; j < 8; j++)
        *(uint2*)(ch + (size_t)token * 256 + h * 32 + j * 4) = f4_to_h4(o[j]);
}

// ---------------- launch ----------------
extern "C" void kernel_launch(void* const* d_in, const int* in_sizes, int n_in,
                              void* d_out, int out_size) {
    const float* src   = (const float*)d_in[0];
    const float* pos   = (const float*)d_in[1];
    const float* refp  = (const float*)d_in[2];
    const float* text  = (const float*)d_in[5];
    const float* so_w  = (const float*)d_in[7];
    const float* so_b  = (const float*)d_in[8];
    const float* aw_w  = (const float*)d_in[9];
    const float* aw_b  = (const float*)d_in[10];
    const float* vp_w  = (const float*)d_in[11];
    const float* vp_b  = (const float*)d_in[12];
    const float* op_w  = (const float*)d_in[13];
    const float* op_b  = (const float*)d_in[14];
    const float* ln1_g = (const float*)d_in[15];
    const float* ln1_b = (const float*)d_in[16];
    const float* ipw   = (const float*)d_in[17];
    const float* ipb   = (const float*)d_in[18];
    const float* mo_w  = (const float*)d_in[19];
    const float* mo_b  = (const float*)d_in[20];
    const float* ln3_g = (const float*)d_in[21];
    const float* ln3_b = (const float*)d_in[22];
    const float* l1_w  = (const float*)d_in[23];
    const float* l1_b  = (const float*)d_in[24];
    const float* l2_w  = (const float*)d_in[25];
    const float* l2_b  = (const float*)d_in[26];
    const float* ln2_g = (const float*)d_in[27];
    const float* ln2_b = (const float*)d_in[28];

    float* out_x = (float*)d_out;
    float* out_text = out_x + (size_t)NTOK * D_MODEL;

    float *q, *offs, *aw, *kh, *vh;
    cudaGetSymbolAddress((void**)&q, g_q);
    cudaGetSymbolAddress((void**)&offs, g_offs);
    cudaGetSymbolAddress((void**)&aw, g_aw);
    cudaGetSymbolAddress((void**)&kh, g_kh);
    cudaGetSymbolAddress((void**)&vh, g_vh);
    __half *val, *A, *B, *hid;
    cudaGetSymbolAddress((void**)&val, g_val);
    cudaGetSymbolAddress((void**)&A, g_A);
    cudaGetSymbolAddress((void**)&B, g_B);
    cudaGetSymbolAddress((void**)&hid, g_hid);
    __half *vpw, *sow, *aww, *opw, *wqw, *mow, *l1w, *l2w;
    cudaGetSymbolAddress((void**)&vpw, g_vpw);
    cudaGetSymbolAddress((void**)&sow, g_sow);
    cudaGetSymbolAddress((void**)&aww, g_aww);
    cudaGetSymbolAddress((void**)&opw, g_opw);
    cudaGetSymbolAddress((void**)&wqw, g_wqw);
    cudaGetSymbolAddress((void**)&mow, g_mow);
    cudaGetSymbolAddress((void**)&l1w, g_l1w);
    cudaGetSymbolAddress((void**)&l2w, g_l2w);

    cudaFuncSetAttribute((const void*)tc_gemm<0, false>,
                         cudaFuncAttributeMaxDynamicSharedMemorySize, GEMM_SMEM);
    cudaFuncSetAttribute((const void*)tc_gemm<0, true>,
                         cudaFuncAttributeMaxDynamicSharedMemorySize, GEMM_SMEM);
    cudaFuncSetAttribute((const void*)tc_gemm<2, true>,
                         cudaFuncAttributeMaxDynamicSharedMemorySize, GEMM_SMEM);
    cudaFuncSetAttribute((const void*)tc_gemm<4, false>,
                         cudaFuncAttributeMaxDynamicSharedMemorySize, GEMM_SMEM);
    cudaFuncSetAttribute((const void*)tc_gemm_ln<true, true>,
                         cudaFuncAttributeMaxDynamicSharedMemorySize, GEMM_LN_SMEM);
    cudaFuncSetAttribute((const void*)tc_gemm_ln<true, false>,
                         cudaFuncAttributeMaxDynamicSharedMemorySize, GEMM_LN_SMEM);
    cudaFuncSetAttribute((const void*)tc_gemm_ln<false, false>,
                         cudaFuncAttributeMaxDynamicSharedMemorySize, GEMM_LN_SMEM);

    const int M = NTOK;
    const int mTiles = cdiv(M, 64);
    dim3 g256(2, mTiles), g384(3, mTiles), g1024(8, mTiles);
    const int nAct4 = M * D_MODEL / 4;

    // 1: weight conversions (batched)
    WJobs J;
    J.j[0] = {vp_w, vpw, 65536 / 4};
    J.j[1] = {so_w, sow, 65536 / 4};
    J.j[2] = {aw_w, aww, 32768 / 4};
    J.j[3] = {op_w, opw, 65536 / 4};
    J.j[4] = {ipw,  wqw, 65536 / 4};
    J.j[5] = {mo_w, mow, 65536 / 4};
    J.j[6] = {l1_w, l1w, 262144 / 4};
    J.j[7] = {l2_w, l2w, 262144 / 4};
    int totW4 = (65536 * 5 + 32768 + 262144 * 2) / 4;
    wconv_kernel<<<cdiv(totW4, 256), 256>>>(J);
    // 2: activation conversions (src -> A, src+pos -> B)
    actconv_kernel<<<cdiv(nAct4, 256), 256>>>(src, pos, A, B, nAct4);
    // 3: text K/V
    kv_proj_kernel<<<B_SZ * LT, 256>>>(text, ipw, ipb, kh, vh);
    // 4: value = src @ vp^T + b  -> fp16
    tc_gemm<0, true><<<g256, 256, GEMM_SMEM>>>(A, vpw, nullptr, vp_b, nullptr,
                                               (float*)val, nullptr, M, 256, 256);
    // 5: fused offs + aw
    tc_gemm<4, false><<<g384, 256, GEMM_SMEM>>>(B, sow, aww, so_b, aw_b,
                                                offs, aw, M, 256, 256);
    // 6: deformable sampling -> ms (fp16, into A)
    msdeform_kernel<<<cdiv(M * NH * 32, 256), 256>>>(val, offs, aw, refp, A);
    // 7: fused GEMM+LN1: x = LN(ms@op^T + b + src) -> out_x; (x+pos) -> B
    tc_gemm_ln<true, true><<<mTiles, 256, GEMM_LN_SMEM>>>(A, opw, op_b, src,
                                                          ln1_g, ln1_b, pos, out_x, B,
                                                          M, 256);
    // 8: qh = (x+pos) @ wq^T + bq (fp32 out)
    tc_gemm<0, false><<<g256, 256, GEMM_SMEM>>>(B, wqw, nullptr, ipb, nullptr,
                                                q, nullptr, M, 256, 256);
    // 9: cross attention -> ctx (fp16, into A)
    cross_attn_kernel<<<cdiv(M * NH, 256), 256>>>(q, kh, vh, A);
    // 10: fused GEMM+LN3: x = LN(ctx@mo^T + b + x) -> out_x; x -> B
    tc_gemm_ln<true, false><<<mTiles, 256, GEMM_LN_SMEM>>>(A, mow, mo_b, out_x,
                                                           ln3_g, ln3_b, nullptr, out_x, B,
                                                           M, 256);
    // 11: hid = relu(x@l1^T + b1) -> fp16
    tc_gemm<2, true><<<g1024, 256, GEMM_SMEM>>>(B, l1w, nullptr, l1_b, nullptr,
                                                (float*)hid, nullptr, M, DFF, 256);
    // 12: fused GEMM+LN2: out = LN(hid@l2^T + b2 + x) -> out_x
    tc_gemm_ln<false, false><<<mTiles, 256, GEMM_LN_SMEM>>>(hid, l2w, l2_b, out_x,
                                                            ln2_g, ln2_b, nullptr, out_x,
                                                            nullptr, M, 1024);
    // 13: pass-through text_memory
    cudaMemcpyAsync(out_text, text, (size_t)B_SZ * LT * D_MODEL * sizeof(float),
                    cudaMemcpyDeviceToDevice, 0);
}

// round 12
// speedup vs baseline: 1.9351x; 1.4000x over previous
#include <cuda_runtime.h>
#include <cuda_fp16.h>
#include <cstdint>
#include <math.h>

// ---------------- problem constants ----------------
#define D_MODEL 256
#define NH 8
#define HD 32
#define NL 4
#define NP 4
#define DFF 1024
#define B_SZ 2
#define LT 20
#define LQ_C 20197
#define NTOK (B_SZ * LQ_C)   // 40394

__device__ __constant__ int c_H[NL]  = {100, 50, 25, 13};
__device__ __constant__ int c_W[NL]  = {152, 76, 38, 19};
__device__ __constant__ int c_St[NL] = {0, 15200, 19000, 19950};

// ---------------- scratch (static device globals; no allocation) ----------------
__device__ float g_offs[NTOK * D_MODEL];
__device__ float g_aw[NTOK * 128];
__device__ __half g_q[NTOK * D_MODEL];
__device__ __half g_kh[B_SZ * LT * D_MODEL];
__device__ __half g_vh[B_SZ * LT * D_MODEL];
__device__ __half g_val[NTOK * D_MODEL];
__device__ __half g_A[NTOK * D_MODEL];     // src -> ms -> ctx (fp16 GEMM A operand)
__device__ __half g_B[NTOK * D_MODEL];     // src+pos -> x+pos -> x
__device__ __half g_hid[NTOK * DFF];
__device__ __half g_vpw[65536];
__device__ __half g_sow[65536];
__device__ __half g_aww[32768];
__device__ __half g_opw[65536];
__device__ __half g_wqw[65536];
__device__ __half g_mow[65536];
__device__ __half g_l1w[262144];
__device__ __half g_l2w[262144];

static inline int cdiv(int a, int b) { return (a + b - 1) / b; }

__device__ __forceinline__ uint32_t smem_u32(const void* p) {
    uint32_t a;
    asm("{ .reg .u64 t; cvta.to.shared.u64 t, %1; cvt.u32.u64 %0, t; }" : "=r"(a) : "l"(p));
    return a;
}
__device__ __forceinline__ void ldm_x4(uint32_t addr, uint32_t& r0, uint32_t& r1,
                                       uint32_t& r2, uint32_t& r3) {
    asm volatile("ldmatrix.sync.aligned.m8n8.x4.shared.b16 {%0,%1,%2,%3}, [%4];"
                 : "=r"(r0), "=r"(r1), "=r"(r2), "=r"(r3) : "r"(addr));
}
__device__ __forceinline__ void mma_f16(float* c, const uint32_t* a, const uint32_t* b) {
    asm volatile(
        "mma.sync.aligned.m16n8k16.row.col.f32.f16.f16.f32 "
        "{%0,%1,%2,%3}, {%4,%5,%6,%7}, {%8,%9}, {%0,%1,%2,%3};"
        : "+f"(c[0]), "+f"(c[1]), "+f"(c[2]), "+f"(c[3])
        : "r"(a[0]), "r"(a[1]), "r"(a[2]), "r"(a[3]), "r"(b[0]), "r"(b[1]));
}
__device__ __forceinline__ uint2 f4_to_h4(float4 v) {
    union { __half2 h2[2]; uint2 u; } U;
    U.h2[0] = __floats2half2_rn(v.x, v.y);
    U.h2[1] = __floats2half2_rn(v.z, v.w);
    return U.u;
}
__device__ __forceinline__ void cpa16(uint32_t dst, const void* src) {
    asm volatile("cp.async.cg.shared.global [%0], [%1], 16;" :: "r"(dst), "l"(src));
}
__device__ __forceinline__ void cpa16z(uint32_t dst, const void* src, bool v) {
    int sz = v ? 16 : 0;
    asm volatile("cp.async.cg.shared.global [%0], [%1], 16, %2;"
                 :: "r"(dst), "l"(src), "r"(sz));
}

// =====================================================================
// tc_gemm: single-pass fp16 GEMM, fp32 accum. C = A[M,K] @ W[N,K]^T + bias
//   MODE 0: +bias   2: +bias,relu
//   MODE 4: fused dual (blocks 0,1 -> C fp32; block 2 -> W2 softmax16 -> C2)
//   OH: write __half to (half*)C instead of fp32.
//   CTA 64x128, 256 thr (warp 32x32), KC=64 (128B rows), 3 stages, 1 sync.
//   launch_bounds(256,3): cap regs ~85 so 3 CTAs/SM (216KB smem) fit.
// =====================================================================
#define KC 64
#define A_TILE_B 8192
#define B_TILE_B 16384
#define STAGE_B (A_TILE_B + B_TILE_B)   // 24 KB
#define NSTAGE 3
#define GEMM_SMEM (NSTAGE * STAGE_B)    // 72 KB

template <int MODE, bool OH>
__global__ void __launch_bounds__(256, 3)
tc_gemm(const __half* __restrict__ A, const __half* __restrict__ W,
        const __half* __restrict__ W2, const float* __restrict__ bias,
        const float* __restrict__ bias2, float* __restrict__ C, float* __restrict__ C2,
        int M, int N, int K) {
    extern __shared__ char smem[];
    const uint32_t sbase = smem_u32(smem);
    const int tid = threadIdx.x;
    const int wid = tid >> 5;
    const int lane = tid & 31;
    const int rowBase = blockIdx.y * 64;
    const int colBase = blockIdx.x * 128;
    const int warpM = wid >> 2;
    const int warpN = wid & 3;
    const bool isAw = (MODE == 4) && (blockIdx.x == 2);

    const __half* bW = isAw ? W2 : (W + (size_t)colBase * K);

    float acc[2][4][4];
#pragma unroll
    for (int mi = 0; mi < 2; mi++)
#pragma unroll
        for (int ni = 0; ni < 4; ni++)
#pragma unroll
            for (int j = 0; j < 4; j++) acc[mi][ni][j] = 0.f;

    const uint32_t swX = (uint32_t)((lane & 7) << 4);
    const int aKB0 = (lane >> 4) * 16;
    uint32_t aRowOff[2];
#pragma unroll
    for (int mi = 0; mi < 2; mi++)
        aRowOff[mi] = (uint32_t)((warpM * 32 + mi * 16 + (lane & 15)) * 128);
    const int grp = lane >> 3;
    const int bKB0 = (grp & 1) * 16;
    uint32_t bRowOff[2];
#pragma unroll
    for (int np = 0; np < 2; np++)
        bRowOff[np] = (uint32_t)((warpN * 32 + np * 16 + ((grp >> 1) << 3) + (lane & 7)) * 128);

    const int nChunks = K / KC;

    auto copy_chunk = [&](int kt, uint32_t stg) {
        const int k0 = kt * KC;
#pragma unroll
        for (int i = 0; i < 4; i++) {
            int idx = tid + i * 256;
            int r = idx >> 3, c = idx & 7;
            uint32_t off = (uint32_t)(r * 128 + ((c * 16) ^ ((r & 7) << 4)));
            cpa16(stg + A_TILE_B + off, bW + (size_t)r * K + k0 + c * 8);
        }
#pragma unroll
        for (int i = 0; i < 2; i++) {
            int idx = tid + i * 256;
            int r = idx >> 3, c = idx & 7;
            uint32_t off = (uint32_t)(r * 128 + ((c * 16) ^ ((r & 7) << 4)));
            int gr = rowBase + r;
            bool v = gr < M;
            int crr = v ? gr : (M - 1);
            cpa16z(stg + off, A + (size_t)crr * K + k0 + c * 8, v);
        }
    };

    copy_chunk(0, sbase);
    asm volatile("cp.async.commit_group;");
    if (nChunks > 1) {
        copy_chunk(1, sbase + STAGE_B);
        asm volatile("cp.async.commit_group;");
    }
    int stgIdx = 0;
    for (int kt = 0; kt < nChunks; kt++) {
        if (kt + 1 < nChunks) asm volatile("cp.async.wait_group 1;");
        else asm volatile("cp.async.wait_group 0;");
        __syncthreads();
        if (kt + 2 < nChunks) {
            int ws = stgIdx + 2;
            if (ws >= NSTAGE) ws -= NSTAGE;
            copy_chunk(kt + 2, sbase + (uint32_t)(ws * STAGE_B));
            asm volatile("cp.async.commit_group;");
        }
        const uint32_t AS = sbase + (uint32_t)(stgIdx * STAGE_B);
        const uint32_t BS = AS + A_TILE_B;
#pragma unroll
        for (int kst = 0; kst < 4; kst++) {
            uint32_t a[2][4];
#pragma unroll
            for (int mi = 0; mi < 2; mi++) {
                uint32_t kb = (uint32_t)(aKB0 + kst * 32);
                ldm_x4(AS + aRowOff[mi] + (kb ^ swX), a[mi][0], a[mi][1], a[mi][2], a[mi][3]);
            }
            uint32_t b[4][2];
#pragma unroll
            for (int np = 0; np < 2; np++) {
                uint32_t kb = (uint32_t)(bKB0 + kst * 32);
                uint32_t r0, r1, r2, r3;
                ldm_x4(BS + bRowOff[np] + (kb ^ swX), r0, r1, r2, r3);
                b[np * 2][0] = r0; b[np * 2][1] = r1;
                b[np * 2 + 1][0] = r2; b[np * 2 + 1][1] = r3;
            }
#pragma unroll
            for (int mi = 0; mi < 2; mi++)
#pragma unroll
                for (int ni = 0; ni < 4; ni++) mma_f16(acc[mi][ni], a[mi], b[ni]);
        }
        stgIdx++;
        if (stgIdx == NSTAGE) stgIdx = 0;
    }

    const int qrow = lane >> 2;
    const int qcol = (lane & 3) * 2;
#pragma unroll
    for (int ni = 0; ni < 4; ni++) {
        int cl_ = warpN * 32 + ni * 8 + qcol;
        int bcol = isAw ? cl_ : (colBase + cl_);
        const float* bp = isAw ? bias2 : bias;
        float b0 = __ldg(bp + bcol), b1 = __ldg(bp + bcol + 1);
#pragma unroll
        for (int mi = 0; mi < 2; mi++) {
            acc[mi][ni][0] += b0; acc[mi][ni][1] += b1;
            acc[mi][ni][2] += b0; acc[mi][ni][3] += b1;
        }
    }
    if (isAw) {
#pragma unroll
        for (int mi = 0; mi < 2; mi++)
#pragma unroll
            for (int g = 0; g < 2; g++)
#pragma unroll
                for (int rh = 0; rh < 2; rh++) {
                    float v0 = acc[mi][2 * g][rh * 2], v1 = acc[mi][2 * g][rh * 2 + 1];
                    float v2 = acc[mi][2 * g + 1][rh * 2], v3 = acc[mi][2 * g + 1][rh * 2 + 1];
                    float mx = fmaxf(fmaxf(v0, v1), fmaxf(v2, v3));
                    mx = fmaxf(mx, __shfl_xor_sync(0xffffffffu, mx, 1));
                    mx = fmaxf(mx, __shfl_xor_sync(0xffffffffu, mx, 2));
                    v0 = expf(v0 - mx); v1 = expf(v1 - mx);
                    v2 = expf(v2 - mx); v3 = expf(v3 - mx);
                    float s = v0 + v1 + v2 + v3;
                    s += __shfl_xor_sync(0xffffffffu, s, 1);
                    s += __shfl_xor_sync(0xffffffffu, s, 2);
                    float inv = 1.f / s;
                    acc[mi][2 * g][rh * 2] = v0 * inv; acc[mi][2 * g][rh * 2 + 1] = v1 * inv;
                    acc[mi][2 * g + 1][rh * 2] = v2 * inv; acc[mi][2 * g + 1][rh * 2 + 1] = v3 * inv;
                }
    }
#pragma unroll
    for (int mi = 0; mi < 2; mi++)
#pragma unroll
        for (int rh = 0; rh < 2; rh++) {
            int row = rowBase + warpM * 32 + mi * 16 + qrow + rh * 8;
            if (row >= M) continue;
#pragma unroll
            for (int ni = 0; ni < 4; ni++) {
                int cl_ = warpN * 32 + ni * 8 + qcol;
                float v0 = acc[mi][ni][rh * 2], v1 = acc[mi][ni][rh * 2 + 1];
                if (MODE == 2) { v0 = fmaxf(v0, 0.f); v1 = fmaxf(v1, 0.f); }
                if (OH) {
                    *(__half2*)((__half*)C + (size_t)row * N + colBase + cl_) =
                        __floats2half2_rn(v0, v1);
                } else if (isAw) {
                    *(float2*)(C2 + (size_t)row * 128 + cl_) = make_float2(v0, v1);
                } else {
                    *(float2*)(C + (size_t)row * N + colBase + cl_) = make_float2(v0, v1);
                }
            }
        }
}

// =====================================================================
// tc_gemm_ln: fp16 GEMM + residual + fused LayerNorm. CTA 64x256 (full rows).
// =====================================================================
#define LA_TILE_B 8192
#define LB_TILE_B 32768
#define LSTAGE_B (LA_TILE_B + LB_TILE_B)
#define GEMM_LN_SMEM (2 * LSTAGE_B)     // 80 KB

template <bool WANTH, bool HASP>
__global__ void __launch_bounds__(256, 2)
tc_gemm_ln(const __half* __restrict__ A, const __half* __restrict__ W,
           const float* __restrict__ bias, const float* __restrict__ R,
           const float* __restrict__ lng, const float* __restrict__ lnb,
           const float* __restrict__ P, float* __restrict__ Cout,
           __half* __restrict__ Sh, int M, int K) {
    extern __shared__ char smem[];
    const uint32_t sbase = smem_u32(smem);
    const int tid = threadIdx.x;
    const int wid = tid >> 5;
    const int lane = tid & 31;
    const int rowBase = blockIdx.x * 64;
    const int warpM = wid >> 2;
    const int warpN = wid & 3;

    float acc[2][8][4];
#pragma unroll
    for (int mi = 0; mi < 2; mi++)
#pragma unroll
        for (int ni = 0; ni < 8; ni++)
#pragma unroll
            for (int j = 0; j < 4; j++) acc[mi][ni][j] = 0.f;

    const uint32_t swX = (uint32_t)((lane & 7) << 4);
    const int aKB0 = (lane >> 4) * 16;
    uint32_t aRowOff[2];
#pragma unroll
    for (int mi = 0; mi < 2; mi++)
        aRowOff[mi] = (uint32_t)((warpM * 32 + mi * 16 + (lane & 15)) * 128);
    const int grp = lane >> 3;
    const int bKB0 = (grp & 1) * 16;
    uint32_t bRowOff[4];
#pragma unroll
    for (int np = 0; np < 4; np++)
        bRowOff[np] = (uint32_t)((warpN * 64 + np * 16 + ((grp >> 1) << 3) + (lane & 7)) * 128);

    const int nChunks = K / KC;

    auto copy_chunk = [&](int kt, uint32_t stg) {
        const int k0 = kt * KC;
#pragma unroll
        for (int i = 0; i < 8; i++) {
            int idx = tid + i * 256;
            int r = idx >> 3, c = idx & 7;
            uint32_t off = (uint32_t)(r * 128 + ((c * 16) ^ ((r & 7) << 4)));
            cpa16(stg + LA_TILE_B + off, W + (size_t)r * K + k0 + c * 8);
        }
#pragma unroll
        for (int i = 0; i < 2; i++) {
            int idx = tid + i * 256;
            int r = idx >> 3, c = idx & 7;
            uint32_t off = (uint32_t)(r * 128 + ((c * 16) ^ ((r & 7) << 4)));
            int gr = rowBase + r;
            bool v = gr < M;
            int crr = v ? gr : (M - 1);
            cpa16z(stg + off, A + (size_t)crr * K + k0 + c * 8, v);
        }
    };

    copy_chunk(0, sbase);
    asm volatile("cp.async.commit_group;");
    for (int kt = 0; kt < nChunks; kt++) {
        if (kt + 1 < nChunks) {
            copy_chunk(kt + 1, sbase + (uint32_t)(((kt + 1) & 1) * LSTAGE_B));
            asm volatile("cp.async.commit_group;");
            asm volatile("cp.async.wait_group 1;");
        } else {
            asm volatile("cp.async.wait_group 0;");
        }
        __syncthreads();
        const uint32_t AS = sbase + (uint32_t)((kt & 1) * LSTAGE_B);
        const uint32_t BS = AS + LA_TILE_B;
#pragma unroll
        for (int kst = 0; kst < 4; kst++) {
            uint32_t a[2][4];
#pragma unroll
            for (int mi = 0; mi < 2; mi++) {
                uint32_t kb = (uint32_t)(aKB0 + kst * 32);
                ldm_x4(AS + aRowOff[mi] + (kb ^ swX), a[mi][0], a[mi][1], a[mi][2], a[mi][3]);
            }
#pragma unroll
            for (int np = 0; np < 4; np++) {
                uint32_t kb = (uint32_t)(bKB0 + kst * 32);
                uint32_t r0, r1, r2, r3;
                ldm_x4(BS + bRowOff[np] + (kb ^ swX), r0, r1, r2, r3);
                uint32_t b0[2] = {r0, r1}, b1[2] = {r2, r3};
#pragma unroll
                for (int mi = 0; mi < 2; mi++) {
                    mma_f16(acc[mi][2 * np], a[mi], b0);
                    mma_f16(acc[mi][2 * np + 1], a[mi], b1);
                }
            }
        }
        if (kt + 1 < nChunks) __syncthreads();
    }

    // ---- fused epilogue: bias + residual + LayerNorm ----
    __syncthreads();
    float* red = (float*)smem;
    const int qrow = lane >> 2;
    const int qcol = (lane & 3) * 2;

#pragma unroll
    for (int mi = 0; mi < 2; mi++)
#pragma unroll
        for (int rh = 0; rh < 2; rh++) {
            int rloc = warpM * 32 + mi * 16 + rh * 8 + qrow;
            int row = rowBase + rloc;
            bool ok = row < M;
            float s = 0.f, qsum = 0.f;
#pragma unroll
            for (int ni = 0; ni < 8; ni++) {
                int col = warpN * 64 + ni * 8 + qcol;
                float b0 = __ldg(bias + col), b1 = __ldg(bias + col + 1);
                float v0 = acc[mi][ni][rh * 2] + b0;
                float v1 = acc[mi][ni][rh * 2 + 1] + b1;
                if (ok) {
                    const float2 rr = *(const float2*)(R + (size_t)row * 256 + col);
                    v0 += rr.x; v1 += rr.y;
                }
                acc[mi][ni][rh * 2] = v0;
                acc[mi][ni][rh * 2 + 1] = v1;
                s += v0 + v1;
                qsum += v0 * v0 + v1 * v1;
            }
            s += __shfl_xor_sync(0xffffffffu, s, 1);
            s += __shfl_xor_sync(0xffffffffu, s, 2);
            qsum += __shfl_xor_sync(0xffffffffu, qsum, 1);
            qsum += __shfl_xor_sync(0xffffffffu, qsum, 2);
            if ((lane & 3) == 0) {
                red[(rloc << 3) + (warpN << 1)] = s;
                red[(rloc << 3) + (warpN << 1) + 1] = qsum;
            }
        }
    __syncthreads();
#pragma unroll
    for (int mi = 0; mi < 2; mi++)
#pragma unroll
        for (int rh = 0; rh < 2; rh++) {
            int rloc = warpM * 32 + mi * 16 + rh * 8 + qrow;
            int row = rowBase + rloc;
            if (row >= M) continue;
            float s = red[(rloc << 3)] + red[(rloc << 3) + 2] +
                      red[(rloc << 3) + 4] + red[(rloc << 3) + 6];
            float qsum = red[(rloc << 3) + 1] + red[(rloc << 3) + 3] +
                         red[(rloc << 3) + 5] + red[(rloc << 3) + 7];
            float mean = s * (1.f / 256.f);
            float var = qsum * (1.f / 256.f) - mean * mean;
            float rstd = rsqrtf(var + 1e-5f);
#pragma unroll
            for (int ni = 0; ni < 8; ni++) {
                int col = warpN * 64 + ni * 8 + qcol;
                float g0 = __ldg(lng + col), g1 = __ldg(lng + col + 1);
                float c0 = __ldg(lnb + col), c1 = __ldg(lnb + col + 1);
                float y0 = (acc[mi][ni][rh * 2] - mean) * rstd * g0 + c0;
                float y1 = (acc[mi][ni][rh * 2 + 1] - mean) * rstd * g1 + c1;
                *(float2*)(Cout + (size_t)row * 256 + col) = make_float2(y0, y1);
                if (WANTH) {
                    float t0 = y0, t1 = y1;
                    if (HASP) {
                        const float2 pp = *(const float2*)(P + (size_t)row * 256 + col);
                        t0 += pp.x; t1 += pp.y;
                    }
                    *(__half2*)(Sh + (size_t)row * 256 + col) = __floats2half2_rn(t0, t1);
                }
            }
        }
}

// ---------------- batched weight conversion (fp32 -> fp16) ----------------
struct WJob { const float* s; __half* h; int n4; };
struct WJobs { WJob j[8]; };
__global__ void wconv_kernel(WJobs J) {
    int i = blockIdx.x * blockDim.x + threadIdx.x;
#pragma unroll
    for (int k = 0; k < 8; k++) {
        int n = J.j[k].n4;
        if (i < n) {
            ((uint2*)J.j[k].h)[i] = f4_to_h4(((const float4*)J.j[k].s)[i]);
            return;
        }
        i -= n;
    }
}
__global__ void actconv_kernel(const float* __restrict__ src, const float* __restrict__ pos,
                               __half* __restrict__ A, __half* __restrict__ B, int n4) {
    int i = blockIdx.x * blockDim.x + threadIdx.x;
    if (i >= n4) return;
    float4 s = ((const float4*)src)[i];
    float4 p = ((const float4*)pos)[i];
    ((uint2*)A)[i] = f4_to_h4(s);
    s.x += p.x; s.y += p.y; s.z += p.z; s.w += p.w;
    ((uint2*)B)[i] = f4_to_h4(s);
}

// ---------------- multi-scale deformable sampling (fp16 value; fp16 out) ----
__global__ void msdeform_kernel(const __half* __restrict__ value, const float* __restrict__ offs,
                                const float* __restrict__ aw, const float* __restrict__ ref,
                                __half* __restrict__ outh) {
    int gw = (blockIdx.x * blockDim.x + threadIdx.x) >> 5;
    int lane = threadIdx.x & 31;
    if (gw >= NTOK * NH) return;
    int token = gw >> 3, h = gw & 7;
    int b = (token >= LQ_C) ? 1 : 0;

    int p = lane & 15;
    int l = p >> 2;
    int Wl = c_W[l], Hl = c_H[l];
    float Wf = (float)Wl, Hf = (float)Hl;
    float rx = __ldg(ref + (size_t)token * 8 + l * 2);
    float ry = __ldg(ref + (size_t)token * 8 + l * 2 + 1);
    float ox = __ldg(offs + (size_t)token * 256 + h * 32 + p * 2);
    float oy = __ldg(offs + (size_t)token * 256 + h * 32 + p * 2 + 1);
    float wA = __ldg(aw + (size_t)token * 128 + h * 16 + p);

    float X = (rx + ox / Wf) * Wf - 0.5f;
    float Y = (ry + oy / Hf) * Hf - 0.5f;
    float x0f = floorf(X), y0f = floorf(Y);
    float lx = X - x0f, ly = Y - y0f;
    int x0 = (int)x0f, y0 = (int)y0f;
    int x1 = x0 + 1, y1 = y0 + 1;
    bool vx0 = (x0 >= 0) & (x0 < Wl), vx1 = (x1 >= 0) & (x1 < Wl);
    bool vy0 = (y0 >= 0) & (y0 < Hl), vy1 = (y1 >= 0) & (y1 < Hl);
    int cx0 = min(max(x0, 0), Wl - 1), cx1 = min(max(x1, 0), Wl - 1);
    int cy0 = min(max(y0, 0), Hl - 1), cy1 = min(max(y1, 0), Hl - 1);
    int base = b * LQ_C + c_St[l];
    int r00 = base + cy0 * Wl + cx0;
    int r01 = base + cy0 * Wl + cx1;
    int r10 = base + cy1 * Wl + cx0;
    int r11 = base + cy1 * Wl + cx1;
    float w00 = wA * (1.f - lx) * (1.f - ly) * (float)(vx0 & vy0);
    float w01 = wA * lx * (1.f - ly) * (float)(vx1 & vy0);
    float w10 = wA * (1.f - lx) * ly * (float)(vx0 & vy1);
    float w11 = wA * lx * ly * (float)(vx1 & vy1);

    const __half* vb = value + h * 32 + lane;
    float acc = 0.f;
#pragma unroll
    for (int pp = 0; pp < 16; pp++) {
        int s00 = __shfl_sync(0xffffffffu, r00, pp);
        int s01 = __shfl_sync(0xffffffffu, r01, pp);
        int s10 = __shfl_sync(0xffffffffu, r10, pp);
        int s11 = __shfl_sync(0xffffffffu, r11, pp);
        float u00 = __shfl_sync(0xffffffffu, w00, pp);
        float u01 = __shfl_sync(0xffffffffu, w01, pp);
        float u10 = __shfl_sync(0xffffffffu, w10, pp);
        float u11 = __shfl_sync(0xffffffffu, w11, pp);
        acc += u00 * __half2float(__ldg(vb + (size_t)s00 * 256));
        acc += u01 * __half2float(__ldg(vb + (size_t)s01 * 256));
        acc += u10 * __half2float(__ldg(vb + (size_t)s10 * 256));
        acc += u11 * __half2float(__ldg(vb + (size_t)s11 * 256));
    }
    outh[(size_t)token * 256 + h * 32 + lane] = __float2half_rn(acc);
}

// ---------------- text K/V projection (fp16 out) ----------------
__global__ void kv_proj_kernel(const float* __restrict__ text, const float* __restrict__ ipw,
                               const float* __restrict__ ipb, __half* __restrict__ kh,
                               __half* __restrict__ vh) {
    int row = blockIdx.x;
    int c = threadIdx.x;
    const float* t = text + (size_t)row * 256;
    const float* wk = ipw + (size_t)(256 + c) * 256;
    const float* wv = ipw + (size_t)(512 + c) * 256;
    float sk = ipb[256 + c], sv = ipb[512 + c];
    for (int k = 0; k < 256; k++) {
        float tv = t[k];
        sk += tv * wk[k];
        sv += tv * wv[k];
    }
    kh[(size_t)row * 256 + c] = __float2half_rn(sk);
    vh[(size_t)row * 256 + c] = __float2half_rn(sv);
}

// ---------------- text cross-attention (all fp16 I/O) ----------------
__global__ void cross_attn_kernel(const __half* __restrict__ qh, const __half* __restrict__ kh,
                                  const __half* __restrict__ vh, __half* __restrict__ ch) {
    int idx = blockIdx.x * blockDim.x + threadIdx.x;
    if (idx >= NTOK * NH) return;
    int token = idx >> 3, h = idx & 7;
    int b = (token >= LQ_C) ? 1 : 0;
    const __half2* q = (const __half2*)(qh + (size_t)token * 256 + h * 32);
    float2 qv[16];
#pragma unroll
    for (int j = 0; j < 16; j++) qv[j] = __half22float2(q[j]);

    float sc[LT];
    float mx = -1e30f;
    const float scale = 0.17677669529663687f;
#pragma unroll 4
    for (int k = 0; k < LT; k++) {
        const __half2* kp = (const __half2*)(kh + (size_t)(b * LT + k) * 256 + h * 32);
        float s = 0.f;
#pragma unroll
        for (int j = 0; j < 16; j++) {
            float2 kv = __half22float2(kp[j]);
            s += qv[j].x * kv.x + qv[j].y * kv.y;
        }
        s *= scale;
        sc[k] = s;
        mx = fmaxf(mx, s);
    }
    float denom = 0.f;
#pragma unroll
    for (int k = 0; k < LT; k++) { sc[k] = expf(sc[k] - mx); denom += sc[k]; }
    float inv = 1.f / denom;
    float2 o[16];
#pragma unroll
    for (int j = 0; j < 16; j++) o[j] = make_float2(0.f, 0.f);
#pragma unroll 4
    for (int k = 0; k < LT; k++) {
        float pw = sc[k] * inv;
        const __half2* vp = (const __half2*)(vh + (size_t)(b * LT + k) * 256 + h * 32);
#pragma unroll
        for (int j = 0; j < 16; j++) {
            float2 vv = __half22float2(vp[j]);
            o[j].x += pw * vv.x;
            o[j].y += pw * vv.y;
        }
    }
    __half2* cp = (__half2*)(ch + (size_t)token * 256 + h * 32);
#pragma unroll
    for (int j = 0; j < 16; j++) cp[j] = __floats2half2_rn(o[j].x, o[j].y);
}

// ---------------- launch ----------------
extern "C" void kernel_launch(void* const* d_in, const int* in_sizes, int n_in,
                              void* d_out, int out_size) {
    const float* src   = (const float*)d_in[0];
    const float* pos   = (const float*)d_in[1];
    const float* refp  = (const float*)d_in[2];
    const float* text  = (const float*)d_in[5];
    const float* so_w  = (const float*)d_in[7];
    const float* so_b  = (const float*)d_in[8];
    const float* aw_w  = (const float*)d_in[9];
    const float* aw_b  = (const float*)d_in[10];
    const float* vp_w  = (const float*)d_in[11];
    const float* vp_b  = (const float*)d_in[12];
    const float* op_w  = (const float*)d_in[13];
    const float* op_b  = (const float*)d_in[14];
    const float* ln1_g = (const float*)d_in[15];
    const float* ln1_b = (const float*)d_in[16];
    const float* ipw   = (const float*)d_in[17];
    const float* ipb   = (const float*)d_in[18];
    const float* mo_w  = (const float*)d_in[19];
    const float* mo_b  = (const float*)d_in[20];
    const float* ln3_g = (const float*)d_in[21];
    const float* ln3_b = (const float*)d_in[22];
    const float* l1_w  = (const float*)d_in[23];
    const float* l1_b  = (const float*)d_in[24];
    const float* l2_w  = (const float*)d_in[25];
    const float* l2_b  = (const float*)d_in[26];
    const float* ln2_g = (const float*)d_in[27];
    const float* ln2_b = (const float*)d_in[28];

    float* out_x = (float*)d_out;
    float* out_text = out_x + (size_t)NTOK * D_MODEL;

    float *offs, *aw;
    cudaGetSymbolAddress((void**)&offs, g_offs);
    cudaGetSymbolAddress((void**)&aw, g_aw);
    __half *q, *kh, *vh, *val, *A, *B, *hid;
    cudaGetSymbolAddress((void**)&q, g_q);
    cudaGetSymbolAddress((void**)&kh, g_kh);
    cudaGetSymbolAddress((void**)&vh, g_vh);
    cudaGetSymbolAddress((void**)&val, g_val);
    cudaGetSymbolAddress((void**)&A, g_A);
    cudaGetSymbolAddress((void**)&B, g_B);
    cudaGetSymbolAddress((void**)&hid, g_hid);
    __half *vpw, *sow, *aww, *opw, *wqw, *mow, *l1w, *l2w;
    cudaGetSymbolAddress((void**)&vpw, g_vpw);
    cudaGetSymbolAddress((void**)&sow, g_sow);
    cudaGetSymbolAddress((void**)&aww, g_aww);
    cudaGetSymbolAddress((void**)&opw, g_opw);
    cudaGetSymbolAddress((void**)&wqw, g_wqw);
    cudaGetSymbolAddress((void**)&mow, g_mow);
    cudaGetSymbolAddress((void**)&l1w, g_l1w);
    cudaGetSymbolAddress((void**)&l2w, g_l2w);

    cudaFuncSetAttribute((const void*)tc_gemm<0, false>,
                         cudaFuncAttributeMaxDynamicSharedMemorySize, GEMM_SMEM);
    cudaFuncSetAttribute((const void*)tc_gemm<0, true>,
                         cudaFuncAttributeMaxDynamicSharedMemorySize, GEMM_SMEM);
    cudaFuncSetAttribute((const void*)tc_gemm<2, true>,
                         cudaFuncAttributeMaxDynamicSharedMemorySize, GEMM_SMEM);
    cudaFuncSetAttribute((const void*)tc_gemm<4, false>,
                         cudaFuncAttributeMaxDynamicSharedMemorySize, GEMM_SMEM);
    cudaFuncSetAttribute((const void*)tc_gemm_ln<true, true>,
                         cudaFuncAttributeMaxDynamicSharedMemorySize, GEMM_LN_SMEM);
    cudaFuncSetAttribute((const void*)tc_gemm_ln<true, false>,
                         cudaFuncAttributeMaxDynamicSharedMemorySize, GEMM_LN_SMEM);
    cudaFuncSetAttribute((const void*)tc_gemm_ln<false, false>,
                         cudaFuncAttributeMaxDynamicSharedMemorySize, GEMM_LN_SMEM);

    const int M = NTOK;
    const int mTiles = cdiv(M, 64);
    dim3 g256(2, mTiles), g384(3, mTiles), g1024(8, mTiles);
    const int nAct4 = M * D_MODEL / 4;

    // 1: weight conversions (batched)
    WJobs J;
    J.j[0] = {vp_w, vpw, 65536 / 4};
    J.j[1] = {so_w, sow, 65536 / 4};
    J.j[2] = {aw_w, aww, 32768 / 4};
    J.j[3] = {op_w, opw, 65536 / 4};
    J.j[4] = {ipw,  wqw, 65536 / 4};
    J.j[5] = {mo_w, mow, 65536 / 4};
    J.j[6] = {l1_w, l1w, 262144 / 4};
    J.j[7] = {l2_w, l2w, 262144 / 4};
    int totW4 = (65536 * 5 + 32768 + 262144 * 2) / 4;
    wconv_kernel<<<cdiv(totW4, 256), 256>>>(J);
    // 2: activation conversions (src -> A, src+pos -> B)
    actconv_kernel<<<cdiv(nAct4, 256), 256>>>(src, pos, A, B, nAct4);
    // 3: text K/V (fp16)
    kv_proj_kernel<<<B_SZ * LT, 256>>>(text, ipw, ipb, kh, vh);
    // 4: value = src @ vp^T + b -> fp16
    tc_gemm<0, true><<<g256, 256, GEMM_SMEM>>>(A, vpw, nullptr, vp_b, nullptr,
                                               (float*)val, nullptr, M, 256, 256);
    // 5: fused offs + aw
    tc_gemm<4, false><<<g384, 256, GEMM_SMEM>>>(B, sow, aww, so_b, aw_b,
                                                offs, aw, M, 256, 256);
    // 6: deformable sampling -> ms (fp16, into A)
    msdeform_kernel<<<cdiv(M * NH * 32, 256), 256>>>(val, offs, aw, refp, A);
    // 7: fused GEMM+LN1: x = LN(ms@op^T + b + src) -> out_x; (x+pos) -> B
    tc_gemm_ln<true, true><<<mTiles, 256, GEMM_LN_SMEM>>>(A, opw, op_b, src,
                                                          ln1_g, ln1_b, pos, out_x, B,
                                                          M, 256);
    // 8: qh = (x+pos) @ wq^T + bq -> fp16
    tc_gemm<0, true><<<g256, 256, GEMM_SMEM>>>(B, wqw, nullptr, ipb, nullptr,
                                               (float*)q, nullptr, M, 256, 256);
    // 9: cross attention -> ctx (fp16, into A)
    cross_attn_kernel<<<cdiv(M * NH, 256), 256>>>(q, kh, vh, A);
    // 10: fused GEMM+LN3: x = LN(ctx@mo^T + b + x) -> out_x; x -> B
    tc_gemm_ln<true, false><<<mTiles, 256, GEMM_LN_SMEM>>>(A, mow, mo_b, out_x,
                                                           ln3_g, ln3_b, nullptr, out_x, B,
                                                           M, 256);
    // 11: hid = relu(x@l1^T + b1) -> fp16
    tc_gemm<2, true><<<g1024, 256, GEMM_SMEM>>>(B, l1w, nullptr, l1_b, nullptr,
                                                (float*)hid, nullptr, M, DFF, 256);
    // 12: fused GEMM+LN2: out = LN(hid@l2^T + b2 + x) -> out_x
    tc_gemm_ln<false, false><<<mTiles, 256, GEMM_LN_SMEM>>>(hid, l2w, l2_b, out_x,
                                                            ln2_g, ln2_b, nullptr, out_x,
                                                            nullptr, M, 1024);
    // 13: pass-through text_memory
    cudaMemcpyAsync(out_text, text, (size_t)B_SZ * LT * D_MODEL * sizeof(float),
                    cudaMemcpyDeviceToDevice, 0);
}

// round 13
// speedup vs baseline: 2.1588x; 1.1156x over previous
#include <cuda_runtime.h>
#include <cuda_fp16.h>
#include <cstdint>
#include <math.h>

// ---------------- problem constants ----------------
#define D_MODEL 256
#define NH 8
#define HD 32
#define NL 4
#define NP 4
#define DFF 1024
#define B_SZ 2
#define LT 20
#define LQ_C 20197
#define NTOK (B_SZ * LQ_C)   // 40394

__device__ __constant__ int c_H[NL]  = {100, 50, 25, 13};
__device__ __constant__ int c_W[NL]  = {152, 76, 38, 19};
__device__ __constant__ int c_St[NL] = {0, 15200, 19000, 19950};

// ---------------- scratch (static device globals; no allocation) ----------------
__device__ float g_offs[NTOK * D_MODEL];
__device__ float g_aw[NTOK * 128];
__device__ __half g_q[NTOK * D_MODEL];
__device__ __half g_kh[B_SZ * LT * D_MODEL];
__device__ __half g_vh[B_SZ * LT * D_MODEL];
__device__ __half g_val[NTOK * D_MODEL];
__device__ __half g_A[NTOK * D_MODEL];
__device__ __half g_B[NTOK * D_MODEL];
__device__ __half g_hid[NTOK * DFF];
__device__ __half g_vpw[65536];
__device__ __half g_sow[65536];
__device__ __half g_aww[32768];
__device__ __half g_opw[65536];
__device__ __half g_wqw[65536];
__device__ __half g_mow[65536];
__device__ __half g_l1w[262144];
__device__ __half g_l2w[262144];

static inline int cdiv(int a, int b) { return (a + b - 1) / b; }

__device__ __forceinline__ uint32_t smem_u32(const void* p) {
    uint32_t a;
    asm("{ .reg .u64 t; cvta.to.shared.u64 t, %1; cvt.u32.u64 %0, t; }" : "=r"(a) : "l"(p));
    return a;
}
__device__ __forceinline__ void ldm_x4(uint32_t addr, uint32_t& r0, uint32_t& r1,
                                       uint32_t& r2, uint32_t& r3) {
    asm volatile("ldmatrix.sync.aligned.m8n8.x4.shared.b16 {%0,%1,%2,%3}, [%4];"
                 : "=r"(r0), "=r"(r1), "=r"(r2), "=r"(r3) : "r"(addr));
}
__device__ __forceinline__ void mma_f16(float* c, const uint32_t* a, const uint32_t* b) {
    asm volatile(
        "mma.sync.aligned.m16n8k16.row.col.f32.f16.f16.f32 "
        "{%0,%1,%2,%3}, {%4,%5,%6,%7}, {%8,%9}, {%0,%1,%2,%3};"
        : "+f"(c[0]), "+f"(c[1]), "+f"(c[2]), "+f"(c[3])
        : "r"(a[0]), "r"(a[1]), "r"(a[2]), "r"(a[3]), "r"(b[0]), "r"(b[1]));
}
__device__ __forceinline__ uint2 f4_to_h4(float4 v) {
    union { __half2 h2[2]; uint2 u; } U;
    U.h2[0] = __floats2half2_rn(v.x, v.y);
    U.h2[1] = __floats2half2_rn(v.z, v.w);
    return U.u;
}
__device__ __forceinline__ void cpa16(uint32_t dst, const void* src) {
    asm volatile("cp.async.cg.shared.global [%0], [%1], 16;" :: "r"(dst), "l"(src));
}
__device__ __forceinline__ void cpa16z(uint32_t dst, const void* src, bool v) {
    int sz = v ? 16 : 0;
    asm volatile("cp.async.cg.shared.global [%0], [%1], 16, %2;"
                 :: "r"(dst), "l"(src), "r"(sz));
}

// =====================================================================
// tc_gemm: single-pass fp16 GEMM, fp32 accum. C = A[M,K] @ W[N,K]^T + bias
//   MODE 0: +bias   2: +bias,relu
//   MODE 4: fused dual (blocks 0,1 -> C fp32; block 2 -> W2 softmax16 -> C2)
//   OH: write __half to (half*)C instead of fp32.
//   CTA 64x128, 256 thr (warp 32x32), KC=64, 3 stages, 1 sync, 3 CTAs/SM.
// =====================================================================
#define KC 64
#define A_TILE_B 8192
#define B_TILE_B 16384
#define STAGE_B (A_TILE_B + B_TILE_B)   // 24 KB
#define NSTAGE 3
#define GEMM_SMEM (NSTAGE * STAGE_B)    // 72 KB

template <int MODE, bool OH>
__global__ void __launch_bounds__(256, 3)
tc_gemm(const __half* __restrict__ A, const __half* __restrict__ W,
        const __half* __restrict__ W2, const float* __restrict__ bias,
        const float* __restrict__ bias2, float* __restrict__ C, float* __restrict__ C2,
        int M, int N, int K) {
    extern __shared__ char smem[];
    const uint32_t sbase = smem_u32(smem);
    const int tid = threadIdx.x;
    const int wid = tid >> 5;
    const int lane = tid & 31;
    const int rowBase = blockIdx.y * 64;
    const int colBase = blockIdx.x * 128;
    const int warpM = wid >> 2;
    const int warpN = wid & 3;
    const bool isAw = (MODE == 4) && (blockIdx.x == 2);

    const __half* bW = isAw ? W2 : (W + (size_t)colBase * K);

    float acc[2][4][4];
#pragma unroll
    for (int mi = 0; mi < 2; mi++)
#pragma unroll
        for (int ni = 0; ni < 4; ni++)
#pragma unroll
            for (int j = 0; j < 4; j++) acc[mi][ni][j] = 0.f;

    const uint32_t swX = (uint32_t)((lane & 7) << 4);
    const int aKB0 = (lane >> 4) * 16;
    uint32_t aRowOff[2];
#pragma unroll
    for (int mi = 0; mi < 2; mi++)
        aRowOff[mi] = (uint32_t)((warpM * 32 + mi * 16 + (lane & 15)) * 128);
    const int grp = lane >> 3;
    const int bKB0 = (grp & 1) * 16;
    uint32_t bRowOff[2];
#pragma unroll
    for (int np = 0; np < 2; np++)
        bRowOff[np] = (uint32_t)((warpN * 32 + np * 16 + ((grp >> 1) << 3) + (lane & 7)) * 128);

    const int nChunks = K / KC;

    auto copy_chunk = [&](int kt, uint32_t stg) {
        const int k0 = kt * KC;
#pragma unroll
        for (int i = 0; i < 4; i++) {
            int idx = tid + i * 256;
            int r = idx >> 3, c = idx & 7;
            uint32_t off = (uint32_t)(r * 128 + ((c * 16) ^ ((r & 7) << 4)));
            cpa16(stg + A_TILE_B + off, bW + (size_t)r * K + k0 + c * 8);
        }
#pragma unroll
        for (int i = 0; i < 2; i++) {
            int idx = tid + i * 256;
            int r = idx >> 3, c = idx & 7;
            uint32_t off = (uint32_t)(r * 128 + ((c * 16) ^ ((r & 7) << 4)));
            int gr = rowBase + r;
            bool v = gr < M;
            int crr = v ? gr : (M - 1);
            cpa16z(stg + off, A + (size_t)crr * K + k0 + c * 8, v);
        }
    };

    copy_chunk(0, sbase);
    asm volatile("cp.async.commit_group;");
    if (nChunks > 1) {
        copy_chunk(1, sbase + STAGE_B);
        asm volatile("cp.async.commit_group;");
    }
    int stgIdx = 0;
    for (int kt = 0; kt < nChunks; kt++) {
        if (kt + 1 < nChunks) asm volatile("cp.async.wait_group 1;");
        else asm volatile("cp.async.wait_group 0;");
        __syncthreads();
        if (kt + 2 < nChunks) {
            int ws = stgIdx + 2;
            if (ws >= NSTAGE) ws -= NSTAGE;
            copy_chunk(kt + 2, sbase + (uint32_t)(ws * STAGE_B));
            asm volatile("cp.async.commit_group;");
        }
        const uint32_t AS = sbase + (uint32_t)(stgIdx * STAGE_B);
        const uint32_t BS = AS + A_TILE_B;
#pragma unroll
        for (int kst = 0; kst < 4; kst++) {
            uint32_t a[2][4];
#pragma unroll
            for (int mi = 0; mi < 2; mi++) {
                uint32_t kb = (uint32_t)(aKB0 + kst * 32);
                ldm_x4(AS + aRowOff[mi] + (kb ^ swX), a[mi][0], a[mi][1], a[mi][2], a[mi][3]);
            }
            uint32_t b[4][2];
#pragma unroll
            for (int np = 0; np < 2; np++) {
                uint32_t kb = (uint32_t)(bKB0 + kst * 32);
                uint32_t r0, r1, r2, r3;
                ldm_x4(BS + bRowOff[np] + (kb ^ swX), r0, r1, r2, r3);
                b[np * 2][0] = r0; b[np * 2][1] = r1;
                b[np * 2 + 1][0] = r2; b[np * 2 + 1][1] = r3;
            }
#pragma unroll
            for (int mi = 0; mi < 2; mi++)
#pragma unroll
                for (int ni = 0; ni < 4; ni++) mma_f16(acc[mi][ni], a[mi], b[ni]);
        }
        stgIdx++;
        if (stgIdx == NSTAGE) stgIdx = 0;
    }

    const int qrow = lane >> 2;
    const int qcol = (lane & 3) * 2;
#pragma unroll
    for (int ni = 0; ni < 4; ni++) {
        int cl_ = warpN * 32 + ni * 8 + qcol;
        int bcol = isAw ? cl_ : (colBase + cl_);
        const float* bp = isAw ? bias2 : bias;
        float b0 = __ldg(bp + bcol), b1 = __ldg(bp + bcol + 1);
#pragma unroll
        for (int mi = 0; mi < 2; mi++) {
            acc[mi][ni][0] += b0; acc[mi][ni][1] += b1;
            acc[mi][ni][2] += b0; acc[mi][ni][3] += b1;
        }
    }
    if (isAw) {
#pragma unroll
        for (int mi = 0; mi < 2; mi++)
#pragma unroll
            for (int g = 0; g < 2; g++)
#pragma unroll
                for (int rh = 0; rh < 2; rh++) {
                    float v0 = acc[mi][2 * g][rh * 2], v1 = acc[mi][2 * g][rh * 2 + 1];
                    float v2 = acc[mi][2 * g + 1][rh * 2], v3 = acc[mi][2 * g + 1][rh * 2 + 1];
                    float mx = fmaxf(fmaxf(v0, v1), fmaxf(v2, v3));
                    mx = fmaxf(mx, __shfl_xor_sync(0xffffffffu, mx, 1));
                    mx = fmaxf(mx, __shfl_xor_sync(0xffffffffu, mx, 2));
                    v0 = expf(v0 - mx); v1 = expf(v1 - mx);
                    v2 = expf(v2 - mx); v3 = expf(v3 - mx);
                    float s = v0 + v1 + v2 + v3;
                    s += __shfl_xor_sync(0xffffffffu, s, 1);
                    s += __shfl_xor_sync(0xffffffffu, s, 2);
                    float inv = 1.f / s;
                    acc[mi][2 * g][rh * 2] = v0 * inv; acc[mi][2 * g][rh * 2 + 1] = v1 * inv;
                    acc[mi][2 * g + 1][rh * 2] = v2 * inv; acc[mi][2 * g + 1][rh * 2 + 1] = v3 * inv;
                }
    }
#pragma unroll
    for (int mi = 0; mi < 2; mi++)
#pragma unroll
        for (int rh = 0; rh < 2; rh++) {
            int row = rowBase + warpM * 32 + mi * 16 + qrow + rh * 8;
            if (row >= M) continue;
#pragma unroll
            for (int ni = 0; ni < 4; ni++) {
                int cl_ = warpN * 32 + ni * 8 + qcol;
                float v0 = acc[mi][ni][rh * 2], v1 = acc[mi][ni][rh * 2 + 1];
                if (MODE == 2) { v0 = fmaxf(v0, 0.f); v1 = fmaxf(v1, 0.f); }
                if (OH) {
                    *(__half2*)((__half*)C + (size_t)row * N + colBase + cl_) =
                        __floats2half2_rn(v0, v1);
                } else if (isAw) {
                    *(float2*)(C2 + (size_t)row * 128 + cl_) = make_float2(v0, v1);
                } else {
                    *(float2*)(C + (size_t)row * N + colBase + cl_) = make_float2(v0, v1);
                }
            }
        }
}

// =====================================================================
// tc_gemm_ln: fp16 GEMM + residual + fused LayerNorm. CTA 64x256 (full rows).
// =====================================================================
#define LA_TILE_B 8192
#define LB_TILE_B 32768
#define LSTAGE_B (LA_TILE_B + LB_TILE_B)
#define GEMM_LN_SMEM (2 * LSTAGE_B)     // 80 KB

template <bool WANTH, bool HASP>
__global__ void __launch_bounds__(256, 2)
tc_gemm_ln(const __half* __restrict__ A, const __half* __restrict__ W,
           const float* __restrict__ bias, const float* __restrict__ R,
           const float* __restrict__ lng, const float* __restrict__ lnb,
           const float* __restrict__ P, float* __restrict__ Cout,
           __half* __restrict__ Sh, int M, int K) {
    extern __shared__ char smem[];
    const uint32_t sbase = smem_u32(smem);
    const int tid = threadIdx.x;
    const int wid = tid >> 5;
    const int lane = tid & 31;
    const int rowBase = blockIdx.x * 64;
    const int warpM = wid >> 2;
    const int warpN = wid & 3;

    float acc[2][8][4];
#pragma unroll
    for (int mi = 0; mi < 2; mi++)
#pragma unroll
        for (int ni = 0; ni < 8; ni++)
#pragma unroll
            for (int j = 0; j < 4; j++) acc[mi][ni][j] = 0.f;

    const uint32_t swX = (uint32_t)((lane & 7) << 4);
    const int aKB0 = (lane >> 4) * 16;
    uint32_t aRowOff[2];
#pragma unroll
    for (int mi = 0; mi < 2; mi++)
        aRowOff[mi] = (uint32_t)((warpM * 32 + mi * 16 + (lane & 15)) * 128);
    const int grp = lane >> 3;
    const int bKB0 = (grp & 1) * 16;
    uint32_t bRowOff[4];
#pragma unroll
    for (int np = 0; np < 4; np++)
        bRowOff[np] = (uint32_t)((warpN * 64 + np * 16 + ((grp >> 1) << 3) + (lane & 7)) * 128);

    const int nChunks = K / KC;

    auto copy_chunk = [&](int kt, uint32_t stg) {
        const int k0 = kt * KC;
#pragma unroll
        for (int i = 0; i < 8; i++) {
            int idx = tid + i * 256;
            int r = idx >> 3, c = idx & 7;
            uint32_t off = (uint32_t)(r * 128 + ((c * 16) ^ ((r & 7) << 4)));
            cpa16(stg + LA_TILE_B + off, W + (size_t)r * K + k0 + c * 8);
        }
#pragma unroll
        for (int i = 0; i < 2; i++) {
            int idx = tid + i * 256;
            int r = idx >> 3, c = idx & 7;
            uint32_t off = (uint32_t)(r * 128 + ((c * 16) ^ ((r & 7) << 4)));
            int gr = rowBase + r;
            bool v = gr < M;
            int crr = v ? gr : (M - 1);
            cpa16z(stg + off, A + (size_t)crr * K + k0 + c * 8, v);
        }
    };

    copy_chunk(0, sbase);
    asm volatile("cp.async.commit_group;");
    for (int kt = 0; kt < nChunks; kt++) {
        if (kt + 1 < nChunks) {
            copy_chunk(kt + 1, sbase + (uint32_t)(((kt + 1) & 1) * LSTAGE_B));
            asm volatile("cp.async.commit_group;");
            asm volatile("cp.async.wait_group 1;");
        } else {
            asm volatile("cp.async.wait_group 0;");
        }
        __syncthreads();
        const uint32_t AS = sbase + (uint32_t)((kt & 1) * LSTAGE_B);
        const uint32_t BS = AS + LA_TILE_B;
#pragma unroll
        for (int kst = 0; kst < 4; kst++) {
            uint32_t a[2][4];
#pragma unroll
            for (int mi = 0; mi < 2; mi++) {
                uint32_t kb = (uint32_t)(aKB0 + kst * 32);
                ldm_x4(AS + aRowOff[mi] + (kb ^ swX), a[mi][0], a[mi][1], a[mi][2], a[mi][3]);
            }
#pragma unroll
            for (int np = 0; np < 4; np++) {
                uint32_t kb = (uint32_t)(bKB0 + kst * 32);
                uint32_t r0, r1, r2, r3;
                ldm_x4(BS + bRowOff[np] + (kb ^ swX), r0, r1, r2, r3);
                uint32_t b0[2] = {r0, r1}, b1[2] = {r2, r3};
#pragma unroll
                for (int mi = 0; mi < 2; mi++) {
                    mma_f16(acc[mi][2 * np], a[mi], b0);
                    mma_f16(acc[mi][2 * np + 1], a[mi], b1);
                }
            }
        }
        if (kt + 1 < nChunks) __syncthreads();
    }

    // ---- fused epilogue: bias + residual + LayerNorm ----
    __syncthreads();
    float* red = (float*)smem;
    const int qrow = lane >> 2;
    const int qcol = (lane & 3) * 2;

#pragma unroll
    for (int mi = 0; mi < 2; mi++)
#pragma unroll
        for (int rh = 0; rh < 2; rh++) {
            int rloc = warpM * 32 + mi * 16 + rh * 8 + qrow;
            int row = rowBase + rloc;
            bool ok = row < M;
            float s = 0.f, qsum = 0.f;
#pragma unroll
            for (int ni = 0; ni < 8; ni++) {
                int col = warpN * 64 + ni * 8 + qcol;
                float b0 = __ldg(bias + col), b1 = __ldg(bias + col + 1);
                float v0 = acc[mi][ni][rh * 2] + b0;
                float v1 = acc[mi][ni][rh * 2 + 1] + b1;
                if (ok) {
                    const float2 rr = *(const float2*)(R + (size_t)row * 256 + col);
                    v0 += rr.x; v1 += rr.y;
                }
                acc[mi][ni][rh * 2] = v0;
                acc[mi][ni][rh * 2 + 1] = v1;
                s += v0 + v1;
                qsum += v0 * v0 + v1 * v1;
            }
            s += __shfl_xor_sync(0xffffffffu, s, 1);
            s += __shfl_xor_sync(0xffffffffu, s, 2);
            qsum += __shfl_xor_sync(0xffffffffu, qsum, 1);
            qsum += __shfl_xor_sync(0xffffffffu, qsum, 2);
            if ((lane & 3) == 0) {
                red[(rloc << 3) + (warpN << 1)] = s;
                red[(rloc << 3) + (warpN << 1) + 1] = qsum;
            }
        }
    __syncthreads();
#pragma unroll
    for (int mi = 0; mi < 2; mi++)
#pragma unroll
        for (int rh = 0; rh < 2; rh++) {
            int rloc = warpM * 32 + mi * 16 + rh * 8 + qrow;
            int row = rowBase + rloc;
            if (row >= M) continue;
            float s = red[(rloc << 3)] + red[(rloc << 3) + 2] +
                      red[(rloc << 3) + 4] + red[(rloc << 3) + 6];
            float qsum = red[(rloc << 3) + 1] + red[(rloc << 3) + 3] +
                         red[(rloc << 3) + 5] + red[(rloc << 3) + 7];
            float mean = s * (1.f / 256.f);
            float var = qsum * (1.f / 256.f) - mean * mean;
            float rstd = rsqrtf(var + 1e-5f);
#pragma unroll
            for (int ni = 0; ni < 8; ni++) {
                int col = warpN * 64 + ni * 8 + qcol;
                float g0 = __ldg(lng + col), g1 = __ldg(lng + col + 1);
                float c0 = __ldg(lnb + col), c1 = __ldg(lnb + col + 1);
                float y0 = (acc[mi][ni][rh * 2] - mean) * rstd * g0 + c0;
                float y1 = (acc[mi][ni][rh * 2 + 1] - mean) * rstd * g1 + c1;
                *(float2*)(Cout + (size_t)row * 256 + col) = make_float2(y0, y1);
                if (WANTH) {
                    float t0 = y0, t1 = y1;
                    if (HASP) {
                        const float2 pp = *(const float2*)(P + (size_t)row * 256 + col);
                        t0 += pp.x; t1 += pp.y;
                    }
                    *(__half2*)(Sh + (size_t)row * 256 + col) = __floats2half2_rn(t0, t1);
                }
            }
        }
}

// ---------------- batched weight conversion (fp32 -> fp16) ----------------
struct WJob { const float* s; __half* h; int n4; };
struct WJobs { WJob j[8]; };
__global__ void wconv_kernel(WJobs J) {
    int i = blockIdx.x * blockDim.x + threadIdx.x;
#pragma unroll
    for (int k = 0; k < 8; k++) {
        int n = J.j[k].n4;
        if (i < n) {
            ((uint2*)J.j[k].h)[i] = f4_to_h4(((const float4*)J.j[k].s)[i]);
            return;
        }
        i -= n;
    }
}
__global__ void actconv_kernel(const float* __restrict__ src, const float* __restrict__ pos,
                               __half* __restrict__ A, __half* __restrict__ B, int n4) {
    int i = blockIdx.x * blockDim.x + threadIdx.x;
    if (i >= n4) return;
    float4 s = ((const float4*)src)[i];
    float4 p = ((const float4*)pos)[i];
    ((uint2*)A)[i] = f4_to_h4(s);
    s.x += p.x; s.y += p.y; s.z += p.z; s.w += p.w;
    ((uint2*)B)[i] = f4_to_h4(s);
}

// ---------------- multi-scale deformable sampling ----------------
// Warp per (token, head). Lanes 0-15 process points 0-7, lanes 16-31 points
// 8-15 concurrently: each lane owns 2 channels (half2). Per-lane shfl source
// selects the point; final shfl_xor(16) combines the two point-halves.
__global__ void msdeform_kernel(const __half* __restrict__ value, const float* __restrict__ offs,
                                const float* __restrict__ aw, const float* __restrict__ ref,
                                __half* __restrict__ outh) {
    int gw = (blockIdx.x * blockDim.x + threadIdx.x) >> 5;
    int lane = threadIdx.x & 31;
    if (gw >= NTOK * NH) return;
    int token = gw >> 3, h = gw & 7;
    int b = (token >= LQ_C) ? 1 : 0;

    // ---- per-lane point setup (p = lane & 15) ----
    int p = lane & 15;
    int l = p >> 2;
    int Wl = c_W[l], Hl = c_H[l];
    float Wf = (float)Wl, Hf = (float)Hl;
    float rx = __ldg(ref + (size_t)token * 8 + l * 2);
    float ry = __ldg(ref + (size_t)token * 8 + l * 2 + 1);
    float ox = __ldg(offs + (size_t)token * 256 + h * 32 + p * 2);
    float oy = __ldg(offs + (size_t)token * 256 + h * 32 + p * 2 + 1);
    float wA = __ldg(aw + (size_t)token * 128 + h * 16 + p);

    float X = (rx + ox / Wf) * Wf - 0.5f;
    float Y = (ry + oy / Hf) * Hf - 0.5f;
    float x0f = floorf(X), y0f = floorf(Y);
    float lx = X - x0f, ly = Y - y0f;
    int x0 = (int)x0f, y0 = (int)y0f;
    int x1 = x0 + 1, y1 = y0 + 1;
    bool vx0 = (x0 >= 0) & (x0 < Wl), vx1 = (x1 >= 0) & (x1 < Wl);
    bool vy0 = (y0 >= 0) & (y0 < Hl), vy1 = (y1 >= 0) & (y1 < Hl);
    int cx0 = min(max(x0, 0), Wl - 1), cx1 = min(max(x1, 0), Wl - 1);
    int cy0 = min(max(y0, 0), Hl - 1), cy1 = min(max(y1, 0), Hl - 1);
    int base = b * LQ_C + c_St[l];
    int r00 = base + cy0 * Wl + cx0;
    int r01 = base + cy0 * Wl + cx1;
    int r10 = base + cy1 * Wl + cx0;
    int r11 = base + cy1 * Wl + cx1;
    float w00 = wA * (1.f - lx) * (1.f - ly) * (float)(vx0 & vy0);
    float w01 = wA * lx * (1.f - ly) * (float)(vx1 & vy0);
    float w10 = wA * (1.f - lx) * ly * (float)(vx0 & vy1);
    float w11 = wA * lx * ly * (float)(vx1 & vy1);

    // ---- gather: 8 iterations, two points per iteration ----
    // half2 pointer: row stride = 128 half2; channel pair = h*16 + (lane&15)
    const __half2* vb2 = (const __half2*)value + h * 16 + (lane & 15);
    const int psel = (lane < 16) ? 0 : 8;
    float2 acc = make_float2(0.f, 0.f);
#pragma unroll
    for (int pp = 0; pp < 8; pp++) {
        int sp = pp + psel;
        int s00 = __shfl_sync(0xffffffffu, r00, sp);
        int s01 = __shfl_sync(0xffffffffu, r01, sp);
        int s10 = __shfl_sync(0xffffffffu, r10, sp);
        int s11 = __shfl_sync(0xffffffffu, r11, sp);
        float u00 = __shfl_sync(0xffffffffu, w00, sp);
        float u01 = __shfl_sync(0xffffffffu, w01, sp);
        float u10 = __shfl_sync(0xffffffffu, w10, sp);
        float u11 = __shfl_sync(0xffffffffu, w11, sp);
        float2 f;
        f = __half22float2(__ldg(vb2 + (size_t)s00 * 128));
        acc.x += u00 * f.x; acc.y += u00 * f.y;
        f = __half22float2(__ldg(vb2 + (size_t)s01 * 128));
        acc.x += u01 * f.x; acc.y += u01 * f.y;
        f = __half22float2(__ldg(vb2 + (size_t)s10 * 128));
        acc.x += u10 * f.x; acc.y += u10 * f.y;
        f = __half22float2(__ldg(vb2 + (size_t)s11 * 128));
        acc.x += u11 * f.x; acc.y += u11 * f.y;
    }
    // combine the two point-halves (lane <-> lane^16 hold same channels)
    acc.x += __shfl_xor_sync(0xffffffffu, acc.x, 16);
    acc.y += __shfl_xor_sync(0xffffffffu, acc.y, 16);
    if (lane < 16) {
        ((__half2*)(outh + (size_t)token * 256 + h * 32))[lane] =
            __floats2half2_rn(acc.x, acc.y);
    }
}

// ---------------- text K/V projection (fp16 out) ----------------
__global__ void kv_proj_kernel(const float* __restrict__ text, const float* __restrict__ ipw,
                               const float* __restrict__ ipb, __half* __restrict__ kh,
                               __half* __restrict__ vh) {
    int row = blockIdx.x;
    int c = threadIdx.x;
    const float* t = text + (size_t)row * 256;
    const float* wk = ipw + (size_t)(256 + c) * 256;
    const float* wv = ipw + (size_t)(512 + c) * 256;
    float sk = ipb[256 + c], sv = ipb[512 + c];
    for (int k = 0; k < 256; k++) {
        float tv = t[k];
        sk += tv * wk[k];
        sv += tv * wv[k];
    }
    kh[(size_t)row * 256 + c] = __float2half_rn(sk);
    vh[(size_t)row * 256 + c] = __float2half_rn(sv);
}

// ---------------- text cross-attention (all fp16 I/O) ----------------
__global__ void cross_attn_kernel(const __half* __restrict__ qh, const __half* __restrict__ kh,
                                  const __half* __restrict__ vh, __half* __restrict__ ch) {
    int idx = blockIdx.x * blockDim.x + threadIdx.x;
    if (idx >= NTOK * NH) return;
    int token = idx >> 3, h = idx & 7;
    int b = (token >= LQ_C) ? 1 : 0;
    const __half2* q = (const __half2*)(qh + (size_t)token * 256 + h * 32);
    float2 qv[16];
#pragma unroll
    for (int j = 0; j < 16; j++) qv[j] = __half22float2(q[j]);

    float sc[LT];
    float mx = -1e30f;
    const float scale = 0.17677669529663687f;
#pragma unroll 4
    for (int k = 0; k < LT; k++) {
        const __half2* kp = (const __half2*)(kh + (size_t)(b * LT + k) * 256 + h * 32);
        float s = 0.f;
#pragma unroll
        for (int j = 0; j < 16; j++) {
            float2 kv = __half22float2(kp[j]);
            s += qv[j].x * kv.x + qv[j].y * kv.y;
        }
        s *= scale;
        sc[k] = s;
        mx = fmaxf(mx, s);
    }
    float denom = 0.f;
#pragma unroll
    for (int k = 0; k < LT; k++) { sc[k] = expf(sc[k] - mx); denom += sc[k]; }
    float inv = 1.f / denom;
    float2 o[16];
#pragma unroll
    for (int j = 0; j < 16; j++) o[j] = make_float2(0.f, 0.f);
#pragma unroll 4
    for (int k = 0; k < LT; k++) {
        float pw = sc[k] * inv;
        const __half2* vp = (const __half2*)(vh + (size_t)(b * LT + k) * 256 + h * 32);
#pragma unroll
        for (int j = 0; j < 16; j++) {
            float2 vv = __half22float2(vp[j]);
            o[j].x += pw * vv.x;
            o[j].y += pw * vv.y;
        }
    }
    __half2* cp = (__half2*)(ch + (size_t)token * 256 + h * 32);
#pragma unroll
    for (int j = 0; j < 16; j++) cp[j] = __floats2half2_rn(o[j].x, o[j].y);
}

// ---------------- launch ----------------
extern "C" void kernel_launch(void* const* d_in, const int* in_sizes, int n_in,
                              void* d_out, int out_size) {
    const float* src   = (const float*)d_in[0];
    const float* pos   = (const float*)d_in[1];
    const float* refp  = (const float*)d_in[2];
    const float* text  = (const float*)d_in[5];
    const float* so_w  = (const float*)d_in[7];
    const float* so_b  = (const float*)d_in[8];
    const float* aw_w  = (const float*)d_in[9];
    const float* aw_b  = (const float*)d_in[10];
    const float* vp_w  = (const float*)d_in[11];
    const float* vp_b  = (const float*)d_in[12];
    const float* op_w  = (const float*)d_in[13];
    const float* op_b  = (const float*)d_in[14];
    const float* ln1_g = (const float*)d_in[15];
    const float* ln1_b = (const float*)d_in[16];
    const float* ipw   = (const float*)d_in[17];
    const float* ipb   = (const float*)d_in[18];
    const float* mo_w  = (const float*)d_in[19];
    const float* mo_b  = (const float*)d_in[20];
    const float* ln3_g = (const float*)d_in[21];
    const float* ln3_b = (const float*)d_in[22];
    const float* l1_w  = (const float*)d_in[23];
    const float* l1_b  = (const float*)d_in[24];
    const float* l2_w  = (const float*)d_in[25];
    const float* l2_b  = (const float*)d_in[26];
    const float* ln2_g = (const float*)d_in[27];
    const float* ln2_b = (const float*)d_in[28];

    float* out_x = (float*)d_out;
    float* out_text = out_x + (size_t)NTOK * D_MODEL;

    float *offs, *aw;
    cudaGetSymbolAddress((void**)&offs, g_offs);
    cudaGetSymbolAddress((void**)&aw, g_aw);
    __half *q, *kh, *vh, *val, *A, *B, *hid;
    cudaGetSymbolAddress((void**)&q, g_q);
    cudaGetSymbolAddress((void**)&kh, g_kh);
    cudaGetSymbolAddress((void**)&vh, g_vh);
    cudaGetSymbolAddress((void**)&val, g_val);
    cudaGetSymbolAddress((void**)&A, g_A);
    cudaGetSymbolAddress((void**)&B, g_B);
    cudaGetSymbolAddress((void**)&hid, g_hid);
    __half *vpw, *sow, *aww, *opw, *wqw, *mow, *l1w, *l2w;
    cudaGetSymbolAddress((void**)&vpw, g_vpw);
    cudaGetSymbolAddress((void**)&sow, g_sow);
    cudaGetSymbolAddress((void**)&aww, g_aww);
    cudaGetSymbolAddress((void**)&opw, g_opw);
    cudaGetSymbolAddress((void**)&wqw, g_wqw);
    cudaGetSymbolAddress((void**)&mow, g_mow);
    cudaGetSymbolAddress((void**)&l1w, g_l1w);
    cudaGetSymbolAddress((void**)&l2w, g_l2w);

    cudaFuncSetAttribute((const void*)tc_gemm<0, false>,
                         cudaFuncAttributeMaxDynamicSharedMemorySize, GEMM_SMEM);
    cudaFuncSetAttribute((const void*)tc_gemm<0, true>,
                         cudaFuncAttributeMaxDynamicSharedMemorySize, GEMM_SMEM);
    cudaFuncSetAttribute((const void*)tc_gemm<2, true>,
                         cudaFuncAttributeMaxDynamicSharedMemorySize, GEMM_SMEM);
    cudaFuncSetAttribute((const void*)tc_gemm<4, false>,
                         cudaFuncAttributeMaxDynamicSharedMemorySize, GEMM_SMEM);
    cudaFuncSetAttribute((const void*)tc_gemm_ln<true, true>,
                         cudaFuncAttributeMaxDynamicSharedMemorySize, GEMM_LN_SMEM);
    cudaFuncSetAttribute((const void*)tc_gemm_ln<true, false>,
                         cudaFuncAttributeMaxDynamicSharedMemorySize, GEMM_LN_SMEM);
    cudaFuncSetAttribute((const void*)tc_gemm_ln<false, false>,
                         cudaFuncAttributeMaxDynamicSharedMemorySize, GEMM_LN_SMEM);

    const int M = NTOK;
    const int mTiles = cdiv(M, 64);
    dim3 g256(2, mTiles), g384(3, mTiles), g1024(8, mTiles);
    const int nAct4 = M * D_MODEL / 4;

    // 1: weight conversions (batched)
    WJobs J;
    J.j[0] = {vp_w, vpw, 65536 / 4};
    J.j[1] = {so_w, sow, 65536 / 4};
    J.j[2] = {aw_w, aww, 32768 / 4};
    J.j[3] = {op_w, opw, 65536 / 4};
    J.j[4] = {ipw,  wqw, 65536 / 4};
    J.j[5] = {mo_w, mow, 65536 / 4};
    J.j[6] = {l1_w, l1w, 262144 / 4};
    J.j[7] = {l2_w, l2w, 262144 / 4};
    int totW4 = (65536 * 5 + 32768 + 262144 * 2) / 4;
    wconv_kernel<<<cdiv(totW4, 256), 256>>>(J);
    // 2: activation conversions (src -> A, src+pos -> B)
    actconv_kernel<<<cdiv(nAct4, 256), 256>>>(src, pos, A, B, nAct4);
    // 3: text K/V (fp16)
    kv_proj_kernel<<<B_SZ * LT, 256>>>(text, ipw, ipb, kh, vh);
    // 4: value = src @ vp^T + b -> fp16
    tc_gemm<0, true><<<g256, 256, GEMM_SMEM>>>(A, vpw, nullptr, vp_b, nullptr,
                                               (float*)val, nullptr, M, 256, 256);
    // 5: fused offs + aw
    tc_gemm<4, false><<<g384, 256, GEMM_SMEM>>>(B, sow, aww, so_b, aw_b,
                                                offs, aw, M, 256, 256);
    // 6: deformable sampling -> ms (fp16, into A)
    msdeform_kernel<<<cdiv(M * NH * 32, 256), 256>>>(val, offs, aw, refp, A);
    // 7: fused GEMM+LN1: x = LN(ms@op^T + b + src) -> out_x; (x+pos) -> B
    tc_gemm_ln<true, true><<<mTiles, 256, GEMM_LN_SMEM>>>(A, opw, op_b, src,
                                                          ln1_g, ln1_b, pos, out_x, B,
                                                          M, 256);
    // 8: qh = (x+pos) @ wq^T + bq -> fp16
    tc_gemm<0, true><<<g256, 256, GEMM_SMEM>>>(B, wqw, nullptr, ipb, nullptr,
                                               (float*)q, nullptr, M, 256, 256);
    // 9: cross attention -> ctx (fp16, into A)
    cross_attn_kernel<<<cdiv(M * NH, 256), 256>>>(q, kh, vh, A);
    // 10: fused GEMM+LN3: x = LN(ctx@mo^T + b + x) -> out_x; x -> B
    tc_gemm_ln<true, false><<<mTiles, 256, GEMM_LN_SMEM>>>(A, mow, mo_b, out_x,
                                                           ln3_g, ln3_b, nullptr, out_x, B,
                                                           M, 256);
    // 11: hid = relu(x@l1^T + b1) -> fp16
    tc_gemm<2, true><<<g1024, 256, GEMM_SMEM>>>(B, l1w, nullptr, l1_b, nullptr,
                                                (float*)hid, nullptr, M, DFF, 256);
    // 12: fused GEMM+LN2: out = LN(hid@l2^T + b2 + x) -> out_x
    tc_gemm_ln<false, false><<<mTiles, 256, GEMM_LN_SMEM>>>(hid, l2w, l2_b, out_x,
                                                            ln2_g, ln2_b, nullptr, out_x,
                                                            nullptr, M, 1024);
    // 13: pass-through text_memory
    cudaMemcpyAsync(out_text, text, (size_t)B_SZ * LT * D_MODEL * sizeof(float),
                    cudaMemcpyDeviceToDevice, 0);
}